// round 2
// baseline (speedup 1.0000x reference)
#include <cuda_runtime.h>
#include <math.h>

// ---------------- constants ----------------
#define B_   2
#define C_   64
#define CH_  32
#define H_   256
#define W_   256
#define HWv  65536
#define QKVC 320
#define NH_  4
#define HWP_ 16384

// ---------------- scratch (static device memory; no allocs) ----------------
__device__ float g_xcat[B_*C_*HWv];              // sorted ch<32 + copied ch>=32
__device__ int   g_idxh[B_*CH_*HWv];
__device__ int   g_idxw[B_*CH_*HWv];
__device__ int   g_invh[B_*CH_*HWv];
__device__ int   g_invw[B_*CH_*HWv];
__device__ float g_qkv_pre[B_*QKVC*HWv];         // conv1x1 output
__device__ float g_qkv[B_*QKVC*HWv];             // after dwconv
__device__ unsigned long long g_sortA[B_*C_*HWv];
__device__ unsigned long long g_sortB[B_*C_*HWv];
__device__ int   g_idx[B_*C_*HWv];               // big sort permutation
__device__ float g_vs [B_*C_*HWv];               // sorted v values
__device__ float g_gq1[B_*C_*HWv];
__device__ float g_gk1[B_*C_*HWv];
__device__ float g_gq2[B_*C_*HWv];
__device__ float g_gk2[B_*C_*HWv];
__device__ float g_norm[2048];                    // [var][qk][b][h][d] packed
__device__ float g_Spart[16*32*4096];
__device__ float g_attn[16*4096];
__device__ float g_out1[B_*C_*HWv];
__device__ float g_out2[B_*C_*HWv];
__device__ float g_prod[B_*C_*HWv];
__device__ float g_proj[B_*C_*HWv];
__device__ float g_tmp [B_*CH_*HWv];

// ---------------- small stable bitonic sort (256 elems) ----------------
__device__ __forceinline__ bool pair_gt(float va, int ia, float vb, int ib) {
    return (va > vb) || (va == vb && ia > ib);
}

__device__ __forceinline__ void bitonic256(float* sv, int* si) {
    int t = threadIdx.x;
    for (int k = 2; k <= 256; k <<= 1) {
        for (int j = k >> 1; j > 0; j >>= 1) {
            int ixj = t ^ j;
            if (ixj > t) {
                bool up = ((t & k) == 0);
                float va = sv[t], vb = sv[ixj];
                int   ia = si[t], ib = si[ixj];
                bool sw = up ? pair_gt(va, ia, vb, ib) : pair_gt(vb, ib, va, ia);
                if (sw) { sv[t] = vb; si[t] = ib; sv[ixj] = va; si[ixj] = ia; }
            }
            __syncthreads();
        }
    }
}

// sort columns (axis H) of x[:, :32]; write sorted vals into g_xcat, idx into g_idxh
__global__ void sort_h_kernel(const float* __restrict__ x) {
    __shared__ float sv[256];
    __shared__ int   si[256];
    int blk = blockIdx.x;                 // b*CH*W
    int b = blk / (CH_*W_);
    int c = (blk / W_) % CH_;
    int w = blk % W_;
    int t = threadIdx.x;
    const float* xp = x + ((size_t)(b*C_ + c))*HWv + w;
    sv[t] = xp[(size_t)t * W_];
    si[t] = t;
    __syncthreads();
    bitonic256(sv, si);
    g_xcat[((size_t)(b*C_ + c))*HWv + (size_t)t*W_ + w] = sv[t];
    g_idxh[((size_t)(b*CH_ + c))*HWv + (size_t)t*W_ + w] = si[t];
}

// sort rows (axis W) of g_xcat[:, :32] in place; idx into g_idxw
__global__ void sort_w_kernel() {
    __shared__ float sv[256];
    __shared__ int   si[256];
    int blk = blockIdx.x;                 // b*CH*H
    int b = blk / (CH_*H_);
    int c = (blk / H_) % CH_;
    int h = blk % H_;
    int t = threadIdx.x;
    float* base = g_xcat + ((size_t)(b*C_ + c))*HWv + (size_t)h*W_;
    sv[t] = base[t];
    si[t] = t;
    __syncthreads();
    bitonic256(sv, si);
    base[t] = sv[t];
    g_idxw[((size_t)(b*CH_ + c))*HWv + (size_t)h*W_ + t] = si[t];
}

__global__ void copy_rest_kernel(const float* __restrict__ x) {
    size_t gid = (size_t)blockIdx.x*256 + threadIdx.x;   // B*32*HW
    int b = (int)(gid / ((size_t)CH_*HWv));
    size_t r = gid % ((size_t)CH_*HWv);
    int c = CH_ + (int)(r / HWv);
    int p = (int)(r % HWv);
    size_t off = ((size_t)(b*C_ + c))*HWv + p;
    g_xcat[off] = x[off];
}

// ---------------- conv1x1 (IC=64, OC tile 64) ----------------
__global__ void conv1x1_kernel(const float* __restrict__ in, const float* __restrict__ w,
                               float* __restrict__ out, int OC) {
    __shared__ float Xs[64][64];    // [ic][px]
    __shared__ float Ws[64][68];    // [ic][oc] transposed, padded
    int p0  = blockIdx.x * 64;
    int oc0 = blockIdx.y * 64;
    int b   = blockIdx.z;
    int t   = threadIdx.x;
#pragma unroll
    for (int r = 0; r < 16; r++) {
        int l = r*256 + t; int ic = l >> 6; int px = l & 63;
        Xs[ic][px] = in[((size_t)(b*64 + ic))*HWv + p0 + px];
    }
#pragma unroll
    for (int r = 0; r < 16; r++) {
        int l = r*256 + t; int oc = l >> 6; int ic = l & 63;
        Ws[ic][oc] = w[(size_t)(oc0 + oc)*64 + ic];
    }
    __syncthreads();
    int tx = t & 15, ty = t >> 4;
    float acc[4][4];
#pragma unroll
    for (int i = 0; i < 4; i++)
#pragma unroll
        for (int j = 0; j < 4; j++) acc[i][j] = 0.f;
#pragma unroll
    for (int ic = 0; ic < 64; ic++) {
        float4 wv = *(const float4*)&Ws[ic][ty*4];
        float4 xv = *(const float4*)&Xs[ic][tx*4];
        acc[0][0] += wv.x*xv.x; acc[0][1] += wv.x*xv.y; acc[0][2] += wv.x*xv.z; acc[0][3] += wv.x*xv.w;
        acc[1][0] += wv.y*xv.x; acc[1][1] += wv.y*xv.y; acc[1][2] += wv.y*xv.z; acc[1][3] += wv.y*xv.w;
        acc[2][0] += wv.z*xv.x; acc[2][1] += wv.z*xv.y; acc[2][2] += wv.z*xv.z; acc[2][3] += wv.z*xv.w;
        acc[3][0] += wv.w*xv.x; acc[3][1] += wv.w*xv.y; acc[3][2] += wv.w*xv.z; acc[3][3] += wv.w*xv.w;
    }
#pragma unroll
    for (int i = 0; i < 4; i++)
#pragma unroll
        for (int j = 0; j < 4; j++)
            out[((size_t)(b*OC + oc0 + ty*4 + i))*HWv + p0 + tx*4 + j] = acc[i][j];
}

// ---------------- depthwise 3x3 SAME ----------------
__global__ void dwconv_kernel(const float* __restrict__ in, const float* __restrict__ wd,
                              float* __restrict__ out) {
    size_t gid = (size_t)blockIdx.x*256 + threadIdx.x;   // B*QKVC*HW
    int p  = (int)(gid % HWv);
    size_t bc = gid / HWv;
    int ch = (int)(bc % QKVC);
    int h = p >> 8, w = p & 255;
    const float* ip = in + bc*HWv;
    const float* wp = wd + (size_t)ch*9;
    float s = 0.f;
#pragma unroll
    for (int dy = -1; dy <= 1; dy++) {
        int hh = h + dy;
        if (hh < 0 || hh >= H_) continue;
#pragma unroll
        for (int dx = -1; dx <= 1; dx++) {
            int ww = w + dx;
            if (ww < 0 || ww >= W_) continue;
            s += ip[hh*W_ + ww] * wp[(dy+1)*3 + (dx+1)];
        }
    }
    out[gid] = s;
}

// ---------------- big sort: keys ----------------
__global__ void build_keys_kernel() {
    size_t gid = (size_t)blockIdx.x*256 + threadIdx.x;   // B*C*HW
    int n   = (int)(gid % HWv);
    int row = (int)(gid / HWv);
    int b = row >> 6, c = row & 63;
    float v = g_qkv[((size_t)(b*QKVC + 4*C_ + c))*HWv + n];
    unsigned u = __float_as_uint(v);
    u ^= (u & 0x80000000u) ? 0xFFFFFFFFu : 0x80000000u;
    g_sortA[gid] = ((unsigned long long)u << 32) | (unsigned)n;
}

// one stable LSD radix pass (8-bit digit of the key half)
__global__ void radix_pass_kernel(const unsigned long long* __restrict__ src,
                                  unsigned long long* __restrict__ dst, int shift) {
    extern __shared__ unsigned short cnt[];   // 256 digits * 256 threads
    __shared__ unsigned digTot[256];
    __shared__ unsigned digBase[256];
    int t = threadIdx.x;
    int row = blockIdx.x;
    const unsigned long long* s = src + (size_t)row*HWv;
    unsigned long long* d = dst + (size_t)row*HWv;
    for (int i = t; i < 65536; i += 256) cnt[i] = 0;
    __syncthreads();
    int base = t * 256;
#pragma unroll 4
    for (int j = 0; j < 256; j++) {
        unsigned dg = (unsigned)(s[base + j] >> shift) & 255u;
        cnt[dg*256 + t]++;
    }
    __syncthreads();
    {   // thread t owns digit t: total
        unsigned tot = 0;
        for (int tt = 0; tt < 256; tt++) tot += cnt[t*256 + tt];
        digTot[t] = tot;
    }
    __syncthreads();
    if (t == 0) {
        unsigned run = 0;
        for (int dd = 0; dd < 256; dd++) { digBase[dd] = run; run += digTot[dd]; }
    }
    __syncthreads();
    {   // per-thread exclusive offsets within digit
        unsigned run = digBase[t];
        for (int tt = 0; tt < 256; tt++) {
            unsigned c = cnt[t*256 + tt];
            cnt[t*256 + tt] = (unsigned short)run;
            run += c;
        }
    }
    __syncthreads();
    for (int j = 0; j < 256; j++) {
        unsigned long long kv = s[base + j];
        unsigned dg = (unsigned)(kv >> shift) & 255u;
        unsigned pos = cnt[dg*256 + t];
        cnt[dg*256 + t] = (unsigned short)(pos + 1u);
        d[pos] = kv;
    }
}

__global__ void extract_kernel() {
    size_t gid = (size_t)blockIdx.x*256 + threadIdx.x;
    unsigned long long kv = g_sortA[gid];
    g_idx[gid] = (int)(kv & 0xFFFFFFFFu);
    unsigned u = (unsigned)(kv >> 32);
    u = (u & 0x80000000u) ? (u ^ 0x80000000u) : ~u;
    g_vs[gid] = __uint_as_float(u);
}

__global__ void gather_kernel() {
    size_t gid = (size_t)blockIdx.x*256 + threadIdx.x;
    int row = (int)(gid / HWv);
    int b = row >> 6, c = row & 63;
    int j = g_idx[gid];
    size_t srcb = ((size_t)(b*QKVC) + c)*HWv;
    g_gq1[gid] = g_qkv[srcb + j];
    g_gk1[gid] = g_qkv[srcb + (size_t)64*HWv + j];
    g_gq2[gid] = g_qkv[srcb + (size_t)128*HWv + j];
    g_gk2[gid] = g_qkv[srcb + (size_t)192*HWv + j];
}

// ---------------- attention ----------------
// norm index packing: (var<<10)|(qk<<9)|(b<<8)|(h<<6)|d
__global__ void norm_kernel() {
    int id = blockIdx.x;
    int d = id & 63, h = (id>>6)&3, b = (id>>8)&1, qk = (id>>9)&1, var = (id>>10)&1;
    const float* src = var ? (qk ? g_gk2 : g_gq2) : (qk ? g_gk1 : g_gq1);
    int c = h*16 + (d>>2), f = d & 3;
    size_t base = ((size_t)(b*64 + c))*HWv + (var ? (size_t)f : (size_t)f*HWP_);
    int stride = var ? 4 : 1;
    float s = 0.f;
    for (int i = threadIdx.x; i < HWP_; i += 128) {
        float v = src[base + (size_t)i*stride];
        s += v * v;
    }
    __shared__ float red[128];
    red[threadIdx.x] = s;
    __syncthreads();
    for (int o = 64; o > 0; o >>= 1) {
        if (threadIdx.x < o) red[threadIdx.x] += red[threadIdx.x + o];
        __syncthreads();
    }
    if (threadIdx.x == 0) g_norm[id] = 1.0f / fmaxf(sqrtf(red[0]), 1e-12f);
}

// S partial: grid (32 slices, 16 vbh), slice = 512 n's
__global__ void qk_kernel() {
    __shared__ float Qs[64][65];
    __shared__ float Ks[64][65];
    int t = threadIdx.x;
    int vbh = blockIdx.y;
    int var = vbh >> 3, b = (vbh>>2)&1, h = vbh & 3;
    const float* qsrc = var ? g_gq2 : g_gq1;
    const float* ksrc = var ? g_gk2 : g_gk1;
    int ty = t >> 4, tx = t & 15;
    float acc[4][4];
#pragma unroll
    for (int i = 0; i < 4; i++)
#pragma unroll
        for (int j = 0; j < 4; j++) acc[i][j] = 0.f;
    int n0 = blockIdx.x * 512;
    for (int tile = 0; tile < 8; tile++) {
        int nb = n0 + tile*64;
#pragma unroll
        for (int rr = 0; rr < 16; rr++) {
            int l = rr*256 + t; int d = l >> 6; int nn = l & 63;
            int c = h*16 + (d>>2), f = d & 3;
            size_t addr = ((size_t)(b*64 + c))*HWv +
                          (var ? (size_t)4*(nb+nn) + f : (size_t)f*HWP_ + nb + nn);
            Qs[d][nn] = qsrc[addr];
            Ks[d][nn] = ksrc[addr];
        }
        __syncthreads();
#pragma unroll 8
        for (int nn = 0; nn < 64; nn++) {
            float qa[4], ka[4];
#pragma unroll
            for (int i = 0; i < 4; i++) { qa[i] = Qs[ty*4+i][nn]; ka[i] = Ks[tx*4+i][nn]; }
#pragma unroll
            for (int i = 0; i < 4; i++)
#pragma unroll
                for (int j = 0; j < 4; j++) acc[i][j] += qa[i]*ka[j];
        }
        __syncthreads();
    }
    float* sp = g_Spart + ((size_t)(vbh*32 + blockIdx.x))*4096;
#pragma unroll
    for (int i = 0; i < 4; i++)
#pragma unroll
        for (int j = 0; j < 4; j++)
            sp[(ty*4+i)*64 + tx*4 + j] = acc[i][j];
}

__global__ void softmax_kernel(const float* __restrict__ temp) {
    int vbh = blockIdx.x;
    int var = vbh >> 3, b = (vbh>>2)&1, h = vbh & 3;
    int d = threadIdx.x;   // 64
    __shared__ float sk[64];
    sk[d] = g_norm[(var<<10) | (1<<9) | (b<<8) | (h<<6) | d];
    __syncthreads();
    float invq = g_norm[(var<<10) | (b<<8) | (h<<6) | d];
    float T = temp[h];
    float sum = 0.f;
    float* arow = g_attn + (size_t)vbh*4096 + d*64;
    const float* sp = g_Spart + (size_t)vbh*32*4096 + d*64;
    for (int e = 0; e < 64; e++) {
        float s = 0.f;
        for (int sl = 0; sl < 32; sl++) s += sp[(size_t)sl*4096 + e];
        float ex = expf(s * invq * sk[e] * T);
        arow[e] = ex;
        sum += ex;
    }
    float r = 1.0f / (sum + 1.0f);
    for (int e = 0; e < 64; e++) arow[e] *= r;
}

__global__ void av_kernel() {
    __shared__ float As[4096];
    int t = threadIdx.x;
    int bid = blockIdx.x;
    int nblk = bid & 63;
    int h = (bid>>6)&3, b = (bid>>8)&1, var = (bid>>9)&1;
    int vbh = (var<<3) | (b<<2) | h;
    for (int l = t; l < 4096; l += 256) As[l] = g_attn[(size_t)vbh*4096 + l];
    __syncthreads();
    int n = nblk*256 + t;
    float acc[64];
#pragma unroll
    for (int d2 = 0; d2 < 64; d2++) acc[d2] = 0.f;
#pragma unroll 1
    for (int e = 0; e < 64; e++) {
        int ce = h*16 + (e>>2), fe = e & 3;
        float v = g_vs[((size_t)(b*64 + ce))*HWv + (var ? (size_t)4*n + fe : (size_t)fe*HWP_ + n)];
#pragma unroll
        for (int d2 = 0; d2 < 64; d2++) acc[d2] += As[d2*64 + e] * v;
    }
    float* o = var ? g_out2 : g_out1;
#pragma unroll 1
    for (int d2 = 0; d2 < 64; d2++) {
        int cd = h*16 + (d2>>2), fd = d2 & 3;
        o[((size_t)(b*64 + cd))*HWv + (var ? (size_t)4*n + fd : (size_t)fd*HWP_ + n)] = acc[d2];
    }
}

// ---------------- epilogue ----------------
__global__ void prod_scatter_kernel() {
    size_t gid = (size_t)blockIdx.x*256 + threadIdx.x;   // B*C*HW
    size_t row = gid / HWv;
    int j = g_idx[gid];
    g_prod[row*HWv + j] = g_out1[gid] * g_out2[gid];
}

__global__ void invw_kernel() {
    size_t gid = (size_t)blockIdx.x*256 + threadIdx.x;   // B*CH*HW
    size_t bc = gid / HWv;
    int p = (int)(gid % HWv);
    int h = p >> 8;
    int j = p & 255;
    int v = g_idxw[gid];
    g_invw[bc*HWv + (size_t)h*W_ + v] = j;
}

__global__ void invh_kernel() {
    size_t gid = (size_t)blockIdx.x*256 + threadIdx.x;   // B*CH*HW
    size_t bc = gid / HWv;
    int p = (int)(gid % HWv);
    int i = p >> 8;
    int w = p & 255;
    int v = g_idxh[gid];
    g_invh[bc*HWv + (size_t)v*W_ + w] = i;
}

__global__ void unsort1_kernel() {
    size_t gid = (size_t)blockIdx.x*256 + threadIdx.x;   // B*CH*HW
    size_t bc = gid / HWv;
    int b = (int)(bc / CH_), c = (int)(bc % CH_);
    int p = (int)(gid % HWv);
    int h = p >> 8;
    int iw = g_invw[gid];
    g_tmp[gid] = g_proj[((size_t)(b*C_ + c))*HWv + (size_t)h*W_ + iw];
}

__global__ void unsort2_kernel(float* __restrict__ out) {
    size_t gid = (size_t)blockIdx.x*256 + threadIdx.x;   // B*C*HW
    int b = (int)(gid / ((size_t)C_*HWv));
    size_t r = gid % ((size_t)C_*HWv);
    int c = (int)(r / HWv);
    int p = (int)(r % HWv);
    if (c < CH_) {
        int w = p & 255;
        size_t bc = (size_t)(b*CH_ + c);
        int ih = g_invh[bc*HWv + p];
        out[gid] = g_tmp[bc*HWv + (size_t)ih*W_ + w];
    } else {
        out[gid] = g_proj[gid];
    }
}

// ---------------- launch ----------------
extern "C" void kernel_launch(void* const* d_in, const int* in_sizes, int n_in,
                              void* d_out, int out_size) {
    const float* x     = (const float*)d_in[0];
    const float* qkvw  = (const float*)d_in[1];
    const float* dww   = (const float*)d_in[2];
    const float* projw = (const float*)d_in[3];
    const float* temp  = (const float*)d_in[4];
    float* out = (float*)d_out;

    cudaFuncSetAttribute((const void*)radix_pass_kernel,
                         cudaFuncAttributeMaxDynamicSharedMemorySize, 131072);

    float *p_xcat, *p_qkvpre, *p_qkv, *p_prod, *p_proj;
    unsigned long long *p_sA, *p_sB;
    cudaGetSymbolAddress((void**)&p_xcat,   g_xcat);
    cudaGetSymbolAddress((void**)&p_qkvpre, g_qkv_pre);
    cudaGetSymbolAddress((void**)&p_qkv,    g_qkv);
    cudaGetSymbolAddress((void**)&p_prod,   g_prod);
    cudaGetSymbolAddress((void**)&p_proj,   g_proj);
    cudaGetSymbolAddress((void**)&p_sA,     g_sortA);
    cudaGetSymbolAddress((void**)&p_sB,     g_sortB);

    const int NBC  = (B_*C_*HWv) / 256;     // 32768
    const int NBCH = (B_*CH_*HWv) / 256;    // 16384

    // stage A: small sorts
    sort_h_kernel<<<B_*CH_*W_, 256>>>(x);
    sort_w_kernel<<<B_*CH_*H_, 256>>>();
    copy_rest_kernel<<<NBCH, 256>>>(x);
    invw_kernel<<<NBCH, 256>>>();
    invh_kernel<<<NBCH, 256>>>();

    // stage B: convs
    conv1x1_kernel<<<dim3(HWv/64, QKVC/64, B_), 256>>>(p_xcat, qkvw, p_qkvpre, QKVC);
    dwconv_kernel<<<(B_*QKVC*HWv)/256, 256>>>(p_qkvpre, dww, p_qkv);

    // stage C: big stable argsort of v rows
    build_keys_kernel<<<NBC, 256>>>();
    radix_pass_kernel<<<B_*C_, 256, 131072>>>(p_sA, p_sB, 32);
    radix_pass_kernel<<<B_*C_, 256, 131072>>>(p_sB, p_sA, 40);
    radix_pass_kernel<<<B_*C_, 256, 131072>>>(p_sA, p_sB, 48);
    radix_pass_kernel<<<B_*C_, 256, 131072>>>(p_sB, p_sA, 56);
    extract_kernel<<<NBC, 256>>>();
    gather_kernel<<<NBC, 256>>>();

    // stage D: attention (both variants)
    norm_kernel<<<2048, 128>>>();
    qk_kernel<<<dim3(32, 16), 256>>>();
    softmax_kernel<<<16, 64>>>(temp);
    av_kernel<<<1024, 256>>>();

    // stage E: epilogue
    prod_scatter_kernel<<<NBC, 256>>>();
    conv1x1_kernel<<<dim3(HWv/64, 1, B_), 256>>>(p_prod, projw, p_proj, C_);
    unsort1_kernel<<<NBCH, 256>>>();
    unsort2_kernel<<<NBC, 256>>>(out);
}

// round 3
// speedup vs baseline: 1.2245x; 1.2245x over previous
#include <cuda_runtime.h>
#include <math.h>

// ---------------- constants ----------------
#define B_   2
#define C_   64
#define CH_  32
#define H_   256
#define W_   256
#define HWv  65536
#define QKVC 320
#define NH_  4
#define HWP_ 16384

// radix sort config
#define R_ROWS 128
#define R_N    65536
#define R_SEG  4096
#define R_NSEG 16
#define R_THREADS 512
#define R_EPT  8

// ---------------- scratch (static device memory; no allocs) ----------------
__device__ float g_xcat[B_*C_*HWv];              // sorted ch<32 + copied ch>=32
__device__ int   g_idxh[B_*CH_*HWv];
__device__ int   g_idxw[B_*CH_*HWv];
__device__ int   g_invh[B_*CH_*HWv];
__device__ int   g_invw[B_*CH_*HWv];
__device__ float g_qkv_pre[B_*QKVC*HWv];         // conv1x1 output
__device__ float g_qkv[B_*QKVC*HWv];             // after dwconv
__device__ unsigned long long g_sortA[B_*C_*HWv];
__device__ unsigned long long g_sortB[B_*C_*HWv];
__device__ unsigned g_rhist[R_ROWS*256*R_NSEG];  // 2MB
__device__ int   g_idx[B_*C_*HWv];               // big sort permutation
__device__ float g_vs [B_*C_*HWv];               // sorted v values
__device__ float g_gq1[B_*C_*HWv];
__device__ float g_gk1[B_*C_*HWv];
__device__ float g_gq2[B_*C_*HWv];
__device__ float g_gk2[B_*C_*HWv];
__device__ float g_norm[2048];                    // [var][qk][b][h][d] packed
__device__ float g_Spart[16*32*4096];
__device__ float g_attn[16*4096];
__device__ float g_out1[B_*C_*HWv];
__device__ float g_out2[B_*C_*HWv];
__device__ float g_prod[B_*C_*HWv];
__device__ float g_proj[B_*C_*HWv];
__device__ float g_tmp [B_*CH_*HWv];

// ---------------- small stable bitonic sort (256 elems) ----------------
__device__ __forceinline__ bool pair_gt(float va, int ia, float vb, int ib) {
    return (va > vb) || (va == vb && ia > ib);
}

__device__ __forceinline__ void bitonic256(float* sv, int* si) {
    int t = threadIdx.x;
    for (int k = 2; k <= 256; k <<= 1) {
        for (int j = k >> 1; j > 0; j >>= 1) {
            int ixj = t ^ j;
            if (ixj > t) {
                bool up = ((t & k) == 0);
                float va = sv[t], vb = sv[ixj];
                int   ia = si[t], ib = si[ixj];
                bool sw = up ? pair_gt(va, ia, vb, ib) : pair_gt(vb, ib, va, ia);
                if (sw) { sv[t] = vb; si[t] = ib; sv[ixj] = va; si[ixj] = ia; }
            }
            __syncthreads();
        }
    }
}

__global__ void sort_h_kernel(const float* __restrict__ x) {
    __shared__ float sv[256];
    __shared__ int   si[256];
    int blk = blockIdx.x;                 // b*CH*W
    int b = blk / (CH_*W_);
    int c = (blk / W_) % CH_;
    int w = blk % W_;
    int t = threadIdx.x;
    const float* xp = x + ((size_t)(b*C_ + c))*HWv + w;
    sv[t] = xp[(size_t)t * W_];
    si[t] = t;
    __syncthreads();
    bitonic256(sv, si);
    g_xcat[((size_t)(b*C_ + c))*HWv + (size_t)t*W_ + w] = sv[t];
    g_idxh[((size_t)(b*CH_ + c))*HWv + (size_t)t*W_ + w] = si[t];
}

__global__ void sort_w_kernel() {
    __shared__ float sv[256];
    __shared__ int   si[256];
    int blk = blockIdx.x;                 // b*CH*H
    int b = blk / (CH_*H_);
    int c = (blk / H_) % CH_;
    int h = blk % H_;
    int t = threadIdx.x;
    float* base = g_xcat + ((size_t)(b*C_ + c))*HWv + (size_t)h*W_;
    sv[t] = base[t];
    si[t] = t;
    __syncthreads();
    bitonic256(sv, si);
    base[t] = sv[t];
    g_idxw[((size_t)(b*CH_ + c))*HWv + (size_t)h*W_ + t] = si[t];
}

__global__ void copy_rest_kernel(const float* __restrict__ x) {
    size_t gid = (size_t)blockIdx.x*256 + threadIdx.x;   // B*32*HW
    int b = (int)(gid / ((size_t)CH_*HWv));
    size_t r = gid % ((size_t)CH_*HWv);
    int c = CH_ + (int)(r / HWv);
    int p = (int)(r % HWv);
    size_t off = ((size_t)(b*C_ + c))*HWv + p;
    g_xcat[off] = x[off];
}

// ---------------- conv1x1 (IC=64, OC tile 64) ----------------
__global__ void conv1x1_kernel(const float* __restrict__ in, const float* __restrict__ w,
                               float* __restrict__ out, int OC) {
    __shared__ float Xs[64][64];    // [ic][px]
    __shared__ float Ws[64][68];    // [ic][oc] transposed, padded
    int p0  = blockIdx.x * 64;
    int oc0 = blockIdx.y * 64;
    int b   = blockIdx.z;
    int t   = threadIdx.x;
#pragma unroll
    for (int r = 0; r < 16; r++) {
        int l = r*256 + t; int ic = l >> 6; int px = l & 63;
        Xs[ic][px] = in[((size_t)(b*64 + ic))*HWv + p0 + px];
    }
#pragma unroll
    for (int r = 0; r < 16; r++) {
        int l = r*256 + t; int oc = l >> 6; int ic = l & 63;
        Ws[ic][oc] = w[(size_t)(oc0 + oc)*64 + ic];
    }
    __syncthreads();
    int tx = t & 15, ty = t >> 4;
    float acc[4][4];
#pragma unroll
    for (int i = 0; i < 4; i++)
#pragma unroll
        for (int j = 0; j < 4; j++) acc[i][j] = 0.f;
#pragma unroll
    for (int ic = 0; ic < 64; ic++) {
        float4 wv = *(const float4*)&Ws[ic][ty*4];
        float4 xv = *(const float4*)&Xs[ic][tx*4];
        acc[0][0] += wv.x*xv.x; acc[0][1] += wv.x*xv.y; acc[0][2] += wv.x*xv.z; acc[0][3] += wv.x*xv.w;
        acc[1][0] += wv.y*xv.x; acc[1][1] += wv.y*xv.y; acc[1][2] += wv.y*xv.z; acc[1][3] += wv.y*xv.w;
        acc[2][0] += wv.z*xv.x; acc[2][1] += wv.z*xv.y; acc[2][2] += wv.z*xv.z; acc[2][3] += wv.z*xv.w;
        acc[3][0] += wv.w*xv.x; acc[3][1] += wv.w*xv.y; acc[3][2] += wv.w*xv.z; acc[3][3] += wv.w*xv.w;
    }
#pragma unroll
    for (int i = 0; i < 4; i++)
#pragma unroll
        for (int j = 0; j < 4; j++)
            out[((size_t)(b*OC + oc0 + ty*4 + i))*HWv + p0 + tx*4 + j] = acc[i][j];
}

// ---------------- depthwise 3x3 SAME ----------------
__global__ void dwconv_kernel(const float* __restrict__ in, const float* __restrict__ wd,
                              float* __restrict__ out) {
    size_t gid = (size_t)blockIdx.x*256 + threadIdx.x;   // B*QKVC*HW
    int p  = (int)(gid % HWv);
    size_t bc = gid / HWv;
    int ch = (int)(bc % QKVC);
    int h = p >> 8, w = p & 255;
    const float* ip = in + bc*HWv;
    const float* wp = wd + (size_t)ch*9;
    float s = 0.f;
#pragma unroll
    for (int dy = -1; dy <= 1; dy++) {
        int hh = h + dy;
        if (hh < 0 || hh >= H_) continue;
#pragma unroll
        for (int dx = -1; dx <= 1; dx++) {
            int ww = w + dx;
            if (ww < 0 || ww >= W_) continue;
            s += ip[hh*W_ + ww] * wp[(dy+1)*3 + (dx+1)];
        }
    }
    out[gid] = s;
}

// ---------------- big sort: keys ----------------
__global__ void build_keys_kernel() {
    size_t gid = (size_t)blockIdx.x*256 + threadIdx.x;   // B*C*HW
    int n   = (int)(gid % HWv);
    int row = (int)(gid / HWv);
    int b = row >> 6, c = row & 63;
    float v = g_qkv[((size_t)(b*QKVC + 4*C_ + c))*HWv + n];
    unsigned u = __float_as_uint(v);
    u ^= (u & 0x80000000u) ? 0xFFFFFFFFu : 0x80000000u;
    g_sortA[gid] = ((unsigned long long)u << 32) | (unsigned)n;
}

// ---------------- multi-block stable radix sort (8-bit digit) ----------------
__global__ void rhist_kernel(const unsigned long long* __restrict__ src, int shift) {
    __shared__ unsigned h[256];
    int row = blockIdx.x >> 4, seg = blockIdx.x & 15;
    int tid = threadIdx.x;
    if (tid < 256) h[tid] = 0;
    __syncthreads();
    const unsigned long long* s = src + (size_t)row*R_N + (size_t)seg*R_SEG;
#pragma unroll
    for (int r = 0; r < R_EPT; r++) {
        unsigned dg = (unsigned)(s[r*R_THREADS + tid] >> shift) & 255u;
        atomicAdd(&h[dg], 1u);
    }
    __syncthreads();
    if (tid < 256)
        g_rhist[((size_t)row*256 + tid)*R_NSEG + seg] = h[tid];
}

__global__ void rscan_kernel() {
    int row = blockIdx.x, dg = threadIdx.x;   // 256 threads
    unsigned* hp = g_rhist + ((size_t)row*256 + dg)*R_NSEG;
    unsigned v[R_NSEG]; unsigned tot = 0;
#pragma unroll
    for (int s2 = 0; s2 < R_NSEG; s2++) { unsigned t = hp[s2]; v[s2] = tot; tot += t; }
    unsigned lane = dg & 31, w = dg >> 5;
    unsigned x = tot;
#pragma unroll
    for (int o = 1; o < 32; o <<= 1) { unsigned y = __shfl_up_sync(0xffffffffu, x, o); if (lane >= o) x += y; }
    __shared__ unsigned wsum[8];
    if (lane == 31) wsum[w] = x;
    __syncthreads();
    if (dg == 0) { unsigned run = 0; for (int i = 0; i < 8; i++) { unsigned t = wsum[i]; wsum[i] = run; run += t; } }
    __syncthreads();
    unsigned base0 = (x - tot) + wsum[w];
#pragma unroll
    for (int s2 = 0; s2 < R_NSEG; s2++) hp[s2] = base0 + v[s2];
}

__global__ void __launch_bounds__(R_THREADS)
rscatter_kernel(const unsigned long long* __restrict__ src,
                unsigned long long* __restrict__ dst, int shift) {
    __shared__ unsigned base[256];
    __shared__ unsigned bb0[256];
    __shared__ unsigned delta[256];
    __shared__ unsigned scanbuf[8];
    __shared__ unsigned long long stage[R_SEG];   // 32KB; rounds reuse it as wcnt/woff
    unsigned short* wcnt = (unsigned short*)stage;              // 16*256 u16 = 8KB
    unsigned*       woff = (unsigned*)(stage + 1024);           // 16*256 u32 = 16KB

    int row = blockIdx.x >> 4, seg = blockIdx.x & 15;
    int tid = threadIdx.x, w = tid >> 5, lane = tid & 31;
    const unsigned long long* s = src + (size_t)row*R_N + (size_t)seg*R_SEG;

    unsigned long long kv[R_EPT];
    unsigned posG[R_EPT];
#pragma unroll
    for (int r = 0; r < R_EPT; r++) kv[r] = s[r*R_THREADS + tid];

    if (tid < 256) {
        unsigned bv = g_rhist[((size_t)row*256 + tid)*R_NSEG + seg];
        base[tid] = bv; bb0[tid] = bv;
    }

    unsigned* wc32 = (unsigned*)wcnt;
#pragma unroll
    for (int r = 0; r < R_EPT; r++) {
        // clear per-warp counters (2048 u32)
        wc32[tid] = 0; wc32[tid + 512] = 0; wc32[tid + 1024] = 0; wc32[tid + 1536] = 0;
        unsigned dg = (unsigned)(kv[r] >> shift) & 255u;
        unsigned mask = __match_any_sync(0xffffffffu, dg);
        unsigned lr = __popc(mask & ((1u << lane) - 1u));
        unsigned cnt = __popc(mask);
        __syncthreads();
        if (lr == 0) wcnt[w*256 + dg] = (unsigned short)cnt;
        __syncthreads();
        if (tid < 256) {
            unsigned run = base[tid];
#pragma unroll
            for (int ww = 0; ww < 16; ww++) {
                unsigned c2 = wcnt[ww*256 + tid];
                woff[ww*256 + tid] = run;
                run += c2;
            }
            base[tid] = run;
        }
        __syncthreads();
        posG[r] = woff[w*256 + dg] + lr;
    }
    __syncthreads();   // protect woff reuse below

    // local exclusive scan of per-digit counts -> delta[dg] = globalBase - localStart
    if (tid < 256) {
        unsigned c = base[tid] - bb0[tid];
        unsigned x = c;
#pragma unroll
        for (int o = 1; o < 32; o <<= 1) { unsigned y = __shfl_up_sync(0xffffffffu, x, o); if (lane >= o) x += y; }
        woff[tid] = x - c;                 // intra-warp exclusive
        if (lane == 31) scanbuf[w] = x;    // warp total (inclusive of warp)
    }
    __syncthreads();
    if (tid == 0) { unsigned run = 0; for (int i = 0; i < 8; i++) { unsigned t2 = scanbuf[i]; scanbuf[i] = run; run += t2; } }
    __syncthreads();
    if (tid < 256) delta[tid] = bb0[tid] - (woff[tid] + scanbuf[tid >> 5]);
    __syncthreads();

    // stage into locally-sorted order (smem), then write out coalesced runs
#pragma unroll
    for (int r = 0; r < R_EPT; r++) {
        unsigned dg = (unsigned)(kv[r] >> shift) & 255u;
        stage[posG[r] - delta[dg]] = kv[r];
    }
    __syncthreads();
    unsigned long long* d = dst + (size_t)row*R_N;
#pragma unroll
    for (int r = 0; r < R_EPT; r++) {
        unsigned i = r*R_THREADS + tid;
        unsigned long long k2 = stage[i];
        unsigned dg = (unsigned)(k2 >> shift) & 255u;
        d[delta[dg] + i] = k2;
    }
}

__global__ void extract_kernel() {
    size_t gid = (size_t)blockIdx.x*256 + threadIdx.x;
    unsigned long long kv = g_sortA[gid];
    g_idx[gid] = (int)(kv & 0xFFFFFFFFu);
    unsigned u = (unsigned)(kv >> 32);
    u = (u & 0x80000000u) ? (u ^ 0x80000000u) : ~u;
    g_vs[gid] = __uint_as_float(u);
}

__global__ void gather_kernel() {
    size_t gid = (size_t)blockIdx.x*256 + threadIdx.x;
    int row = (int)(gid / HWv);
    int b = row >> 6, c = row & 63;
    int j = g_idx[gid];
    size_t srcb = ((size_t)(b*QKVC) + c)*HWv;
    g_gq1[gid] = g_qkv[srcb + j];
    g_gk1[gid] = g_qkv[srcb + (size_t)64*HWv + j];
    g_gq2[gid] = g_qkv[srcb + (size_t)128*HWv + j];
    g_gk2[gid] = g_qkv[srcb + (size_t)192*HWv + j];
}

// ---------------- attention ----------------
__global__ void norm_kernel() {
    int id = blockIdx.x;
    int d = id & 63, h = (id>>6)&3, b = (id>>8)&1, qk = (id>>9)&1, var = (id>>10)&1;
    const float* src = var ? (qk ? g_gk2 : g_gq2) : (qk ? g_gk1 : g_gq1);
    int c = h*16 + (d>>2), f = d & 3;
    size_t base = ((size_t)(b*64 + c))*HWv + (var ? (size_t)f : (size_t)f*HWP_);
    int stride = var ? 4 : 1;
    float s = 0.f;
    for (int i = threadIdx.x; i < HWP_; i += 128) {
        float v = src[base + (size_t)i*stride];
        s += v * v;
    }
    __shared__ float red[128];
    red[threadIdx.x] = s;
    __syncthreads();
    for (int o = 64; o > 0; o >>= 1) {
        if (threadIdx.x < o) red[threadIdx.x] += red[threadIdx.x + o];
        __syncthreads();
    }
    if (threadIdx.x == 0) g_norm[id] = 1.0f / fmaxf(sqrtf(red[0]), 1e-12f);
}

__global__ void qk_kernel() {
    __shared__ float Qs[64][65];
    __shared__ float Ks[64][65];
    int t = threadIdx.x;
    int vbh = blockIdx.y;
    int var = vbh >> 3, b = (vbh>>2)&1, h = vbh & 3;
    const float* qsrc = var ? g_gq2 : g_gq1;
    const float* ksrc = var ? g_gk2 : g_gk1;
    int ty = t >> 4, tx = t & 15;
    float acc[4][4];
#pragma unroll
    for (int i = 0; i < 4; i++)
#pragma unroll
        for (int j = 0; j < 4; j++) acc[i][j] = 0.f;
    int n0 = blockIdx.x * 512;
    for (int tile = 0; tile < 8; tile++) {
        int nb = n0 + tile*64;
#pragma unroll
        for (int rr = 0; rr < 16; rr++) {
            int l = rr*256 + t; int d = l >> 6; int nn = l & 63;
            int c = h*16 + (d>>2), f = d & 3;
            size_t addr = ((size_t)(b*64 + c))*HWv +
                          (var ? (size_t)4*(nb+nn) + f : (size_t)f*HWP_ + nb + nn);
            Qs[d][nn] = qsrc[addr];
            Ks[d][nn] = ksrc[addr];
        }
        __syncthreads();
#pragma unroll 8
        for (int nn = 0; nn < 64; nn++) {
            float qa[4], ka[4];
#pragma unroll
            for (int i = 0; i < 4; i++) { qa[i] = Qs[ty*4+i][nn]; ka[i] = Ks[tx*4+i][nn]; }
#pragma unroll
            for (int i = 0; i < 4; i++)
#pragma unroll
                for (int j = 0; j < 4; j++) acc[i][j] += qa[i]*ka[j];
        }
        __syncthreads();
    }
    float* sp = g_Spart + ((size_t)(vbh*32 + blockIdx.x))*4096;
#pragma unroll
    for (int i = 0; i < 4; i++)
#pragma unroll
        for (int j = 0; j < 4; j++)
            sp[(ty*4+i)*64 + tx*4 + j] = acc[i][j];
}

// one block per (vbh, d); 64 threads, one e each
__global__ void softmax_kernel(const float* __restrict__ temp) {
    int blk = blockIdx.x;
    int vbh = blk >> 6, d = blk & 63;
    int var = vbh >> 3, b = (vbh>>2)&1, h = vbh & 3;
    int e = threadIdx.x;   // 64
    float sk = g_norm[(var<<10) | (1<<9) | (b<<8) | (h<<6) | e];
    float invq = g_norm[(var<<10) | (b<<8) | (h<<6) | d];
    float T = temp[h];
    const float* sp = g_Spart + (size_t)vbh*32*4096 + d*64 + e;
    float s = 0.f;
#pragma unroll
    for (int sl = 0; sl < 32; sl++) s += sp[(size_t)sl*4096];
    float ex = expf(s * invq * sk * T);
    __shared__ float red[64];
    red[e] = ex;
    __syncthreads();
    if (e < 32) {
        float p = red[e] + red[e + 32];
#pragma unroll
        for (int o = 16; o > 0; o >>= 1) p += __shfl_down_sync(0xffffffffu, p, o);
        if (e == 0) red[0] = p;
    }
    __syncthreads();
    float r = 1.0f / (red[0] + 1.0f);
    g_attn[(size_t)vbh*4096 + d*64 + e] = ex * r;
}

__global__ void av_kernel() {
    __shared__ float As[4096];
    int t = threadIdx.x;
    int bid = blockIdx.x;
    int nblk = bid & 63;
    int h = (bid>>6)&3, b = (bid>>8)&1, var = (bid>>9)&1;
    int vbh = (var<<3) | (b<<2) | h;
    for (int l = t; l < 4096; l += 256) As[l] = g_attn[(size_t)vbh*4096 + l];
    __syncthreads();
    int n = nblk*256 + t;
    float acc[64];
#pragma unroll
    for (int d2 = 0; d2 < 64; d2++) acc[d2] = 0.f;
#pragma unroll 4
    for (int e0 = 0; e0 < 64; e0 += 4) {
        int ce = h*16 + (e0 >> 2);
        size_t cb = ((size_t)(b*64 + ce))*HWv;
        float v0, v1, v2, v3;
        if (var) {
            float4 vv = *(const float4*)&g_vs[cb + 4*(size_t)n];
            v0 = vv.x; v1 = vv.y; v2 = vv.z; v3 = vv.w;
        } else {
            v0 = g_vs[cb + n];
            v1 = g_vs[cb + HWP_ + n];
            v2 = g_vs[cb + 2*HWP_ + n];
            v3 = g_vs[cb + 3*HWP_ + n];
        }
#pragma unroll
        for (int d2 = 0; d2 < 64; d2++) {
            float4 a = *(const float4*)&As[d2*64 + e0];
            acc[d2] += a.x*v0 + a.y*v1 + a.z*v2 + a.w*v3;
        }
    }
    float* o = var ? g_out2 : g_out1;
#pragma unroll 1
    for (int d2 = 0; d2 < 64; d2++) {
        int cd = h*16 + (d2>>2), fd = d2 & 3;
        o[((size_t)(b*64 + cd))*HWv + (var ? (size_t)4*n + fd : (size_t)fd*HWP_ + n)] = acc[d2];
    }
}

// ---------------- epilogue ----------------
__global__ void prod_scatter_kernel() {
    size_t gid = (size_t)blockIdx.x*256 + threadIdx.x;   // B*C*HW
    size_t row = gid / HWv;
    int j = g_idx[gid];
    g_prod[row*HWv + j] = g_out1[gid] * g_out2[gid];
}

__global__ void invw_kernel() {
    size_t gid = (size_t)blockIdx.x*256 + threadIdx.x;   // B*CH*HW
    size_t bc = gid / HWv;
    int p = (int)(gid % HWv);
    int h = p >> 8;
    int j = p & 255;
    int v = g_idxw[gid];
    g_invw[bc*HWv + (size_t)h*W_ + v] = j;
}

__global__ void invh_kernel() {
    size_t gid = (size_t)blockIdx.x*256 + threadIdx.x;   // B*CH*HW
    size_t bc = gid / HWv;
    int p = (int)(gid % HWv);
    int i = p >> 8;
    int w = p & 255;
    int v = g_idxh[gid];
    g_invh[bc*HWv + (size_t)v*W_ + w] = i;
}

__global__ void unsort1_kernel() {
    size_t gid = (size_t)blockIdx.x*256 + threadIdx.x;   // B*CH*HW
    size_t bc = gid / HWv;
    int b = (int)(bc / CH_), c = (int)(bc % CH_);
    int p = (int)(gid % HWv);
    int h = p >> 8;
    int iw = g_invw[gid];
    g_tmp[gid] = g_proj[((size_t)(b*C_ + c))*HWv + (size_t)h*W_ + iw];
}

__global__ void unsort2_kernel(float* __restrict__ out) {
    size_t gid = (size_t)blockIdx.x*256 + threadIdx.x;   // B*C*HW
    int b = (int)(gid / ((size_t)C_*HWv));
    size_t r = gid % ((size_t)C_*HWv);
    int c = (int)(r / HWv);
    int p = (int)(r % HWv);
    if (c < CH_) {
        int w = p & 255;
        size_t bc = (size_t)(b*CH_ + c);
        int ih = g_invh[bc*HWv + p];
        out[gid] = g_tmp[bc*HWv + (size_t)ih*W_ + w];
    } else {
        out[gid] = g_proj[gid];
    }
}

// ---------------- launch ----------------
extern "C" void kernel_launch(void* const* d_in, const int* in_sizes, int n_in,
                              void* d_out, int out_size) {
    const float* x     = (const float*)d_in[0];
    const float* qkvw  = (const float*)d_in[1];
    const float* dww   = (const float*)d_in[2];
    const float* projw = (const float*)d_in[3];
    const float* temp  = (const float*)d_in[4];
    float* out = (float*)d_out;

    float *p_xcat, *p_qkvpre, *p_qkv, *p_prod, *p_proj;
    unsigned long long *p_sA, *p_sB;
    cudaGetSymbolAddress((void**)&p_xcat,   g_xcat);
    cudaGetSymbolAddress((void**)&p_qkvpre, g_qkv_pre);
    cudaGetSymbolAddress((void**)&p_qkv,    g_qkv);
    cudaGetSymbolAddress((void**)&p_prod,   g_prod);
    cudaGetSymbolAddress((void**)&p_proj,   g_proj);
    cudaGetSymbolAddress((void**)&p_sA,     g_sortA);
    cudaGetSymbolAddress((void**)&p_sB,     g_sortB);

    const int NBC  = (B_*C_*HWv) / 256;     // 32768
    const int NBCH = (B_*CH_*HWv) / 256;    // 16384

    // stage A: small sorts
    sort_h_kernel<<<B_*CH_*W_, 256>>>(x);
    sort_w_kernel<<<B_*CH_*H_, 256>>>();
    copy_rest_kernel<<<NBCH, 256>>>(x);
    invw_kernel<<<NBCH, 256>>>();
    invh_kernel<<<NBCH, 256>>>();

    // stage B: convs
    conv1x1_kernel<<<dim3(HWv/64, QKVC/64, B_), 256>>>(p_xcat, qkvw, p_qkvpre, QKVC);
    dwconv_kernel<<<(B_*QKVC*HWv)/256, 256>>>(p_qkvpre, dww, p_qkv);

    // stage C: big stable argsort of v rows (multi-block radix, 4 passes)
    build_keys_kernel<<<NBC, 256>>>();
    {
        const int NB = R_ROWS * R_NSEG;   // 2048
        unsigned long long* bufs[2] = { p_sA, p_sB };
        int shifts[4] = { 32, 40, 48, 56 };
        for (int p2 = 0; p2 < 4; p2++) {
            unsigned long long* s = bufs[p2 & 1];
            unsigned long long* d = bufs[(p2 & 1) ^ 1];
            rhist_kernel   <<<NB, R_THREADS>>>(s, shifts[p2]);
            rscan_kernel   <<<R_ROWS, 256>>>();
            rscatter_kernel<<<NB, R_THREADS>>>(s, d, shifts[p2]);
        }
    }
    extract_kernel<<<NBC, 256>>>();
    gather_kernel<<<NBC, 256>>>();

    // stage D: attention (both variants)
    norm_kernel<<<2048, 128>>>();
    qk_kernel<<<dim3(32, 16), 256>>>();
    softmax_kernel<<<16*64, 64>>>(temp);
    av_kernel<<<1024, 256>>>();

    // stage E: epilogue
    prod_scatter_kernel<<<NBC, 256>>>();
    conv1x1_kernel<<<dim3(HWv/64, 1, B_), 256>>>(p_prod, projw, p_proj, C_);
    unsort1_kernel<<<NBCH, 256>>>();
    unsort2_kernel<<<NBCH*2, 256>>>(out);
}

// round 5
// speedup vs baseline: 1.2486x; 1.0197x over previous
#include <cuda_runtime.h>
#include <math.h>

// ---------------- constants ----------------
#define B_   2
#define C_   64
#define CH_  32
#define H_   256
#define W_   256
#define HWv  65536
#define QKVC 320
#define NH_  4
#define HWP_ 16384

// radix sort config
#define R_ROWS 128
#define R_N    65536
#define R_SEG  4096
#define R_NSEG 16
#define R_THREADS 512
#define R_EPT  8

// ---------------- scratch (static device memory; no allocs) ----------------
__device__ float g_xcat[B_*C_*HWv];              // sorted ch<32 + copied ch>=32
__device__ int   g_invh[B_*CH_*HWv];
__device__ int   g_invw[B_*CH_*HWv];
__device__ float g_qkv_pre[B_*QKVC*HWv];         // conv1x1 output
__device__ float g_qkv[B_*QKVC*HWv];             // after dwconv (q1,k1,q2,k2; v -> keys)
__device__ unsigned long long g_sortA[B_*C_*HWv];
__device__ unsigned long long g_sortB[B_*C_*HWv];
__device__ unsigned g_rhist[R_ROWS*256*R_NSEG];  // 2MB
__device__ int   g_idx[B_*C_*HWv];               // big sort permutation
__device__ float g_vs [B_*C_*HWv];               // sorted v values
__device__ float g_gq1[B_*C_*HWv];
__device__ float g_gk1[B_*C_*HWv];
__device__ float g_gq2[B_*C_*HWv];
__device__ float g_gk2[B_*C_*HWv];
__device__ float g_norm[2048];                    // [var][qk][b][h][d] packed
__device__ float g_Spart[16*32*4096];
__device__ float g_attn[16*4096];
__device__ float g_out1[B_*C_*HWv];
__device__ float g_prod[B_*C_*HWv];
__device__ float g_proj[B_*C_*HWv];

// ---------------- small stable bitonic sort (256 elems) ----------------
__device__ __forceinline__ bool pair_gt(float va, int ia, float vb, int ib) {
    return (va > vb) || (va == vb && ia > ib);
}

__device__ __forceinline__ void bitonic256(float* sv, int* si) {
    int t = threadIdx.x;
    for (int k = 2; k <= 256; k <<= 1) {
        for (int j = k >> 1; j > 0; j >>= 1) {
            int ixj = t ^ j;
            if (ixj > t) {
                bool up = ((t & k) == 0);
                float va = sv[t], vb = sv[ixj];
                int   ia = si[t], ib = si[ixj];
                bool sw = up ? pair_gt(va, ia, vb, ib) : pair_gt(vb, ib, va, ia);
                if (sw) { sv[t] = vb; si[t] = ib; sv[ixj] = va; si[ixj] = ia; }
            }
            __syncthreads();
        }
    }
}

// sort columns (axis H); write sorted vals + inverse permutation directly
__global__ void sort_h_kernel(const float* __restrict__ x) {
    __shared__ float sv[256];
    __shared__ int   si[256];
    int blk = blockIdx.x;                 // b*CH*W
    int b = blk / (CH_*W_);
    int c = (blk / W_) % CH_;
    int w = blk % W_;
    int t = threadIdx.x;
    const float* xp = x + ((size_t)(b*C_ + c))*HWv + w;
    sv[t] = xp[(size_t)t * W_];
    si[t] = t;
    __syncthreads();
    bitonic256(sv, si);
    g_xcat[((size_t)(b*C_ + c))*HWv + (size_t)t*W_ + w] = sv[t];
    // invh[si[t]][w] = t
    g_invh[((size_t)(b*CH_ + c))*HWv + (size_t)si[t]*W_ + w] = t;
}

// sort rows (axis W) of g_xcat in place; inverse perm directly
__global__ void sort_w_kernel() {
    __shared__ float sv[256];
    __shared__ int   si[256];
    int blk = blockIdx.x;                 // b*CH*H
    int b = blk / (CH_*H_);
    int c = (blk / H_) % CH_;
    int h = blk % H_;
    int t = threadIdx.x;
    float* base = g_xcat + ((size_t)(b*C_ + c))*HWv + (size_t)h*W_;
    sv[t] = base[t];
    si[t] = t;
    __syncthreads();
    bitonic256(sv, si);
    base[t] = sv[t];
    g_invw[((size_t)(b*CH_ + c))*HWv + (size_t)h*W_ + si[t]] = t;
}

__global__ void copy_rest_kernel(const float* __restrict__ x) {
    size_t gid = (size_t)blockIdx.x*256 + threadIdx.x;   // B*32*HW/4
    int b = (int)(gid / ((size_t)CH_*HWv/4));
    size_t r = gid % ((size_t)CH_*HWv/4);
    int c = CH_ + (int)(r / (HWv/4));
    int p = (int)(r % (HWv/4)) * 4;
    size_t off = ((size_t)(b*C_ + c))*HWv + p;
    *(float4*)&g_xcat[off] = *(const float4*)&x[off];
}

// ---------------- conv1x1 (IC=64; tile 128px x 64oc; 48KB smem exactly) ----------------
__global__ void conv1x1_kernel(const float* __restrict__ in, const float* __restrict__ w,
                               float* __restrict__ out, int OC) {
    __shared__ float Xs[64][128];   // [ic][px]  32KB
    __shared__ float Ws[64][64];    // [ic][oc]  16KB
    int p0  = blockIdx.x * 128;
    int oc0 = blockIdx.y * 64;
    int b   = blockIdx.z;
    int t   = threadIdx.x;
#pragma unroll
    for (int r = 0; r < 8; r++) {
        int l = r*256 + t; int ic = l >> 5; int grp = l & 31;
        *(float4*)&Xs[ic][grp*4] = *(const float4*)&in[((size_t)(b*64 + ic))*HWv + p0 + grp*4];
    }
#pragma unroll
    for (int r = 0; r < 16; r++) {
        int l = r*256 + t; int oc = l >> 6; int ic = l & 63;
        Ws[ic][oc] = w[(size_t)(oc0 + oc)*64 + ic];
    }
    __syncthreads();
    int tx = t & 15, ty = t >> 4;        // px group, oc group
    float acc[4][8];
#pragma unroll
    for (int i = 0; i < 4; i++)
#pragma unroll
        for (int j = 0; j < 8; j++) acc[i][j] = 0.f;
#pragma unroll
    for (int ic = 0; ic < 64; ic++) {
        float4 wv = *(const float4*)&Ws[ic][ty*4];
        float4 x0 = *(const float4*)&Xs[ic][tx*8];
        float4 x1 = *(const float4*)&Xs[ic][tx*8+4];
        float xv[8] = {x0.x,x0.y,x0.z,x0.w,x1.x,x1.y,x1.z,x1.w};
        float wa[4] = {wv.x,wv.y,wv.z,wv.w};
#pragma unroll
        for (int i = 0; i < 4; i++)
#pragma unroll
            for (int j = 0; j < 8; j++) acc[i][j] += wa[i]*xv[j];
    }
#pragma unroll
    for (int i = 0; i < 4; i++) {
        size_t ob = ((size_t)(b*OC + oc0 + ty*4 + i))*HWv + p0 + tx*8;
        *(float4*)&out[ob]     = make_float4(acc[i][0],acc[i][1],acc[i][2],acc[i][3]);
        *(float4*)&out[ob + 4] = make_float4(acc[i][4],acc[i][5],acc[i][6],acc[i][7]);
    }
}

// ---------------- depthwise 3x3 SAME (4 px/thread) + key build for v ----------------
__global__ void dwconv_kernel(const float* __restrict__ in, const float* __restrict__ wd) {
    size_t gid = (size_t)blockIdx.x*256 + threadIdx.x;   // B*QKVC*HW/4
    int p4 = (int)((gid % (HWv/4)) * 4);
    size_t bc = gid / (HWv/4);
    int ch = (int)(bc % QKVC);
    int b  = (int)(bc / QKVC);
    int h = p4 >> 8, w0 = p4 & 255;
    const float* ip = in + bc*HWv;
    float wreg[9];
#pragma unroll
    for (int i = 0; i < 9; i++) wreg[i] = __ldg(&wd[(size_t)ch*9 + i]);
    float o[4] = {0.f,0.f,0.f,0.f};
#pragma unroll
    for (int dy = -1; dy <= 1; dy++) {
        int hh = h + dy;
        if (hh < 0 || hh >= H_) continue;
        const float* rp = ip + (size_t)hh*W_;
        float a[6];
#pragma unroll
        for (int k2 = 0; k2 < 6; k2++) {
            int ww = w0 - 1 + k2;
            a[k2] = (ww >= 0 && ww < W_) ? rp[ww] : 0.f;
        }
        float wl = wreg[(dy+1)*3], wm = wreg[(dy+1)*3+1], wr = wreg[(dy+1)*3+2];
#pragma unroll
        for (int k2 = 0; k2 < 4; k2++)
            o[k2] += a[k2]*wl + a[k2+1]*wm + a[k2+2]*wr;
    }
    if (ch < 256) {
        *(float4*)&g_qkv[bc*HWv + p4] = make_float4(o[0],o[1],o[2],o[3]);
    } else {
        int row = b*64 + (ch - 256);
        unsigned long long* kp = &g_sortA[(size_t)row*HWv + p4];
#pragma unroll
        for (int k2 = 0; k2 < 4; k2++) {
            unsigned u = __float_as_uint(o[k2]);
            u ^= (u & 0x80000000u) ? 0xFFFFFFFFu : 0x80000000u;
            kp[k2] = ((unsigned long long)u << 32) | (unsigned)(p4 + k2);
        }
    }
}

// ---------------- multi-block stable radix sort (8-bit digit) ----------------
__global__ void rhist_kernel(const unsigned long long* __restrict__ src, int shift) {
    __shared__ unsigned h[256];
    int row = blockIdx.x >> 4, seg = blockIdx.x & 15;
    int tid = threadIdx.x;
    if (tid < 256) h[tid] = 0;
    __syncthreads();
    const unsigned long long* s = src + (size_t)row*R_N + (size_t)seg*R_SEG;
#pragma unroll
    for (int r = 0; r < R_EPT; r++) {
        unsigned dg = (unsigned)(s[r*R_THREADS + tid] >> shift) & 255u;
        atomicAdd(&h[dg], 1u);
    }
    __syncthreads();
    if (tid < 256)
        g_rhist[((size_t)row*256 + tid)*R_NSEG + seg] = h[tid];
}

__global__ void rscan_kernel() {
    int row = blockIdx.x, dg = threadIdx.x;   // 256 threads
    unsigned* hp = g_rhist + ((size_t)row*256 + dg)*R_NSEG;
    unsigned v[R_NSEG]; unsigned tot = 0;
#pragma unroll
    for (int s2 = 0; s2 < R_NSEG; s2++) { unsigned t = hp[s2]; v[s2] = tot; tot += t; }
    unsigned lane = dg & 31, w = dg >> 5;
    unsigned x = tot;
#pragma unroll
    for (int o = 1; o < 32; o <<= 1) { unsigned y = __shfl_up_sync(0xffffffffu, x, o); if (lane >= o) x += y; }
    __shared__ unsigned wsum[8];
    if (lane == 31) wsum[w] = x;
    __syncthreads();
    if (dg == 0) { unsigned run = 0; for (int i = 0; i < 8; i++) { unsigned t = wsum[i]; wsum[i] = run; run += t; } }
    __syncthreads();
    unsigned base0 = (x - tot) + wsum[w];
#pragma unroll
    for (int s2 = 0; s2 < R_NSEG; s2++) hp[s2] = base0 + v[s2];
}

__global__ void __launch_bounds__(R_THREADS)
rscatter_kernel(const unsigned long long* __restrict__ src,
                unsigned long long* __restrict__ dst, int shift) {
    __shared__ unsigned base[256];
    __shared__ unsigned bb0[256];
    __shared__ unsigned delta[256];
    __shared__ unsigned scanbuf[8];
    __shared__ unsigned long long stage[R_SEG];   // 32KB; rounds reuse it as wcnt/woff
    unsigned short* wcnt = (unsigned short*)stage;              // 16*256 u16 = 8KB
    unsigned*       woff = (unsigned*)(stage + 1024);           // 16*256 u32 = 16KB

    int row = blockIdx.x >> 4, seg = blockIdx.x & 15;
    int tid = threadIdx.x, w = tid >> 5, lane = tid & 31;
    const unsigned long long* s = src + (size_t)row*R_N + (size_t)seg*R_SEG;

    unsigned long long kv[R_EPT];
    unsigned posG[R_EPT];
#pragma unroll
    for (int r = 0; r < R_EPT; r++) kv[r] = s[r*R_THREADS + tid];

    if (tid < 256) {
        unsigned bv = g_rhist[((size_t)row*256 + tid)*R_NSEG + seg];
        base[tid] = bv; bb0[tid] = bv;
    }

    unsigned* wc32 = (unsigned*)wcnt;
#pragma unroll
    for (int r = 0; r < R_EPT; r++) {
        wc32[tid] = 0; wc32[tid + 512] = 0; wc32[tid + 1024] = 0; wc32[tid + 1536] = 0;
        unsigned dg = (unsigned)(kv[r] >> shift) & 255u;
        unsigned mask = __match_any_sync(0xffffffffu, dg);
        unsigned lr = __popc(mask & ((1u << lane) - 1u));
        unsigned cnt = __popc(mask);
        __syncthreads();
        if (lr == 0) wcnt[w*256 + dg] = (unsigned short)cnt;
        __syncthreads();
        if (tid < 256) {
            unsigned run = base[tid];
#pragma unroll
            for (int ww = 0; ww < 16; ww++) {
                unsigned c2 = wcnt[ww*256 + tid];
                woff[ww*256 + tid] = run;
                run += c2;
            }
            base[tid] = run;
        }
        __syncthreads();
        posG[r] = woff[w*256 + dg] + lr;
    }
    __syncthreads();

    if (tid < 256) {
        unsigned c = base[tid] - bb0[tid];
        unsigned x = c;
#pragma unroll
        for (int o = 1; o < 32; o <<= 1) { unsigned y = __shfl_up_sync(0xffffffffu, x, o); if (lane >= o) x += y; }
        woff[tid] = x - c;
        if (lane == 31) scanbuf[w] = x;
    }
    __syncthreads();
    if (tid == 0) { unsigned run = 0; for (int i = 0; i < 8; i++) { unsigned t2 = scanbuf[i]; scanbuf[i] = run; run += t2; } }
    __syncthreads();
    if (tid < 256) delta[tid] = bb0[tid] - (woff[tid] + scanbuf[tid >> 5]);
    __syncthreads();

#pragma unroll
    for (int r = 0; r < R_EPT; r++) {
        unsigned dg = (unsigned)(kv[r] >> shift) & 255u;
        stage[posG[r] - delta[dg]] = kv[r];
    }
    __syncthreads();
    unsigned long long* d = dst + (size_t)row*R_N;
#pragma unroll
    for (int r = 0; r < R_EPT; r++) {
        unsigned i = r*R_THREADS + tid;
        unsigned long long k2 = stage[i];
        unsigned dg = (unsigned)(k2 >> shift) & 255u;
        d[delta[dg] + i] = k2;
    }
}

// ---------------- fused extract + gather ----------------
__global__ void extract_gather_kernel() {
    size_t gid = (size_t)blockIdx.x*256 + threadIdx.x;
    int row = (int)(gid / HWv);
    int b = row >> 6, c = row & 63;
    unsigned long long kv = g_sortA[gid];
    int j = (int)(kv & 0xFFFFFFFFu);
    g_idx[gid] = j;
    unsigned u = (unsigned)(kv >> 32);
    u = (u & 0x80000000u) ? (u ^ 0x80000000u) : ~u;
    g_vs[gid] = __uint_as_float(u);
    size_t srcb = ((size_t)(b*QKVC) + c)*HWv;
    g_gq1[gid] = g_qkv[srcb + j];
    g_gk1[gid] = g_qkv[srcb + (size_t)64*HWv + j];
    g_gq2[gid] = g_qkv[srcb + (size_t)128*HWv + j];
    g_gk2[gid] = g_qkv[srcb + (size_t)192*HWv + j];
}

// ---------------- attention ----------------
__global__ void norm_kernel() {
    int id = blockIdx.x;
    int d = id & 63, h = (id>>6)&3, b = (id>>8)&1, qk = (id>>9)&1, var = (id>>10)&1;
    const float* src = var ? (qk ? g_gk2 : g_gq2) : (qk ? g_gk1 : g_gq1);
    int c = h*16 + (d>>2), f = d & 3;
    size_t base = ((size_t)(b*64 + c))*HWv + (var ? (size_t)f : (size_t)f*HWP_);
    int stride = var ? 4 : 1;
    float s = 0.f;
    for (int i = threadIdx.x; i < HWP_; i += 128) {
        float v = src[base + (size_t)i*stride];
        s += v * v;
    }
    __shared__ float red[128];
    red[threadIdx.x] = s;
    __syncthreads();
    for (int o = 64; o > 0; o >>= 1) {
        if (threadIdx.x < o) red[threadIdx.x] += red[threadIdx.x + o];
        __syncthreads();
    }
    if (threadIdx.x == 0) g_norm[id] = 1.0f / fmaxf(sqrtf(red[0]), 1e-12f);
}

__global__ void qk_kernel() {
    __shared__ float Qs[64][65];
    __shared__ float Ks[64][65];
    int t = threadIdx.x;
    int vbh = blockIdx.y;
    int var = vbh >> 3, b = (vbh>>2)&1, h = vbh & 3;
    const float* qsrc = var ? g_gq2 : g_gq1;
    const float* ksrc = var ? g_gk2 : g_gk1;
    int ty = t >> 4, tx = t & 15;
    float acc[4][4];
#pragma unroll
    for (int i = 0; i < 4; i++)
#pragma unroll
        for (int j = 0; j < 4; j++) acc[i][j] = 0.f;
    int n0 = blockIdx.x * 512;
    for (int tile = 0; tile < 8; tile++) {
        int nb = n0 + tile*64;
#pragma unroll
        for (int rr = 0; rr < 16; rr++) {
            int l = rr*256 + t; int d = l >> 6; int nn = l & 63;
            int c = h*16 + (d>>2), f = d & 3;
            size_t addr = ((size_t)(b*64 + c))*HWv +
                          (var ? (size_t)4*(nb+nn) + f : (size_t)f*HWP_ + nb + nn);
            Qs[d][nn] = qsrc[addr];
            Ks[d][nn] = ksrc[addr];
        }
        __syncthreads();
#pragma unroll 8
        for (int nn = 0; nn < 64; nn++) {
            float qa[4], ka[4];
#pragma unroll
            for (int i = 0; i < 4; i++) { qa[i] = Qs[ty*4+i][nn]; ka[i] = Ks[tx*4+i][nn]; }
#pragma unroll
            for (int i = 0; i < 4; i++)
#pragma unroll
                for (int j = 0; j < 4; j++) acc[i][j] += qa[i]*ka[j];
        }
        __syncthreads();
    }
    float* sp = g_Spart + ((size_t)(vbh*32 + blockIdx.x))*4096;
#pragma unroll
    for (int i = 0; i < 4; i++)
#pragma unroll
        for (int j = 0; j < 4; j++)
            sp[(ty*4+i)*64 + tx*4 + j] = acc[i][j];
}

__global__ void softmax_kernel(const float* __restrict__ temp) {
    int blk = blockIdx.x;
    int vbh = blk >> 6, d = blk & 63;
    int var = vbh >> 3, b = (vbh>>2)&1, h = vbh & 3;
    int e = threadIdx.x;   // 64
    float sk = g_norm[(var<<10) | (1<<9) | (b<<8) | (h<<6) | e];
    float invq = g_norm[(var<<10) | (b<<8) | (h<<6) | d];
    float T = temp[h];
    const float* sp = g_Spart + (size_t)vbh*32*4096 + d*64 + e;
    float s = 0.f;
#pragma unroll
    for (int sl = 0; sl < 32; sl++) s += sp[(size_t)sl*4096];
    float ex = expf(s * invq * sk * T);
    __shared__ float red[64];
    red[e] = ex;
    __syncthreads();
    if (e < 32) {
        float p = red[e] + red[e + 32];
#pragma unroll
        for (int o = 16; o > 0; o >>= 1) p += __shfl_down_sync(0xffffffffu, p, o);
        if (e == 0) red[0] = p;
    }
    __syncthreads();
    float r = 1.0f / (red[0] + 1.0f);
    g_attn[(size_t)vbh*4096 + d*64 + e] = ex * r;
}

// av var=0: writes g_out1
__global__ void av0_kernel() {
    __shared__ float As[4096];
    int t = threadIdx.x;
    int bid = blockIdx.x;                 // 512: (b,h,nblk)
    int nblk = bid & 63;
    int h = (bid>>6)&3, b = (bid>>8)&1;
    int vbh = (b<<2) | h;
    for (int l = t; l < 4096; l += 256) As[l] = g_attn[(size_t)vbh*4096 + l];
    __syncthreads();
    int n = nblk*256 + t;
    float acc[64];
#pragma unroll
    for (int d2 = 0; d2 < 64; d2++) acc[d2] = 0.f;
#pragma unroll 4
    for (int e0 = 0; e0 < 64; e0 += 4) {
        int ce = h*16 + (e0 >> 2);
        size_t cb = ((size_t)(b*64 + ce))*HWv;
        float v0 = g_vs[cb + n];
        float v1 = g_vs[cb + HWP_ + n];
        float v2 = g_vs[cb + 2*HWP_ + n];
        float v3 = g_vs[cb + 3*HWP_ + n];
#pragma unroll
        for (int d2 = 0; d2 < 64; d2++) {
            float4 a = *(const float4*)&As[d2*64 + e0];
            acc[d2] += a.x*v0 + a.y*v1 + a.z*v2 + a.w*v3;
        }
    }
#pragma unroll 1
    for (int d2 = 0; d2 < 64; d2++) {
        int cd = h*16 + (d2>>2), fd = d2 & 3;
        g_out1[((size_t)(b*64 + cd))*HWv + (size_t)fd*HWP_ + n] = acc[d2];
    }
}

// av var=1 fused with product + scatter into original-hw domain
__global__ void av1_kernel() {
    __shared__ float As[4096];
    int t = threadIdx.x;
    int bid = blockIdx.x;                 // 512: (b,h,nblk)
    int nblk = bid & 63;
    int h = (bid>>6)&3, b = (bid>>8)&1;
    int vbh = 8 | (b<<2) | h;
    for (int l = t; l < 4096; l += 256) As[l] = g_attn[(size_t)vbh*4096 + l];
    __syncthreads();
    int n = nblk*256 + t;
    float acc[64];
#pragma unroll
    for (int d2 = 0; d2 < 64; d2++) acc[d2] = 0.f;
#pragma unroll 4
    for (int e0 = 0; e0 < 64; e0 += 4) {
        int ce = h*16 + (e0 >> 2);
        size_t cb = ((size_t)(b*64 + ce))*HWv;
        float4 vv = *(const float4*)&g_vs[cb + 4*(size_t)n];
#pragma unroll
        for (int d2 = 0; d2 < 64; d2++) {
            float4 a = *(const float4*)&As[d2*64 + e0];
            acc[d2] += a.x*vv.x + a.y*vv.y + a.z*vv.z + a.w*vv.w;
        }
    }
    // product with out1 at same sorted positions, scatter via idx
#pragma unroll 1
    for (int cg = 0; cg < 16; cg++) {
        int cd = h*16 + cg;
        size_t rb = ((size_t)(b*64 + cd))*HWv;
        size_t pos = rb + 4*(size_t)n;
        float4 o1 = *(const float4*)&g_out1[pos];
        int4   j4 = *(const int4*)&g_idx[pos];
        g_prod[rb + j4.x] = acc[cg*4 + 0] * o1.x;
        g_prod[rb + j4.y] = acc[cg*4 + 1] * o1.y;
        g_prod[rb + j4.z] = acc[cg*4 + 2] * o1.z;
        g_prod[rb + j4.w] = acc[cg*4 + 3] * o1.w;
    }
}

// ---------------- fused unsort (both axes) ----------------
__global__ void unsort_kernel(float* __restrict__ out) {
    size_t gid = (size_t)blockIdx.x*256 + threadIdx.x;   // B*C*HW
    int b = (int)(gid / ((size_t)C_*HWv));
    size_t r0 = gid % ((size_t)C_*HWv);
    int c = (int)(r0 / HWv);
    int p = (int)(r0 % HWv);
    if (c < CH_) {
        int j = p & 255;
        size_t bc = (size_t)(b*CH_ + c);
        int r = g_invh[bc*HWv + p];
        int jw = g_invw[bc*HWv + (size_t)r*W_ + j];
        out[gid] = g_proj[((size_t)(b*C_ + c))*HWv + (size_t)r*W_ + jw];
    } else {
        out[gid] = g_proj[gid];
    }
}

// ---------------- launch ----------------
extern "C" void kernel_launch(void* const* d_in, const int* in_sizes, int n_in,
                              void* d_out, int out_size) {
    const float* x     = (const float*)d_in[0];
    const float* qkvw  = (const float*)d_in[1];
    const float* dww   = (const float*)d_in[2];
    const float* projw = (const float*)d_in[3];
    const float* temp  = (const float*)d_in[4];
    float* out = (float*)d_out;

    float *p_xcat, *p_qkvpre, *p_prod;
    unsigned long long *p_sA, *p_sB;
    cudaGetSymbolAddress((void**)&p_xcat,   g_xcat);
    cudaGetSymbolAddress((void**)&p_qkvpre, g_qkv_pre);
    cudaGetSymbolAddress((void**)&p_prod,   g_prod);
    cudaGetSymbolAddress((void**)&p_sA,     g_sortA);
    cudaGetSymbolAddress((void**)&p_sB,     g_sortB);
    float* p_proj;
    cudaGetSymbolAddress((void**)&p_proj,   g_proj);

    const int NBC  = (B_*C_*HWv) / 256;     // 32768

    // stage A: small sorts (+ inverse perms fused)
    sort_h_kernel<<<B_*CH_*W_, 256>>>(x);
    sort_w_kernel<<<B_*CH_*H_, 256>>>();
    copy_rest_kernel<<<(B_*CH_*HWv/4)/256, 256>>>(x);

    // stage B: convs (dwconv also emits sort keys for v channels)
    conv1x1_kernel<<<dim3(HWv/128, QKVC/64, B_), 256>>>(p_xcat, qkvw, p_qkvpre, QKVC);
    dwconv_kernel<<<(B_*QKVC*HWv/4)/256, 256>>>(p_qkvpre, dww);

    // stage C: big stable argsort of v rows (multi-block radix, 4 passes)
    {
        const int NB = R_ROWS * R_NSEG;   // 2048
        unsigned long long* bufs[2] = { p_sA, p_sB };
        int shifts[4] = { 32, 40, 48, 56 };
        for (int p2 = 0; p2 < 4; p2++) {
            unsigned long long* s = bufs[p2 & 1];
            unsigned long long* d = bufs[(p2 & 1) ^ 1];
            rhist_kernel   <<<NB, R_THREADS>>>(s, shifts[p2]);
            rscan_kernel   <<<R_ROWS, 256>>>();
            rscatter_kernel<<<NB, R_THREADS>>>(s, d, shifts[p2]);
        }
    }
    extract_gather_kernel<<<NBC, 256>>>();

    // stage D: attention (both variants)
    norm_kernel<<<2048, 128>>>();
    qk_kernel<<<dim3(32, 16), 256>>>();
    softmax_kernel<<<16*64, 64>>>(temp);
    av0_kernel<<<512, 256>>>();
    av1_kernel<<<512, 256>>>();

    // stage E: epilogue
    conv1x1_kernel<<<dim3(HWv/128, 1, B_), 256>>>(p_prod, projw, p_proj, C_);
    unsort_kernel<<<NBC, 256>>>(out);
}

// round 7
// speedup vs baseline: 1.3451x; 1.0772x over previous
#include <cuda_runtime.h>
#include <math.h>

// ---------------- constants ----------------
#define B_   2
#define C_   64
#define CH_  32
#define H_   256
#define W_   256
#define HWv  65536
#define QKVC 320
#define NH_  4
#define HWP_ 16384

// radix sort config
#define R_ROWS 128
#define R_N    65536
#define R_SEG  4096
#define R_NSEG 16
#define R_THREADS 512
#define R_EPT  8

// conv1x1 tiling
#define CV_PX 256
#define CV_SMEM (64*CV_PX*4 + 64*64*4)   // 81920 bytes

// ---------------- scratch (static device memory; no allocs) ----------------
__device__ float g_xcat[B_*C_*HWv];              // sorted ch<32 + copied ch>=32
__device__ int   g_invh[B_*CH_*HWv];
__device__ int   g_invw[B_*CH_*HWv];
__device__ float g_qkv_pre[B_*QKVC*HWv];         // conv1x1 output
__device__ float g_qkv[B_*QKVC*HWv];             // after dwconv (q1,k1,q2,k2; v -> keys)
__device__ unsigned long long g_sortA[B_*C_*HWv];
__device__ unsigned long long g_sortB[B_*C_*HWv];
__device__ unsigned g_rhist[R_ROWS*256*R_NSEG];  // 2MB
__device__ int   g_idx[B_*C_*HWv];               // big sort permutation
__device__ float g_vs [B_*C_*HWv];               // sorted v values
__device__ float g_gq1[B_*C_*HWv];
__device__ float g_gk1[B_*C_*HWv];
__device__ float g_gq2[B_*C_*HWv];
__device__ float g_gk2[B_*C_*HWv];
__device__ float g_norm[2048];                    // [var][qk][b][h][d] packed
__device__ float g_Spart[16*32*4096];
__device__ float g_attn[16*4096];
__device__ float g_out1[B_*C_*HWv];
__device__ float g_prod[B_*C_*HWv];
__device__ float g_proj[B_*C_*HWv];

// ---------------- small stable bitonic sort (256 elems) ----------------
__device__ __forceinline__ bool pair_gt(float va, int ia, float vb, int ib) {
    return (va > vb) || (va == vb && ia > ib);
}

__device__ __forceinline__ void bitonic256(float* sv, int* si) {
    int t = threadIdx.x;
    for (int k = 2; k <= 256; k <<= 1) {
        for (int j = k >> 1; j > 0; j >>= 1) {
            int ixj = t ^ j;
            if (ixj > t) {
                bool up = ((t & k) == 0);
                float va = sv[t], vb = sv[ixj];
                int   ia = si[t], ib = si[ixj];
                bool sw = up ? pair_gt(va, ia, vb, ib) : pair_gt(vb, ib, va, ia);
                if (sw) { sv[t] = vb; si[t] = ib; sv[ixj] = va; si[ixj] = ia; }
            }
            __syncthreads();
        }
    }
}

// sort columns (axis H); write sorted vals + inverse permutation directly
__global__ void sort_h_kernel(const float* __restrict__ x) {
    __shared__ float sv[256];
    __shared__ int   si[256];
    int blk = blockIdx.x;                 // b*CH*W
    int b = blk / (CH_*W_);
    int c = (blk / W_) % CH_;
    int w = blk % W_;
    int t = threadIdx.x;
    const float* xp = x + ((size_t)(b*C_ + c))*HWv + w;
    sv[t] = xp[(size_t)t * W_];
    si[t] = t;
    __syncthreads();
    bitonic256(sv, si);
    g_xcat[((size_t)(b*C_ + c))*HWv + (size_t)t*W_ + w] = sv[t];
    g_invh[((size_t)(b*CH_ + c))*HWv + (size_t)si[t]*W_ + w] = t;
}

// sort rows (axis W) of g_xcat in place; inverse perm directly
__global__ void sort_w_kernel() {
    __shared__ float sv[256];
    __shared__ int   si[256];
    int blk = blockIdx.x;                 // b*CH*H
    int b = blk / (CH_*H_);
    int c = (blk / H_) % CH_;
    int h = blk % H_;
    int t = threadIdx.x;
    float* base = g_xcat + ((size_t)(b*C_ + c))*HWv + (size_t)h*W_;
    sv[t] = base[t];
    si[t] = t;
    __syncthreads();
    bitonic256(sv, si);
    base[t] = sv[t];
    g_invw[((size_t)(b*CH_ + c))*HWv + (size_t)h*W_ + si[t]] = t;
}

__global__ void copy_rest_kernel(const float* __restrict__ x) {
    size_t gid = (size_t)blockIdx.x*256 + threadIdx.x;   // B*32*HW/4
    int b = (int)(gid / ((size_t)CH_*HWv/4));
    size_t r = gid % ((size_t)CH_*HWv/4);
    int c = CH_ + (int)(r / (HWv/4));
    int p = (int)(r % (HWv/4)) * 4;
    size_t off = ((size_t)(b*C_ + c))*HWv + p;
    *(float4*)&g_xcat[off] = *(const float4*)&x[off];
}

// ---------------- conv1x1 (IC=64; tile 256px x 64oc; 8x8 microtile) ----------------
__global__ void __launch_bounds__(256)
conv1x1_kernel(const float* __restrict__ in, const float* __restrict__ w,
               float* __restrict__ out, int OC) {
    extern __shared__ float sm[];
    float* Xs = sm;                 // [64][256]
    float* Ws = sm + 64*CV_PX;      // [64][64]
    int p0  = blockIdx.x * CV_PX;
    int oc0 = blockIdx.y * 64;
    int b   = blockIdx.z;
    int t   = threadIdx.x;
#pragma unroll
    for (int r = 0; r < 16; r++) {
        int l = r*256 + t; int ic = l >> 6; int grp = l & 63;
        *(float4*)&Xs[ic*CV_PX + grp*4] =
            *(const float4*)&in[((size_t)(b*64 + ic))*HWv + p0 + grp*4];
    }
#pragma unroll
    for (int r = 0; r < 16; r++) {
        int l = r*256 + t; int oc = l >> 6; int ic = l & 63;
        Ws[ic*64 + oc] = w[(size_t)(oc0 + oc)*64 + ic];
    }
    __syncthreads();
    int tx = t & 31, ty = t >> 5;       // px group (32), oc group (8)
    float acc[8][8];
#pragma unroll
    for (int i = 0; i < 8; i++)
#pragma unroll
        for (int j = 0; j < 8; j++) acc[i][j] = 0.f;
#pragma unroll
    for (int ic = 0; ic < 64; ic++) {
        float4 xa = *(const float4*)&Xs[ic*CV_PX + tx*4];
        float4 xb = *(const float4*)&Xs[ic*CV_PX + 128 + tx*4];
        float4 wa = *(const float4*)&Ws[ic*64 + ty*8];
        float4 wb = *(const float4*)&Ws[ic*64 + ty*8 + 4];
        float xv[8] = {xa.x,xa.y,xa.z,xa.w,xb.x,xb.y,xb.z,xb.w};
        float wv[8] = {wa.x,wa.y,wa.z,wa.w,wb.x,wb.y,wb.z,wb.w};
#pragma unroll
        for (int i = 0; i < 8; i++)
#pragma unroll
            for (int j = 0; j < 8; j++) acc[i][j] += wv[i]*xv[j];
    }
#pragma unroll
    for (int i = 0; i < 8; i++) {
        size_t ob = ((size_t)(b*OC + oc0 + ty*8 + i))*HWv + p0;
        *(float4*)&out[ob + tx*4]       = make_float4(acc[i][0],acc[i][1],acc[i][2],acc[i][3]);
        *(float4*)&out[ob + 128 + tx*4] = make_float4(acc[i][4],acc[i][5],acc[i][6],acc[i][7]);
    }
}

// ---------------- depthwise 3x3 SAME (4 px/thread) + key build for v ----------------
__global__ void dwconv_kernel(const float* __restrict__ in, const float* __restrict__ wd) {
    size_t gid = (size_t)blockIdx.x*256 + threadIdx.x;   // B*QKVC*HW/4
    int p4 = (int)((gid % (HWv/4)) * 4);
    size_t bc = gid / (HWv/4);
    int ch = (int)(bc % QKVC);
    int b  = (int)(bc / QKVC);
    int h = p4 >> 8, w0 = p4 & 255;
    const float* ip = in + bc*HWv;
    float wreg[9];
#pragma unroll
    for (int i = 0; i < 9; i++) wreg[i] = __ldg(&wd[(size_t)ch*9 + i]);
    float o[4] = {0.f,0.f,0.f,0.f};
#pragma unroll
    for (int dy = -1; dy <= 1; dy++) {
        int hh = h + dy;
        if (hh < 0 || hh >= H_) continue;
        const float* rp = ip + (size_t)hh*W_;
        float a[6];
#pragma unroll
        for (int k2 = 0; k2 < 6; k2++) {
            int ww = w0 - 1 + k2;
            a[k2] = (ww >= 0 && ww < W_) ? rp[ww] : 0.f;
        }
        float wl = wreg[(dy+1)*3], wm = wreg[(dy+1)*3+1], wr = wreg[(dy+1)*3+2];
#pragma unroll
        for (int k2 = 0; k2 < 4; k2++)
            o[k2] += a[k2]*wl + a[k2+1]*wm + a[k2+2]*wr;
    }
    if (ch < 256) {
        *(float4*)&g_qkv[bc*HWv + p4] = make_float4(o[0],o[1],o[2],o[3]);
    } else {
        int row = b*64 + (ch - 256);
        unsigned long long* kp = &g_sortA[(size_t)row*HWv + p4];
#pragma unroll
        for (int k2 = 0; k2 < 4; k2++) {
            unsigned u = __float_as_uint(o[k2]);
            u ^= (u & 0x80000000u) ? 0xFFFFFFFFu : 0x80000000u;
            kp[k2] = ((unsigned long long)u << 32) | (unsigned)(p4 + k2);
        }
    }
}

// ---------------- multi-block stable radix sort (8-bit digit) ----------------
__global__ void rhist_kernel(const unsigned long long* __restrict__ src, int shift) {
    __shared__ unsigned h[256];
    int row = blockIdx.x >> 4, seg = blockIdx.x & 15;
    int tid = threadIdx.x;
    if (tid < 256) h[tid] = 0;
    __syncthreads();
    const unsigned long long* s = src + (size_t)row*R_N + (size_t)seg*R_SEG;
#pragma unroll
    for (int r = 0; r < R_EPT; r++) {
        unsigned dg = (unsigned)(s[r*R_THREADS + tid] >> shift) & 255u;
        atomicAdd(&h[dg], 1u);
    }
    __syncthreads();
    if (tid < 256)
        g_rhist[((size_t)row*256 + tid)*R_NSEG + seg] = h[tid];
}

__global__ void rscan_kernel() {
    int row = blockIdx.x, dg = threadIdx.x;   // 256 threads
    unsigned* hp = g_rhist + ((size_t)row*256 + dg)*R_NSEG;
    unsigned v[R_NSEG]; unsigned tot = 0;
#pragma unroll
    for (int s2 = 0; s2 < R_NSEG; s2++) { unsigned t = hp[s2]; v[s2] = tot; tot += t; }
    unsigned lane = dg & 31, w = dg >> 5;
    unsigned x = tot;
#pragma unroll
    for (int o = 1; o < 32; o <<= 1) { unsigned y = __shfl_up_sync(0xffffffffu, x, o); if (lane >= o) x += y; }
    __shared__ unsigned wsum[8];
    if (lane == 31) wsum[w] = x;
    __syncthreads();
    if (dg == 0) { unsigned run = 0; for (int i = 0; i < 8; i++) { unsigned t = wsum[i]; wsum[i] = run; run += t; } }
    __syncthreads();
    unsigned base0 = (x - tot) + wsum[w];
#pragma unroll
    for (int s2 = 0; s2 < R_NSEG; s2++) hp[s2] = base0 + v[s2];
}

__global__ void __launch_bounds__(R_THREADS)
rscatter_kernel(const unsigned long long* __restrict__ src,
                unsigned long long* __restrict__ dst, int shift) {
    __shared__ unsigned base[256];
    __shared__ unsigned bb0[256];
    __shared__ unsigned delta[256];
    __shared__ unsigned scanbuf[8];
    __shared__ unsigned long long stage[R_SEG];   // 32KB; rounds reuse it as wcnt/woff
    unsigned short* wcnt = (unsigned short*)stage;              // 16*256 u16 = 8KB
    unsigned*       woff = (unsigned*)(stage + 1024);           // 16*256 u32 = 16KB

    int row = blockIdx.x >> 4, seg = blockIdx.x & 15;
    int tid = threadIdx.x, w = tid >> 5, lane = tid & 31;
    const unsigned long long* s = src + (size_t)row*R_N + (size_t)seg*R_SEG;

    unsigned long long kv[R_EPT];
    unsigned posG[R_EPT];
#pragma unroll
    for (int r = 0; r < R_EPT; r++) kv[r] = s[r*R_THREADS + tid];

    if (tid < 256) {
        unsigned bv = g_rhist[((size_t)row*256 + tid)*R_NSEG + seg];
        base[tid] = bv; bb0[tid] = bv;
    }

    unsigned* wc32 = (unsigned*)wcnt;
#pragma unroll
    for (int r = 0; r < R_EPT; r++) {
        wc32[tid] = 0; wc32[tid + 512] = 0; wc32[tid + 1024] = 0; wc32[tid + 1536] = 0;
        unsigned dg = (unsigned)(kv[r] >> shift) & 255u;
        unsigned mask = __match_any_sync(0xffffffffu, dg);
        unsigned lr = __popc(mask & ((1u << lane) - 1u));
        unsigned cnt = __popc(mask);
        __syncthreads();
        if (lr == 0) wcnt[w*256 + dg] = (unsigned short)cnt;
        __syncthreads();
        if (tid < 256) {
            unsigned run = base[tid];
#pragma unroll
            for (int ww = 0; ww < 16; ww++) {
                unsigned c2 = wcnt[ww*256 + tid];
                woff[ww*256 + tid] = run;
                run += c2;
            }
            base[tid] = run;
        }
        __syncthreads();
        posG[r] = woff[w*256 + dg] + lr;
    }
    __syncthreads();

    if (tid < 256) {
        unsigned c = base[tid] - bb0[tid];
        unsigned x = c;
#pragma unroll
        for (int o = 1; o < 32; o <<= 1) { unsigned y = __shfl_up_sync(0xffffffffu, x, o); if (lane >= o) x += y; }
        woff[tid] = x - c;
        if (lane == 31) scanbuf[w] = x;
    }
    __syncthreads();
    if (tid == 0) { unsigned run = 0; for (int i = 0; i < 8; i++) { unsigned t2 = scanbuf[i]; scanbuf[i] = run; run += t2; } }
    __syncthreads();
    if (tid < 256) delta[tid] = bb0[tid] - (woff[tid] + scanbuf[tid >> 5]);
    __syncthreads();

#pragma unroll
    for (int r = 0; r < R_EPT; r++) {
        unsigned dg = (unsigned)(kv[r] >> shift) & 255u;
        stage[posG[r] - delta[dg]] = kv[r];
    }
    __syncthreads();
    unsigned long long* d = dst + (size_t)row*R_N;
#pragma unroll
    for (int r = 0; r < R_EPT; r++) {
        unsigned i = r*R_THREADS + tid;
        unsigned long long k2 = stage[i];
        unsigned dg = (unsigned)(k2 >> shift) & 255u;
        d[delta[dg] + i] = k2;
    }
}

// ---------------- fused extract + gather ----------------
__global__ void extract_gather_kernel() {
    size_t gid = (size_t)blockIdx.x*256 + threadIdx.x;
    int row = (int)(gid / HWv);
    int b = row >> 6, c = row & 63;
    unsigned long long kv = g_sortA[gid];
    int j = (int)(kv & 0xFFFFFFFFu);
    g_idx[gid] = j;
    unsigned u = (unsigned)(kv >> 32);
    u = (u & 0x80000000u) ? (u ^ 0x80000000u) : ~u;
    g_vs[gid] = __uint_as_float(u);
    size_t srcb = ((size_t)(b*QKVC) + c)*HWv;
    g_gq1[gid] = g_qkv[srcb + j];
    g_gk1[gid] = g_qkv[srcb + (size_t)64*HWv + j];
    g_gq2[gid] = g_qkv[srcb + (size_t)128*HWv + j];
    g_gk2[gid] = g_qkv[srcb + (size_t)192*HWv + j];
}

// ---------------- attention ----------------
__global__ void norm_kernel() {
    int id = blockIdx.x;
    int d = id & 63, h = (id>>6)&3, b = (id>>8)&1, qk = (id>>9)&1, var = (id>>10)&1;
    const float* src = var ? (qk ? g_gk2 : g_gq2) : (qk ? g_gk1 : g_gq1);
    int c = h*16 + (d>>2), f = d & 3;
    size_t base = ((size_t)(b*64 + c))*HWv + (var ? (size_t)f : (size_t)f*HWP_);
    int stride = var ? 4 : 1;
    float s = 0.f;
    for (int i = threadIdx.x; i < HWP_; i += 128) {
        float v = src[base + (size_t)i*stride];
        s += v * v;
    }
    __shared__ float red[128];
    red[threadIdx.x] = s;
    __syncthreads();
    for (int o = 64; o > 0; o >>= 1) {
        if (threadIdx.x < o) red[threadIdx.x] += red[threadIdx.x + o];
        __syncthreads();
    }
    if (threadIdx.x == 0) g_norm[id] = 1.0f / fmaxf(sqrtf(red[0]), 1e-12f);
}

__global__ void qk_kernel() {
    __shared__ float Qs[64][65];
    __shared__ float Ks[64][65];
    int t = threadIdx.x;
    int vbh = blockIdx.y;
    int var = vbh >> 3, b = (vbh>>2)&1, h = vbh & 3;
    const float* qsrc = var ? g_gq2 : g_gq1;
    const float* ksrc = var ? g_gk2 : g_gk1;
    int ty = t >> 4, tx = t & 15;
    float acc[4][4];
#pragma unroll
    for (int i = 0; i < 4; i++)
#pragma unroll
        for (int j = 0; j < 4; j++) acc[i][j] = 0.f;
    int n0 = blockIdx.x * 512;
    for (int tile = 0; tile < 8; tile++) {
        int nb = n0 + tile*64;
#pragma unroll
        for (int rr = 0; rr < 16; rr++) {
            int l = rr*256 + t; int d = l >> 6; int nn = l & 63;
            int c = h*16 + (d>>2), f = d & 3;
            size_t addr = ((size_t)(b*64 + c))*HWv +
                          (var ? (size_t)4*(nb+nn) + f : (size_t)f*HWP_ + nb + nn);
            Qs[d][nn] = qsrc[addr];
            Ks[d][nn] = ksrc[addr];
        }
        __syncthreads();
#pragma unroll 8
        for (int nn = 0; nn < 64; nn++) {
            float qa[4], ka[4];
#pragma unroll
            for (int i = 0; i < 4; i++) { qa[i] = Qs[ty*4+i][nn]; ka[i] = Ks[tx*4+i][nn]; }
#pragma unroll
            for (int i = 0; i < 4; i++)
#pragma unroll
                for (int j = 0; j < 4; j++) acc[i][j] += qa[i]*ka[j];
        }
        __syncthreads();
    }
    float* sp = g_Spart + ((size_t)(vbh*32 + blockIdx.x))*4096;
#pragma unroll
    for (int i = 0; i < 4; i++)
#pragma unroll
        for (int j = 0; j < 4; j++)
            sp[(ty*4+i)*64 + tx*4 + j] = acc[i][j];
}

__global__ void softmax_kernel(const float* __restrict__ temp) {
    int blk = blockIdx.x;
    int vbh = blk >> 6, d = blk & 63;
    int var = vbh >> 3, b = (vbh>>2)&1, h = vbh & 3;
    int e = threadIdx.x;   // 64
    float sk = g_norm[(var<<10) | (1<<9) | (b<<8) | (h<<6) | e];
    float invq = g_norm[(var<<10) | (b<<8) | (h<<6) | d];
    float T = temp[h];
    const float* sp = g_Spart + (size_t)vbh*32*4096 + d*64 + e;
    float s = 0.f;
#pragma unroll
    for (int sl = 0; sl < 32; sl++) s += sp[(size_t)sl*4096];
    float ex = expf(s * invq * sk * T);
    __shared__ float red[64];
    red[e] = ex;
    __syncthreads();
    if (e < 32) {
        float p = red[e] + red[e + 32];
#pragma unroll
        for (int o = 16; o > 0; o >>= 1) p += __shfl_down_sync(0xffffffffu, p, o);
        if (e == 0) red[0] = p;
    }
    __syncthreads();
    float r = 1.0f / (red[0] + 1.0f);
    g_attn[(size_t)vbh*4096 + d*64 + e] = ex * r;
}

// av var=0: writes g_out1
__global__ void av0_kernel() {
    __shared__ float As[4096];
    int t = threadIdx.x;
    int bid = blockIdx.x;                 // 512: (b,h,nblk)
    int nblk = bid & 63;
    int h = (bid>>6)&3, b = (bid>>8)&1;
    int vbh = (b<<2) | h;
    for (int l = t; l < 4096; l += 256) As[l] = g_attn[(size_t)vbh*4096 + l];
    __syncthreads();
    int n = nblk*256 + t;
    float acc[64];
#pragma unroll
    for (int d2 = 0; d2 < 64; d2++) acc[d2] = 0.f;
#pragma unroll 4
    for (int e0 = 0; e0 < 64; e0 += 4) {
        int ce = h*16 + (e0 >> 2);
        size_t cb = ((size_t)(b*64 + ce))*HWv;
        float v0 = g_vs[cb + n];
        float v1 = g_vs[cb + HWP_ + n];
        float v2 = g_vs[cb + 2*HWP_ + n];
        float v3 = g_vs[cb + 3*HWP_ + n];
#pragma unroll
        for (int d2 = 0; d2 < 64; d2++) {
            float4 a = *(const float4*)&As[d2*64 + e0];
            acc[d2] += a.x*v0 + a.y*v1 + a.z*v2 + a.w*v3;
        }
    }
#pragma unroll 1
    for (int d2 = 0; d2 < 64; d2++) {
        int cd = h*16 + (d2>>2), fd = d2 & 3;
        g_out1[((size_t)(b*64 + cd))*HWv + (size_t)fd*HWP_ + n] = acc[d2];
    }
}

// av var=1 fused with product + scatter into original-hw domain
__global__ void av1_kernel() {
    __shared__ float As[4096];
    int t = threadIdx.x;
    int bid = blockIdx.x;                 // 512: (b,h,nblk)
    int nblk = bid & 63;
    int h = (bid>>6)&3, b = (bid>>8)&1;
    int vbh = 8 | (b<<2) | h;
    for (int l = t; l < 4096; l += 256) As[l] = g_attn[(size_t)vbh*4096 + l];
    __syncthreads();
    int n = nblk*256 + t;
    float acc[64];
#pragma unroll
    for (int d2 = 0; d2 < 64; d2++) acc[d2] = 0.f;
#pragma unroll 4
    for (int e0 = 0; e0 < 64; e0 += 4) {
        int ce = h*16 + (e0 >> 2);
        size_t cb = ((size_t)(b*64 + ce))*HWv;
        float4 vv = *(const float4*)&g_vs[cb + 4*(size_t)n];
#pragma unroll
        for (int d2 = 0; d2 < 64; d2++) {
            float4 a = *(const float4*)&As[d2*64 + e0];
            acc[d2] += a.x*vv.x + a.y*vv.y + a.z*vv.z + a.w*vv.w;
        }
    }
    // product with out1 at same sorted positions, scatter via idx
#pragma unroll 1
    for (int cg = 0; cg < 16; cg++) {
        int cd = h*16 + cg;
        size_t rb = ((size_t)(b*64 + cd))*HWv;
        size_t pos = rb + 4*(size_t)n;
        float4 o1 = *(const float4*)&g_out1[pos];
        int4   j4 = *(const int4*)&g_idx[pos];
        g_prod[rb + j4.x] = acc[cg*4 + 0] * o1.x;
        g_prod[rb + j4.y] = acc[cg*4 + 1] * o1.y;
        g_prod[rb + j4.z] = acc[cg*4 + 2] * o1.z;
        g_prod[rb + j4.w] = acc[cg*4 + 3] * o1.w;
    }
}

// ---------------- fused unsort (both axes) ----------------
__global__ void unsort_kernel(float* __restrict__ out) {
    size_t gid = (size_t)blockIdx.x*256 + threadIdx.x;   // B*C*HW
    int b = (int)(gid / ((size_t)C_*HWv));
    size_t r0 = gid % ((size_t)C_*HWv);
    int c = (int)(r0 / HWv);
    int p = (int)(r0 % HWv);
    if (c < CH_) {
        int j = p & 255;
        size_t bc = (size_t)(b*CH_ + c);
        int r = g_invh[bc*HWv + p];
        int jw = g_invw[bc*HWv + (size_t)r*W_ + j];
        out[gid] = g_proj[((size_t)(b*C_ + c))*HWv + (size_t)r*W_ + jw];
    } else {
        out[gid] = g_proj[gid];
    }
}

// ---------------- launch ----------------
extern "C" void kernel_launch(void* const* d_in, const int* in_sizes, int n_in,
                              void* d_out, int out_size) {
    const float* x     = (const float*)d_in[0];
    const float* qkvw  = (const float*)d_in[1];
    const float* dww   = (const float*)d_in[2];
    const float* projw = (const float*)d_in[3];
    const float* temp  = (const float*)d_in[4];
    float* out = (float*)d_out;

    cudaFuncSetAttribute((const void*)conv1x1_kernel,
                         cudaFuncAttributeMaxDynamicSharedMemorySize, CV_SMEM);

    float *p_xcat, *p_qkvpre, *p_prod;
    unsigned long long *p_sA, *p_sB;
    cudaGetSymbolAddress((void**)&p_xcat,   g_xcat);
    cudaGetSymbolAddress((void**)&p_qkvpre, g_qkv_pre);
    cudaGetSymbolAddress((void**)&p_prod,   g_prod);
    cudaGetSymbolAddress((void**)&p_sA,     g_sortA);
    cudaGetSymbolAddress((void**)&p_sB,     g_sortB);
    float* p_proj;
    cudaGetSymbolAddress((void**)&p_proj,   g_proj);

    const int NBC  = (B_*C_*HWv) / 256;     // 32768

    // stage A: small sorts (+ inverse perms fused)
    sort_h_kernel<<<B_*CH_*W_, 256>>>(x);
    sort_w_kernel<<<B_*CH_*H_, 256>>>();
    copy_rest_kernel<<<(B_*CH_*HWv/4)/256, 256>>>(x);

    // stage B: convs (dwconv also emits sort keys for v channels)
    conv1x1_kernel<<<dim3(HWv/CV_PX, QKVC/64, B_), 256, CV_SMEM>>>(p_xcat, qkvw, p_qkvpre, QKVC);
    dwconv_kernel<<<(B_*QKVC*HWv/4)/256, 256>>>(p_qkvpre, dww);

    // stage C: big stable argsort of v rows (multi-block radix, 4 passes)
    {
        const int NB = R_ROWS * R_NSEG;   // 2048
        unsigned long long* bufs[2] = { p_sA, p_sB };
        int shifts[4] = { 32, 40, 48, 56 };
        for (int p2 = 0; p2 < 4; p2++) {
            unsigned long long* s = bufs[p2 & 1];
            unsigned long long* d = bufs[(p2 & 1) ^ 1];
            rhist_kernel   <<<NB, R_THREADS>>>(s, shifts[p2]);
            rscan_kernel   <<<R_ROWS, 256>>>();
            rscatter_kernel<<<NB, R_THREADS>>>(s, d, shifts[p2]);
        }
    }
    extract_gather_kernel<<<NBC, 256>>>();

    // stage D: attention (both variants)
    norm_kernel<<<2048, 128>>>();
    qk_kernel<<<dim3(32, 16), 256>>>();
    softmax_kernel<<<16*64, 64>>>(temp);
    av0_kernel<<<512, 256>>>();
    av1_kernel<<<512, 256>>>();

    // stage E: epilogue
    conv1x1_kernel<<<dim3(HWv/CV_PX, 1, B_), 256, CV_SMEM>>>(p_prod, projw, p_proj, C_);
    unsort_kernel<<<NBC, 256>>>(out);
}

// round 8
// speedup vs baseline: 1.3957x; 1.0376x over previous
#include <cuda_runtime.h>
#include <math.h>

// ---------------- constants ----------------
#define B_   2
#define C_   64
#define CH_  32
#define H_   256
#define W_   256
#define HWv  65536
#define QKVC 320
#define NH_  4
#define HWP_ 16384

// radix sort config
#define R_ROWS 128
#define R_N    65536
#define R_SEG  4096
#define R_NSEG 16
#define R_THREADS 512
#define R_EPT  8

// conv1x1 tiling
#define CV_PX 256
#define CV_SMEM (64*CV_PX*4 + 64*64*4)   // 81920 bytes

// ---------------- scratch (static device memory; no allocs) ----------------
__device__ float g_xcat[B_*C_*HWv];
__device__ int   g_invh[B_*CH_*HWv];
__device__ int   g_invw[B_*CH_*HWv];
__device__ float g_qkv_pre[B_*QKVC*HWv];
__device__ float g_qkv[B_*QKVC*HWv];
__device__ unsigned long long g_sortA[B_*C_*HWv];
__device__ unsigned long long g_sortB[B_*C_*HWv];
__device__ unsigned g_rhist[R_ROWS*256*R_NSEG];
__device__ int   g_idx[B_*C_*HWv];
__device__ float g_vs [B_*C_*HWv];
__device__ float g_gq1[B_*C_*HWv];
__device__ float g_gk1[B_*C_*HWv];
__device__ float g_gq2[B_*C_*HWv];
__device__ float g_gk2[B_*C_*HWv];
__device__ float g_norm[2048];                 // final 1/max(sqrt(ss),1e-12)
__device__ float g_npart[2048*256];            // partial sums [bin][slot]
__device__ float g_Spart[16*32*4096];
__device__ float g_attn[16*4096];
__device__ float g_out1[B_*C_*HWv];
__device__ float g_prod[B_*C_*HWv];
__device__ float g_proj[B_*C_*HWv];

// ---------------- small stable bitonic sort (256 elems) ----------------
__device__ __forceinline__ bool pair_gt(float va, int ia, float vb, int ib) {
    return (va > vb) || (va == vb && ia > ib);
}

__device__ __forceinline__ void bitonic256(float* sv, int* si) {
    int t = threadIdx.x;
    for (int k = 2; k <= 256; k <<= 1) {
        for (int j = k >> 1; j > 0; j >>= 1) {
            int ixj = t ^ j;
            if (ixj > t) {
                bool up = ((t & k) == 0);
                float va = sv[t], vb = sv[ixj];
                int   ia = si[t], ib = si[ixj];
                bool sw = up ? pair_gt(va, ia, vb, ib) : pair_gt(vb, ib, va, ia);
                if (sw) { sv[t] = vb; si[t] = ib; sv[ixj] = va; si[ixj] = ia; }
            }
            __syncthreads();
        }
    }
}

__global__ void sort_h_kernel(const float* __restrict__ x) {
    __shared__ float sv[256];
    __shared__ int   si[256];
    int blk = blockIdx.x;
    int b = blk / (CH_*W_);
    int c = (blk / W_) % CH_;
    int w = blk % W_;
    int t = threadIdx.x;
    const float* xp = x + ((size_t)(b*C_ + c))*HWv + w;
    sv[t] = xp[(size_t)t * W_];
    si[t] = t;
    __syncthreads();
    bitonic256(sv, si);
    g_xcat[((size_t)(b*C_ + c))*HWv + (size_t)t*W_ + w] = sv[t];
    g_invh[((size_t)(b*CH_ + c))*HWv + (size_t)si[t]*W_ + w] = t;
}

__global__ void sort_w_kernel() {
    __shared__ float sv[256];
    __shared__ int   si[256];
    int blk = blockIdx.x;
    int b = blk / (CH_*H_);
    int c = (blk / H_) % CH_;
    int h = blk % H_;
    int t = threadIdx.x;
    float* base = g_xcat + ((size_t)(b*C_ + c))*HWv + (size_t)h*W_;
    sv[t] = base[t];
    si[t] = t;
    __syncthreads();
    bitonic256(sv, si);
    base[t] = sv[t];
    g_invw[((size_t)(b*CH_ + c))*HWv + (size_t)h*W_ + si[t]] = t;
}

__global__ void copy_rest_kernel(const float* __restrict__ x) {
    size_t gid = (size_t)blockIdx.x*256 + threadIdx.x;
    int b = (int)(gid / ((size_t)CH_*HWv/4));
    size_t r = gid % ((size_t)CH_*HWv/4);
    int c = CH_ + (int)(r / (HWv/4));
    int p = (int)(r % (HWv/4)) * 4;
    size_t off = ((size_t)(b*C_ + c))*HWv + p;
    *(float4*)&g_xcat[off] = *(const float4*)&x[off];
}

// ---------------- conv1x1 (IC=64; tile 256px x 64oc; 8x8 microtile) ----------------
__global__ void __launch_bounds__(256)
conv1x1_kernel(const float* __restrict__ in, const float* __restrict__ w,
               float* __restrict__ out, int OC) {
    extern __shared__ float sm[];
    float* Xs = sm;                 // [64][256]
    float* Ws = sm + 64*CV_PX;      // [64][64]
    int p0  = blockIdx.x * CV_PX;
    int oc0 = blockIdx.y * 64;
    int b   = blockIdx.z;
    int t   = threadIdx.x;
#pragma unroll
    for (int r = 0; r < 16; r++) {
        int l = r*256 + t; int ic = l >> 6; int grp = l & 63;
        *(float4*)&Xs[ic*CV_PX + grp*4] =
            *(const float4*)&in[((size_t)(b*64 + ic))*HWv + p0 + grp*4];
    }
#pragma unroll
    for (int r = 0; r < 16; r++) {
        int l = r*256 + t; int oc = l >> 6; int ic = l & 63;
        Ws[ic*64 + oc] = w[(size_t)(oc0 + oc)*64 + ic];
    }
    __syncthreads();
    int tx = t & 31, ty = t >> 5;
    float acc[8][8];
#pragma unroll
    for (int i = 0; i < 8; i++)
#pragma unroll
        for (int j = 0; j < 8; j++) acc[i][j] = 0.f;
#pragma unroll
    for (int ic = 0; ic < 64; ic++) {
        float4 xa = *(const float4*)&Xs[ic*CV_PX + tx*4];
        float4 xb = *(const float4*)&Xs[ic*CV_PX + 128 + tx*4];
        float4 wa = *(const float4*)&Ws[ic*64 + ty*8];
        float4 wb = *(const float4*)&Ws[ic*64 + ty*8 + 4];
        float xv[8] = {xa.x,xa.y,xa.z,xa.w,xb.x,xb.y,xb.z,xb.w};
        float wv[8] = {wa.x,wa.y,wa.z,wa.w,wb.x,wb.y,wb.z,wb.w};
#pragma unroll
        for (int i = 0; i < 8; i++)
#pragma unroll
            for (int j = 0; j < 8; j++) acc[i][j] += wv[i]*xv[j];
    }
#pragma unroll
    for (int i = 0; i < 8; i++) {
        size_t ob = ((size_t)(b*OC + oc0 + ty*8 + i))*HWv + p0;
        *(float4*)&out[ob + tx*4]       = make_float4(acc[i][0],acc[i][1],acc[i][2],acc[i][3]);
        *(float4*)&out[ob + 128 + tx*4] = make_float4(acc[i][4],acc[i][5],acc[i][6],acc[i][7]);
    }
}

// ---------------- depthwise 3x3 SAME, 2D smem tile (8 rows/block) ----------------
__global__ void __launch_bounds__(256)
dwconv_kernel(const float* __restrict__ in, const float* __restrict__ wd) {
    __shared__ float tile[10][W_];   // 10KB
    int bid = blockIdx.x;            // (b*QKVC+ch)*32 + hblk
    int hblk = bid & 31;
    int chbc = bid >> 5;
    int ch = chbc % QKVC;
    int b  = chbc / QKVC;
    int h0 = hblk * 8;
    int t = threadIdx.x;
    const float* ip = in + (size_t)chbc * HWv;
#pragma unroll
    for (int r = 0; r < 10; r++) {
        int hh = h0 - 1 + r;
        tile[r][t] = (hh >= 0 && hh < H_) ? ip[(size_t)hh*W_ + t] : 0.f;
    }
    float wreg[9];
#pragma unroll
    for (int i = 0; i < 9; i++) wreg[i] = __ldg(&wd[(size_t)ch*9 + i]);
    __syncthreads();

    float wl[10], wm[10], wr[10];
#pragma unroll
    for (int r = 0; r < 10; r++) {
        wm[r] = tile[r][t];
        wl[r] = (t > 0)   ? tile[r][t-1] : 0.f;
        wr[r] = (t < 255) ? tile[r][t+1] : 0.f;
    }

    if (ch < 256) {
        float* op = g_qkv + (size_t)chbc*HWv;
#pragma unroll
        for (int r = 0; r < 8; r++) {
            float s = wl[r  ]*wreg[0] + wm[r  ]*wreg[1] + wr[r  ]*wreg[2]
                    + wl[r+1]*wreg[3] + wm[r+1]*wreg[4] + wr[r+1]*wreg[5]
                    + wl[r+2]*wreg[6] + wm[r+2]*wreg[7] + wr[r+2]*wreg[8];
            op[(size_t)(h0 + r)*W_ + t] = s;
        }
    } else {
        int row = b*64 + (ch - 256);
        unsigned long long* kp = g_sortA + (size_t)row*HWv;
#pragma unroll
        for (int r = 0; r < 8; r++) {
            float s = wl[r  ]*wreg[0] + wm[r  ]*wreg[1] + wr[r  ]*wreg[2]
                    + wl[r+1]*wreg[3] + wm[r+1]*wreg[4] + wr[r+1]*wreg[5]
                    + wl[r+2]*wreg[6] + wm[r+2]*wreg[7] + wr[r+2]*wreg[8];
            unsigned u = __float_as_uint(s);
            u ^= (u & 0x80000000u) ? 0xFFFFFFFFu : 0x80000000u;
            int n = (h0 + r)*W_ + t;
            kp[n] = ((unsigned long long)u << 32) | (unsigned)n;
        }
    }
}

// ---------------- multi-block stable radix sort (8-bit digit) ----------------
__global__ void rhist_kernel(const unsigned long long* __restrict__ src, int shift) {
    __shared__ unsigned h[256];
    int row = blockIdx.x >> 4, seg = blockIdx.x & 15;
    int tid = threadIdx.x;
    if (tid < 256) h[tid] = 0;
    __syncthreads();
    const unsigned long long* s = src + (size_t)row*R_N + (size_t)seg*R_SEG;
#pragma unroll
    for (int r = 0; r < R_EPT; r++) {
        unsigned dg = (unsigned)(s[r*R_THREADS + tid] >> shift) & 255u;
        atomicAdd(&h[dg], 1u);
    }
    __syncthreads();
    if (tid < 256)
        g_rhist[((size_t)row*256 + tid)*R_NSEG + seg] = h[tid];
}

__global__ void rscan_kernel() {
    int row = blockIdx.x, dg = threadIdx.x;
    unsigned* hp = g_rhist + ((size_t)row*256 + dg)*R_NSEG;
    unsigned v[R_NSEG]; unsigned tot = 0;
#pragma unroll
    for (int s2 = 0; s2 < R_NSEG; s2++) { unsigned t = hp[s2]; v[s2] = tot; tot += t; }
    unsigned lane = dg & 31, w = dg >> 5;
    unsigned x = tot;
#pragma unroll
    for (int o = 1; o < 32; o <<= 1) { unsigned y = __shfl_up_sync(0xffffffffu, x, o); if (lane >= o) x += y; }
    __shared__ unsigned wsum[8];
    if (lane == 31) wsum[w] = x;
    __syncthreads();
    if (dg == 0) { unsigned run = 0; for (int i = 0; i < 8; i++) { unsigned t = wsum[i]; wsum[i] = run; run += t; } }
    __syncthreads();
    unsigned base0 = (x - tot) + wsum[w];
#pragma unroll
    for (int s2 = 0; s2 < R_NSEG; s2++) hp[s2] = base0 + v[s2];
}

__global__ void __launch_bounds__(R_THREADS)
rscatter_kernel(const unsigned long long* __restrict__ src,
                unsigned long long* __restrict__ dst, int shift) {
    __shared__ unsigned base[256];
    __shared__ unsigned bb0[256];
    __shared__ unsigned delta[256];
    __shared__ unsigned scanbuf[8];
    __shared__ unsigned long long stage[R_SEG];
    unsigned short* wcnt = (unsigned short*)stage;
    unsigned*       woff = (unsigned*)(stage + 1024);

    int row = blockIdx.x >> 4, seg = blockIdx.x & 15;
    int tid = threadIdx.x, w = tid >> 5, lane = tid & 31;
    const unsigned long long* s = src + (size_t)row*R_N + (size_t)seg*R_SEG;

    unsigned long long kv[R_EPT];
    unsigned posG[R_EPT];
#pragma unroll
    for (int r = 0; r < R_EPT; r++) kv[r] = s[r*R_THREADS + tid];

    if (tid < 256) {
        unsigned bv = g_rhist[((size_t)row*256 + tid)*R_NSEG + seg];
        base[tid] = bv; bb0[tid] = bv;
    }

    unsigned* wc32 = (unsigned*)wcnt;
#pragma unroll
    for (int r = 0; r < R_EPT; r++) {
        wc32[tid] = 0; wc32[tid + 512] = 0; wc32[tid + 1024] = 0; wc32[tid + 1536] = 0;
        unsigned dg = (unsigned)(kv[r] >> shift) & 255u;
        unsigned mask = __match_any_sync(0xffffffffu, dg);
        unsigned lr = __popc(mask & ((1u << lane) - 1u));
        unsigned cnt = __popc(mask);
        __syncthreads();
        if (lr == 0) wcnt[w*256 + dg] = (unsigned short)cnt;
        __syncthreads();
        if (tid < 256) {
            unsigned run = base[tid];
#pragma unroll
            for (int ww = 0; ww < 16; ww++) {
                unsigned c2 = wcnt[ww*256 + tid];
                woff[ww*256 + tid] = run;
                run += c2;
            }
            base[tid] = run;
        }
        __syncthreads();
        posG[r] = woff[w*256 + dg] + lr;
    }
    __syncthreads();

    if (tid < 256) {
        unsigned c = base[tid] - bb0[tid];
        unsigned x = c;
#pragma unroll
        for (int o = 1; o < 32; o <<= 1) { unsigned y = __shfl_up_sync(0xffffffffu, x, o); if (lane >= o) x += y; }
        woff[tid] = x - c;
        if (lane == 31) scanbuf[w] = x;
    }
    __syncthreads();
    if (tid == 0) { unsigned run = 0; for (int i = 0; i < 8; i++) { unsigned t2 = scanbuf[i]; scanbuf[i] = run; run += t2; } }
    __syncthreads();
    if (tid < 256) delta[tid] = bb0[tid] - (woff[tid] + scanbuf[tid >> 5]);
    __syncthreads();

#pragma unroll
    for (int r = 0; r < R_EPT; r++) {
        unsigned dg = (unsigned)(kv[r] >> shift) & 255u;
        stage[posG[r] - delta[dg]] = kv[r];
    }
    __syncthreads();
    unsigned long long* d = dst + (size_t)row*R_N;
#pragma unroll
    for (int r = 0; r < R_EPT; r++) {
        unsigned i = r*R_THREADS + tid;
        unsigned long long k2 = stage[i];
        unsigned dg = (unsigned)(k2 >> shift) & 255u;
        d[delta[dg] + i] = k2;
    }
}

// ---------------- fused extract + gather + norm partials ----------------
__device__ __forceinline__ float warp_sum(float x) {
#pragma unroll
    for (int o = 16; o > 0; o >>= 1) x += __shfl_down_sync(0xffffffffu, x, o);
    return x;
}

__global__ void extract_gather_kernel() {
    __shared__ float red1[8], red2[8], red3[8][4], red4[8][4];
    size_t gid = (size_t)blockIdx.x*256 + threadIdx.x;
    int row = (int)(gid / HWv);
    int b = row >> 6, c = row & 63;
    int t = threadIdx.x, lane = t & 31, w = t >> 5;
    unsigned long long kv = g_sortA[gid];
    int j = (int)(kv & 0xFFFFFFFFu);
    g_idx[gid] = j;
    unsigned u = (unsigned)(kv >> 32);
    u = (u & 0x80000000u) ? (u ^ 0x80000000u) : ~u;
    g_vs[gid] = __uint_as_float(u);
    size_t srcb = ((size_t)(b*QKVC) + c)*HWv;
    float q1 = g_qkv[srcb + j];
    float k1 = g_qkv[srcb + (size_t)64*HWv + j];
    float q2 = g_qkv[srcb + (size_t)128*HWv + j];
    float k2 = g_qkv[srcb + (size_t)192*HWv + j];
    g_gq1[gid] = q1;
    g_gk1[gid] = k1;
    g_gq2[gid] = q2;
    g_gk2[gid] = k2;

    // norm partials
    float s1 = warp_sum(q1*q1);
    float s2 = warp_sum(k1*k1);
    // var1: group by lane%4
    float s3 = q2*q2, s4 = k2*k2;
#pragma unroll
    for (int o = 16; o >= 4; o >>= 1) {
        s3 += __shfl_down_sync(0xffffffffu, s3, o);
        s4 += __shfl_down_sync(0xffffffffu, s4, o);
    }
    if (lane == 0) { red1[w] = s1; red2[w] = s2; }
    if (lane < 4)  { red3[w][lane] = s3; red4[w][lane] = s4; }
    __syncthreads();
    int n0 = (int)(gid & 0xFFFF) - t;         // block-start n
    int blk = n0 >> 8;                         // 0..255 within row
    int h = c >> 4, dbase = (c & 15) << 2;
    if (t == 0) {
        float a = 0, bb = 0;
#pragma unroll
        for (int i = 0; i < 8; i++) { a += red1[i]; bb += red2[i]; }
        int f = n0 >> 14;
        int d0 = dbase + f;
        int slot = blk - f*64;
        // var0 q bin: (0<<10)|(0<<9)|(b<<8)|(h<<6)|d0
        g_npart[(size_t)(((b<<8)|(h<<6)|d0))*256 + slot] = a;
        g_npart[(size_t)(((1<<9)|(b<<8)|(h<<6)|d0))*256 + slot] = bb;
    }
    if (t < 4) {
        float a = 0, bb = 0;
#pragma unroll
        for (int i = 0; i < 8; i++) { a += red3[i][t]; bb += red4[i][t]; }
        int d0 = dbase + t;
        g_npart[(size_t)(((1<<10)|(b<<8)|(h<<6)|d0))*256 + blk] = a;
        g_npart[(size_t)(((1<<10)|(1<<9)|(b<<8)|(h<<6)|d0))*256 + blk] = bb;
    }
}

// reduce partials -> g_norm
__global__ void reduce_norm_kernel() {
    int bin = blockIdx.x * 128 + threadIdx.x;   // 2048
    int var = (bin >> 10) & 1;
    int nslot = var ? 256 : 64;
    const float* p = g_npart + (size_t)bin*256;
    float s = 0.f;
    for (int i = 0; i < nslot; i++) s += p[i];
    g_norm[bin] = 1.0f / fmaxf(sqrtf(s), 1e-12f);
}

// ---------------- attention ----------------
__global__ void qk_kernel() {
    __shared__ float Qs[64][65];
    __shared__ float Ks[64][65];
    int t = threadIdx.x;
    int vbh = blockIdx.y;
    int var = vbh >> 3, b = (vbh>>2)&1, h = vbh & 3;
    const float* qsrc = var ? g_gq2 : g_gq1;
    const float* ksrc = var ? g_gk2 : g_gk1;
    int ty = t >> 4, tx = t & 15;
    float acc[4][4];
#pragma unroll
    for (int i = 0; i < 4; i++)
#pragma unroll
        for (int j = 0; j < 4; j++) acc[i][j] = 0.f;
    int n0 = blockIdx.x * 512;
    for (int tile = 0; tile < 8; tile++) {
        int nb = n0 + tile*64;
#pragma unroll
        for (int rr = 0; rr < 16; rr++) {
            int l = rr*256 + t; int d = l >> 6; int nn = l & 63;
            int c = h*16 + (d>>2), f = d & 3;
            size_t addr = ((size_t)(b*64 + c))*HWv +
                          (var ? (size_t)4*(nb+nn) + f : (size_t)f*HWP_ + nb + nn);
            Qs[d][nn] = qsrc[addr];
            Ks[d][nn] = ksrc[addr];
        }
        __syncthreads();
#pragma unroll 8
        for (int nn = 0; nn < 64; nn++) {
            float qa[4], ka[4];
#pragma unroll
            for (int i = 0; i < 4; i++) { qa[i] = Qs[ty*4+i][nn]; ka[i] = Ks[tx*4+i][nn]; }
#pragma unroll
            for (int i = 0; i < 4; i++)
#pragma unroll
                for (int j = 0; j < 4; j++) acc[i][j] += qa[i]*ka[j];
        }
        __syncthreads();
    }
    float* sp = g_Spart + ((size_t)(vbh*32 + blockIdx.x))*4096;
#pragma unroll
    for (int i = 0; i < 4; i++)
#pragma unroll
        for (int j = 0; j < 4; j++)
            sp[(ty*4+i)*64 + tx*4 + j] = acc[i][j];
}

__global__ void softmax_kernel(const float* __restrict__ temp) {
    int blk = blockIdx.x;
    int vbh = blk >> 6, d = blk & 63;
    int var = vbh >> 3, b = (vbh>>2)&1, h = vbh & 3;
    int e = threadIdx.x;
    float sk = g_norm[(var<<10) | (1<<9) | (b<<8) | (h<<6) | e];
    float invq = g_norm[(var<<10) | (b<<8) | (h<<6) | d];
    float T = temp[h];
    const float* sp = g_Spart + (size_t)vbh*32*4096 + d*64 + e;
    float s = 0.f;
#pragma unroll
    for (int sl = 0; sl < 32; sl++) s += sp[(size_t)sl*4096];
    float ex = expf(s * invq * sk * T);
    __shared__ float red[64];
    red[e] = ex;
    __syncthreads();
    if (e < 32) {
        float p = red[e] + red[e + 32];
#pragma unroll
        for (int o = 16; o > 0; o >>= 1) p += __shfl_down_sync(0xffffffffu, p, o);
        if (e == 0) red[0] = p;
    }
    __syncthreads();
    float r = 1.0f / (red[0] + 1.0f);
    g_attn[(size_t)vbh*4096 + d*64 + e] = ex * r;
}

// merged av: var = bid bit 9
__global__ void av_kernel() {
    __shared__ float As[4096];
    int t = threadIdx.x;
    int bid = blockIdx.x;                 // 1024: (var,b,h,nblk)
    int nblk = bid & 63;
    int h = (bid>>6)&3, b = (bid>>8)&1, var = (bid>>9)&1;
    int vbh = (var<<3) | (b<<2) | h;
    for (int l = t; l < 4096; l += 256) As[l] = g_attn[(size_t)vbh*4096 + l];
    __syncthreads();
    int n = nblk*256 + t;
    float acc[64];
#pragma unroll
    for (int d2 = 0; d2 < 64; d2++) acc[d2] = 0.f;
    if (!var) {
#pragma unroll 4
        for (int e0 = 0; e0 < 64; e0 += 4) {
            int ce = h*16 + (e0 >> 2);
            size_t cb = ((size_t)(b*64 + ce))*HWv;
            float v0 = g_vs[cb + n];
            float v1 = g_vs[cb + HWP_ + n];
            float v2 = g_vs[cb + 2*HWP_ + n];
            float v3 = g_vs[cb + 3*HWP_ + n];
#pragma unroll
            for (int d2 = 0; d2 < 64; d2++) {
                float4 a = *(const float4*)&As[d2*64 + e0];
                acc[d2] += a.x*v0 + a.y*v1 + a.z*v2 + a.w*v3;
            }
        }
#pragma unroll 1
        for (int d2 = 0; d2 < 64; d2++) {
            int cd = h*16 + (d2>>2), fd = d2 & 3;
            g_out1[((size_t)(b*64 + cd))*HWv + (size_t)fd*HWP_ + n] = acc[d2];
        }
    } else {
#pragma unroll 4
        for (int e0 = 0; e0 < 64; e0 += 4) {
            int ce = h*16 + (e0 >> 2);
            size_t cb = ((size_t)(b*64 + ce))*HWv;
            float4 vv = *(const float4*)&g_vs[cb + 4*(size_t)n];
#pragma unroll
            for (int d2 = 0; d2 < 64; d2++) {
                float4 a = *(const float4*)&As[d2*64 + e0];
                acc[d2] += a.x*vv.x + a.y*vv.y + a.z*vv.z + a.w*vv.w;
            }
        }
#pragma unroll 1
        for (int cg = 0; cg < 16; cg++) {
            int cd = h*16 + cg;
            size_t rb = ((size_t)(b*64 + cd))*HWv;
            size_t pos = rb + 4*(size_t)n;
            float4 o1 = *(const float4*)&g_out1[pos];
            int4   j4 = *(const int4*)&g_idx[pos];
            g_prod[rb + j4.x] = acc[cg*4 + 0] * o1.x;
            g_prod[rb + j4.y] = acc[cg*4 + 1] * o1.y;
            g_prod[rb + j4.z] = acc[cg*4 + 2] * o1.z;
            g_prod[rb + j4.w] = acc[cg*4 + 3] * o1.w;
        }
    }
}

// ---------------- fused unsort (both axes) ----------------
__global__ void unsort_kernel(float* __restrict__ out) {
    size_t gid = (size_t)blockIdx.x*256 + threadIdx.x;
    int b = (int)(gid / ((size_t)C_*HWv));
    size_t r0 = gid % ((size_t)C_*HWv);
    int c = (int)(r0 / HWv);
    int p = (int)(r0 % HWv);
    if (c < CH_) {
        int j = p & 255;
        size_t bc = (size_t)(b*CH_ + c);
        int r = g_invh[bc*HWv + p];
        int jw = g_invw[bc*HWv + (size_t)r*W_ + j];
        out[gid] = g_proj[((size_t)(b*C_ + c))*HWv + (size_t)r*W_ + jw];
    } else {
        out[gid] = g_proj[gid];
    }
}

// ---------------- launch ----------------
extern "C" void kernel_launch(void* const* d_in, const int* in_sizes, int n_in,
                              void* d_out, int out_size) {
    const float* x     = (const float*)d_in[0];
    const float* qkvw  = (const float*)d_in[1];
    const float* dww   = (const float*)d_in[2];
    const float* projw = (const float*)d_in[3];
    const float* temp  = (const float*)d_in[4];
    float* out = (float*)d_out;

    cudaFuncSetAttribute((const void*)conv1x1_kernel,
                         cudaFuncAttributeMaxDynamicSharedMemorySize, CV_SMEM);

    float *p_xcat, *p_qkvpre, *p_prod, *p_proj;
    unsigned long long *p_sA, *p_sB;
    cudaGetSymbolAddress((void**)&p_xcat,   g_xcat);
    cudaGetSymbolAddress((void**)&p_qkvpre, g_qkv_pre);
    cudaGetSymbolAddress((void**)&p_prod,   g_prod);
    cudaGetSymbolAddress((void**)&p_proj,   g_proj);
    cudaGetSymbolAddress((void**)&p_sA,     g_sortA);
    cudaGetSymbolAddress((void**)&p_sB,     g_sortB);

    const int NBC  = (B_*C_*HWv) / 256;     // 32768

    // stage A: small sorts (+ inverse perms fused)
    sort_h_kernel<<<B_*CH_*W_, 256>>>(x);
    sort_w_kernel<<<B_*CH_*H_, 256>>>();
    copy_rest_kernel<<<(B_*CH_*HWv/4)/256, 256>>>(x);

    // stage B: convs (dwconv also emits sort keys for v channels)
    conv1x1_kernel<<<dim3(HWv/CV_PX, QKVC/64, B_), 256, CV_SMEM>>>(p_xcat, qkvw, p_qkvpre, QKVC);
    dwconv_kernel<<<B_*QKVC*32, 256>>>(p_qkvpre, dww);

    // stage C: big stable argsort of v rows (multi-block radix, 4 passes)
    {
        const int NB = R_ROWS * R_NSEG;   // 2048
        unsigned long long* bufs[2] = { p_sA, p_sB };
        int shifts[4] = { 32, 40, 48, 56 };
        for (int p2 = 0; p2 < 4; p2++) {
            unsigned long long* s = bufs[p2 & 1];
            unsigned long long* d = bufs[(p2 & 1) ^ 1];
            rhist_kernel   <<<NB, R_THREADS>>>(s, shifts[p2]);
            rscan_kernel   <<<R_ROWS, 256>>>();
            rscatter_kernel<<<NB, R_THREADS>>>(s, d, shifts[p2]);
        }
    }
    extract_gather_kernel<<<NBC, 256>>>();
    reduce_norm_kernel<<<16, 128>>>();

    // stage D: attention (both variants)
    qk_kernel<<<dim3(32, 16), 256>>>();
    softmax_kernel<<<16*64, 64>>>(temp);
    av_kernel<<<1024, 256>>>();

    // stage E: epilogue
    conv1x1_kernel<<<dim3(HWv/CV_PX, 1, B_), 256, CV_SMEM>>>(p_prod, projw, p_proj, C_);
    unsort_kernel<<<NBC, 256>>>(out);
}

// round 9
// speedup vs baseline: 1.4145x; 1.0135x over previous
#include <cuda_runtime.h>
#include <math.h>

// ---------------- constants ----------------
#define B_   2
#define C_   64
#define CH_  32
#define H_   256
#define W_   256
#define HWv  65536
#define QKVC 320
#define NH_  4
#define HWP_ 16384

// radix sort config
#define R_ROWS 128
#define R_N    65536
#define R_SEG  4096
#define R_NSEG 16
#define R_THREADS 512
#define R_EPT  8

// conv1x1 tiling
#define CV_PX 256
#define CV_SMEM (64*CV_PX*4 + 64*64*4)   // 81920 bytes

// ---------------- scratch (static device memory; no allocs) ----------------
__device__ float g_xcat[B_*C_*HWv];
__device__ int   g_invh[B_*CH_*HWv];
__device__ int   g_invw[B_*CH_*HWv];
__device__ float g_qkv_pre[B_*QKVC*HWv];
__device__ float g_qkv[B_*QKVC*HWv];
__device__ unsigned long long g_sortA[B_*C_*HWv];
__device__ unsigned long long g_sortB[B_*C_*HWv];
__device__ unsigned g_rhist[R_ROWS*256*R_NSEG];
__device__ int   g_idx[B_*C_*HWv];
__device__ float g_vs [B_*C_*HWv];
__device__ float g_norm[2048];
__device__ float g_npart[2048*32];            // [bin][slice]
__device__ float g_Spart[16*32*4096];
__device__ float g_attn[16*4096];
__device__ float g_out1[B_*C_*HWv];
__device__ float g_prod[B_*C_*HWv];
__device__ float g_proj[B_*C_*HWv];

// ---------------- small stable bitonic sort (256 elems) ----------------
__device__ __forceinline__ bool pair_gt(float va, int ia, float vb, int ib) {
    return (va > vb) || (va == vb && ia > ib);
}

__device__ __forceinline__ void bitonic256(float* sv, int* si) {
    int t = threadIdx.x;
    for (int k = 2; k <= 256; k <<= 1) {
        for (int j = k >> 1; j > 0; j >>= 1) {
            int ixj = t ^ j;
            if (ixj > t) {
                bool up = ((t & k) == 0);
                float va = sv[t], vb = sv[ixj];
                int   ia = si[t], ib = si[ixj];
                bool sw = up ? pair_gt(va, ia, vb, ib) : pair_gt(vb, ib, va, ia);
                if (sw) { sv[t] = vb; si[t] = ib; sv[ixj] = va; si[ixj] = ia; }
            }
            __syncthreads();
        }
    }
}

__global__ void sort_h_kernel(const float* __restrict__ x) {
    __shared__ float sv[256];
    __shared__ int   si[256];
    int blk = blockIdx.x;
    int b = blk / (CH_*W_);
    int c = (blk / W_) % CH_;
    int w = blk % W_;
    int t = threadIdx.x;
    const float* xp = x + ((size_t)(b*C_ + c))*HWv + w;
    sv[t] = xp[(size_t)t * W_];
    si[t] = t;
    __syncthreads();
    bitonic256(sv, si);
    g_xcat[((size_t)(b*C_ + c))*HWv + (size_t)t*W_ + w] = sv[t];
    g_invh[((size_t)(b*CH_ + c))*HWv + (size_t)si[t]*W_ + w] = t;
}

__global__ void sort_w_kernel() {
    __shared__ float sv[256];
    __shared__ int   si[256];
    int blk = blockIdx.x;
    int b = blk / (CH_*H_);
    int c = (blk / H_) % CH_;
    int h = blk % H_;
    int t = threadIdx.x;
    float* base = g_xcat + ((size_t)(b*C_ + c))*HWv + (size_t)h*W_;
    sv[t] = base[t];
    si[t] = t;
    __syncthreads();
    bitonic256(sv, si);
    base[t] = sv[t];
    g_invw[((size_t)(b*CH_ + c))*HWv + (size_t)h*W_ + si[t]] = t;
}

__global__ void copy_rest_kernel(const float* __restrict__ x) {
    size_t gid = (size_t)blockIdx.x*256 + threadIdx.x;
    int b = (int)(gid / ((size_t)CH_*HWv/4));
    size_t r = gid % ((size_t)CH_*HWv/4);
    int c = CH_ + (int)(r / (HWv/4));
    int p = (int)(r % (HWv/4)) * 4;
    size_t off = ((size_t)(b*C_ + c))*HWv + p;
    *(float4*)&g_xcat[off] = *(const float4*)&x[off];
}

// ---------------- conv1x1 (IC=64; tile 256px x 64oc; 8x8 microtile) ----------------
__global__ void __launch_bounds__(256)
conv1x1_kernel(const float* __restrict__ in, const float* __restrict__ w,
               float* __restrict__ out, int OC) {
    extern __shared__ float sm[];
    float* Xs = sm;                 // [64][256]
    float* Ws = sm + 64*CV_PX;      // [64][64]
    int p0  = blockIdx.x * CV_PX;
    int oc0 = blockIdx.y * 64;
    int b   = blockIdx.z;
    int t   = threadIdx.x;
#pragma unroll
    for (int r = 0; r < 16; r++) {
        int l = r*256 + t; int ic = l >> 6; int grp = l & 63;
        *(float4*)&Xs[ic*CV_PX + grp*4] =
            *(const float4*)&in[((size_t)(b*64 + ic))*HWv + p0 + grp*4];
    }
#pragma unroll
    for (int r = 0; r < 16; r++) {
        int l = r*256 + t; int oc = l >> 6; int ic = l & 63;
        Ws[ic*64 + oc] = w[(size_t)(oc0 + oc)*64 + ic];
    }
    __syncthreads();
    int tx = t & 31, ty = t >> 5;
    float acc[8][8];
#pragma unroll
    for (int i = 0; i < 8; i++)
#pragma unroll
        for (int j = 0; j < 8; j++) acc[i][j] = 0.f;
#pragma unroll
    for (int ic = 0; ic < 64; ic++) {
        float4 xa = *(const float4*)&Xs[ic*CV_PX + tx*4];
        float4 xb = *(const float4*)&Xs[ic*CV_PX + 128 + tx*4];
        float4 wa = *(const float4*)&Ws[ic*64 + ty*8];
        float4 wb = *(const float4*)&Ws[ic*64 + ty*8 + 4];
        float xv[8] = {xa.x,xa.y,xa.z,xa.w,xb.x,xb.y,xb.z,xb.w};
        float wv[8] = {wa.x,wa.y,wa.z,wa.w,wb.x,wb.y,wb.z,wb.w};
#pragma unroll
        for (int i = 0; i < 8; i++)
#pragma unroll
            for (int j = 0; j < 8; j++) acc[i][j] += wv[i]*xv[j];
    }
#pragma unroll
    for (int i = 0; i < 8; i++) {
        size_t ob = ((size_t)(b*OC + oc0 + ty*8 + i))*HWv + p0;
        *(float4*)&out[ob + tx*4]       = make_float4(acc[i][0],acc[i][1],acc[i][2],acc[i][3]);
        *(float4*)&out[ob + 128 + tx*4] = make_float4(acc[i][4],acc[i][5],acc[i][6],acc[i][7]);
    }
}

// ---------------- depthwise 3x3 SAME, 2D smem tile (8 rows/block) ----------------
__global__ void __launch_bounds__(256)
dwconv_kernel(const float* __restrict__ in, const float* __restrict__ wd) {
    __shared__ float tile[10][W_];
    int bid = blockIdx.x;
    int hblk = bid & 31;
    int chbc = bid >> 5;
    int ch = chbc % QKVC;
    int b  = chbc / QKVC;
    int h0 = hblk * 8;
    int t = threadIdx.x;
    const float* ip = in + (size_t)chbc * HWv;
#pragma unroll
    for (int r = 0; r < 10; r++) {
        int hh = h0 - 1 + r;
        tile[r][t] = (hh >= 0 && hh < H_) ? ip[(size_t)hh*W_ + t] : 0.f;
    }
    float wreg[9];
#pragma unroll
    for (int i = 0; i < 9; i++) wreg[i] = __ldg(&wd[(size_t)ch*9 + i]);
    __syncthreads();

    float wl[10], wm[10], wr[10];
#pragma unroll
    for (int r = 0; r < 10; r++) {
        wm[r] = tile[r][t];
        wl[r] = (t > 0)   ? tile[r][t-1] : 0.f;
        wr[r] = (t < 255) ? tile[r][t+1] : 0.f;
    }

    if (ch < 256) {
        float* op = g_qkv + (size_t)chbc*HWv;
#pragma unroll
        for (int r = 0; r < 8; r++) {
            float s = wl[r  ]*wreg[0] + wm[r  ]*wreg[1] + wr[r  ]*wreg[2]
                    + wl[r+1]*wreg[3] + wm[r+1]*wreg[4] + wr[r+1]*wreg[5]
                    + wl[r+2]*wreg[6] + wm[r+2]*wreg[7] + wr[r+2]*wreg[8];
            op[(size_t)(h0 + r)*W_ + t] = s;
        }
    } else {
        int row = b*64 + (ch - 256);
        unsigned long long* kp = g_sortA + (size_t)row*HWv;
#pragma unroll
        for (int r = 0; r < 8; r++) {
            float s = wl[r  ]*wreg[0] + wm[r  ]*wreg[1] + wr[r  ]*wreg[2]
                    + wl[r+1]*wreg[3] + wm[r+1]*wreg[4] + wr[r+1]*wreg[5]
                    + wl[r+2]*wreg[6] + wm[r+2]*wreg[7] + wr[r+2]*wreg[8];
            unsigned u = __float_as_uint(s);
            u ^= (u & 0x80000000u) ? 0xFFFFFFFFu : 0x80000000u;
            int n = (h0 + r)*W_ + t;
            kp[n] = ((unsigned long long)u << 32) | (unsigned)n;
        }
    }
}

// ---------------- multi-block stable radix sort (8-bit digit) ----------------
__global__ void rhist_kernel(const unsigned long long* __restrict__ src, int shift) {
    __shared__ unsigned h[256];
    int row = blockIdx.x >> 4, seg = blockIdx.x & 15;
    int tid = threadIdx.x;
    if (tid < 256) h[tid] = 0;
    __syncthreads();
    const unsigned long long* s = src + (size_t)row*R_N + (size_t)seg*R_SEG;
#pragma unroll
    for (int r = 0; r < R_EPT; r++) {
        unsigned dg = (unsigned)(s[r*R_THREADS + tid] >> shift) & 255u;
        atomicAdd(&h[dg], 1u);
    }
    __syncthreads();
    if (tid < 256)
        g_rhist[((size_t)row*256 + tid)*R_NSEG + seg] = h[tid];
}

__global__ void rscan_kernel() {
    int row = blockIdx.x, dg = threadIdx.x;
    unsigned* hp = g_rhist + ((size_t)row*256 + dg)*R_NSEG;
    unsigned v[R_NSEG]; unsigned tot = 0;
#pragma unroll
    for (int s2 = 0; s2 < R_NSEG; s2++) { unsigned t = hp[s2]; v[s2] = tot; tot += t; }
    unsigned lane = dg & 31, w = dg >> 5;
    unsigned x = tot;
#pragma unroll
    for (int o = 1; o < 32; o <<= 1) { unsigned y = __shfl_up_sync(0xffffffffu, x, o); if (lane >= o) x += y; }
    __shared__ unsigned wsum[8];
    if (lane == 31) wsum[w] = x;
    __syncthreads();
    if (dg == 0) { unsigned run = 0; for (int i = 0; i < 8; i++) { unsigned t = wsum[i]; wsum[i] = run; run += t; } }
    __syncthreads();
    unsigned base0 = (x - tot) + wsum[w];
#pragma unroll
    for (int s2 = 0; s2 < R_NSEG; s2++) hp[s2] = base0 + v[s2];
}

// final!=0: emit g_idx / g_vs directly instead of u64 keys
__global__ void __launch_bounds__(R_THREADS)
rscatter_kernel(const unsigned long long* __restrict__ src,
                unsigned long long* __restrict__ dst, int shift, int final_) {
    __shared__ unsigned base[256];
    __shared__ unsigned bb0[256];
    __shared__ unsigned delta[256];
    __shared__ unsigned scanbuf[8];
    __shared__ unsigned long long stage[R_SEG];
    unsigned short* wcnt = (unsigned short*)stage;
    unsigned*       woff = (unsigned*)(stage + 1024);

    int row = blockIdx.x >> 4, seg = blockIdx.x & 15;
    int tid = threadIdx.x, w = tid >> 5, lane = tid & 31;
    const unsigned long long* s = src + (size_t)row*R_N + (size_t)seg*R_SEG;

    unsigned long long kv[R_EPT];
    unsigned posG[R_EPT];
#pragma unroll
    for (int r = 0; r < R_EPT; r++) kv[r] = s[r*R_THREADS + tid];

    if (tid < 256) {
        unsigned bv = g_rhist[((size_t)row*256 + tid)*R_NSEG + seg];
        base[tid] = bv; bb0[tid] = bv;
    }

    unsigned* wc32 = (unsigned*)wcnt;
#pragma unroll
    for (int r = 0; r < R_EPT; r++) {
        wc32[tid] = 0; wc32[tid + 512] = 0; wc32[tid + 1024] = 0; wc32[tid + 1536] = 0;
        unsigned dg = (unsigned)(kv[r] >> shift) & 255u;
        unsigned mask = __match_any_sync(0xffffffffu, dg);
        unsigned lr = __popc(mask & ((1u << lane) - 1u));
        unsigned cnt = __popc(mask);
        __syncthreads();
        if (lr == 0) wcnt[w*256 + dg] = (unsigned short)cnt;
        __syncthreads();
        if (tid < 256) {
            unsigned run = base[tid];
#pragma unroll
            for (int ww = 0; ww < 16; ww++) {
                unsigned c2 = wcnt[ww*256 + tid];
                woff[ww*256 + tid] = run;
                run += c2;
            }
            base[tid] = run;
        }
        __syncthreads();
        posG[r] = woff[w*256 + dg] + lr;
    }
    __syncthreads();

    if (tid < 256) {
        unsigned c = base[tid] - bb0[tid];
        unsigned x = c;
#pragma unroll
        for (int o = 1; o < 32; o <<= 1) { unsigned y = __shfl_up_sync(0xffffffffu, x, o); if (lane >= o) x += y; }
        woff[tid] = x - c;
        if (lane == 31) scanbuf[w] = x;
    }
    __syncthreads();
    if (tid == 0) { unsigned run = 0; for (int i = 0; i < 8; i++) { unsigned t2 = scanbuf[i]; scanbuf[i] = run; run += t2; } }
    __syncthreads();
    if (tid < 256) delta[tid] = bb0[tid] - (woff[tid] + scanbuf[tid >> 5]);
    __syncthreads();

#pragma unroll
    for (int r = 0; r < R_EPT; r++) {
        unsigned dg = (unsigned)(kv[r] >> shift) & 255u;
        stage[posG[r] - delta[dg]] = kv[r];
    }
    __syncthreads();
    if (!final_) {
        unsigned long long* d = dst + (size_t)row*R_N;
#pragma unroll
        for (int r = 0; r < R_EPT; r++) {
            unsigned i = r*R_THREADS + tid;
            unsigned long long k2 = stage[i];
            unsigned dg = (unsigned)(k2 >> shift) & 255u;
            d[delta[dg] + i] = k2;
        }
    } else {
        int*   di = g_idx + (size_t)row*R_N;
        float* dv = g_vs  + (size_t)row*R_N;
#pragma unroll
        for (int r = 0; r < R_EPT; r++) {
            unsigned i = r*R_THREADS + tid;
            unsigned long long k2 = stage[i];
            unsigned dg = (unsigned)(k2 >> shift) & 255u;
            unsigned pos = delta[dg] + i;
            unsigned u = (unsigned)(k2 >> 32);
            u = (u & 0x80000000u) ? (u ^ 0x80000000u) : ~u;
            di[pos] = (int)(k2 & 0xFFFFFFFFu);
            dv[pos] = __uint_as_float(u);
        }
    }
}

// ---------------- attention: qk with direct gather + norm partials ----------------
__global__ void qk_kernel() {
    __shared__ float Qs[64][65];
    __shared__ float Ks[64][65];
    __shared__ float nred[2][4][64];
    int t = threadIdx.x;
    int vbh = blockIdx.y;
    int var = vbh >> 3, b = (vbh>>2)&1, h = vbh & 3;
    int ty = t >> 4, tx = t & 15;
    int dn = t & 63, qtr = t >> 6;
    float acc[4][4];
#pragma unroll
    for (int i = 0; i < 4; i++)
#pragma unroll
        for (int j = 0; j < 4; j++) acc[i][j] = 0.f;
    float sumq = 0.f, sumk = 0.f;
    int n0 = blockIdx.x * 512;
    int qplane = var ? 128 : 0;
    for (int tile = 0; tile < 8; tile++) {
        int nb = n0 + tile*64;
#pragma unroll
        for (int rr = 0; rr < 16; rr++) {
            int l = rr*256 + t; int d = l >> 6; int nn = l & 63;
            int c = h*16 + (d>>2), f = d & 3;
            int pos = var ? 4*(nb+nn) + f : f*HWP_ + nb + nn;
            int j = g_idx[((size_t)(b*64 + c))*HWv + pos];
            size_t qb = ((size_t)(b*QKVC + qplane + c))*HWv;
            Qs[d][nn] = g_qkv[qb + j];
            Ks[d][nn] = g_qkv[qb + (size_t)64*HWv + j];
        }
        __syncthreads();
        // norm partials: 4 threads per d, 16 nn each
#pragma unroll
        for (int i = 0; i < 16; i++) {
            float qv = Qs[dn][qtr*16 + i];
            float kv = Ks[dn][qtr*16 + i];
            sumq += qv*qv; sumk += kv*kv;
        }
#pragma unroll 8
        for (int nn = 0; nn < 64; nn++) {
            float qa[4], ka[4];
#pragma unroll
            for (int i = 0; i < 4; i++) { qa[i] = Qs[ty*4+i][nn]; ka[i] = Ks[tx*4+i][nn]; }
#pragma unroll
            for (int i = 0; i < 4; i++)
#pragma unroll
                for (int j = 0; j < 4; j++) acc[i][j] += qa[i]*ka[j];
        }
        __syncthreads();
    }
    nred[0][qtr][dn] = sumq;
    nred[1][qtr][dn] = sumk;
    float* sp = g_Spart + ((size_t)(vbh*32 + blockIdx.x))*4096;
#pragma unroll
    for (int i = 0; i < 4; i++)
#pragma unroll
        for (int j = 0; j < 4; j++)
            sp[(ty*4+i)*64 + tx*4 + j] = acc[i][j];
    __syncthreads();
    if (t < 128) {
        int qk = t >> 6, d = t & 63;
        float s = nred[qk][0][d] + nred[qk][1][d] + nred[qk][2][d] + nred[qk][3][d];
        int bin = (var<<10) | (qk<<9) | (b<<8) | (h<<6) | d;
        g_npart[(size_t)bin*32 + blockIdx.x] = s;
    }
}

__global__ void reduce_norm_kernel() {
    int bin = blockIdx.x * 128 + threadIdx.x;   // 2048
    const float* p = g_npart + (size_t)bin*32;
    float s = 0.f;
#pragma unroll
    for (int i = 0; i < 32; i++) s += p[i];
    g_norm[bin] = 1.0f / fmaxf(sqrtf(s), 1e-12f);
}

__global__ void softmax_kernel(const float* __restrict__ temp) {
    int blk = blockIdx.x;
    int vbh = blk >> 6, d = blk & 63;
    int var = vbh >> 3, b = (vbh>>2)&1, h = vbh & 3;
    int e = threadIdx.x;
    float sk = g_norm[(var<<10) | (1<<9) | (b<<8) | (h<<6) | e];
    float invq = g_norm[(var<<10) | (b<<8) | (h<<6) | d];
    float T = temp[h];
    const float* sp = g_Spart + (size_t)vbh*32*4096 + d*64 + e;
    float s = 0.f;
#pragma unroll
    for (int sl = 0; sl < 32; sl++) s += sp[(size_t)sl*4096];
    float ex = expf(s * invq * sk * T);
    __shared__ float red[64];
    red[e] = ex;
    __syncthreads();
    if (e < 32) {
        float p = red[e] + red[e + 32];
#pragma unroll
        for (int o = 16; o > 0; o >>= 1) p += __shfl_down_sync(0xffffffffu, p, o);
        if (e == 0) red[0] = p;
    }
    __syncthreads();
    float r = 1.0f / (red[0] + 1.0f);
    g_attn[(size_t)vbh*4096 + d*64 + e] = ex * r;
}

// merged av: var = bid bit 9
__global__ void av_kernel() {
    __shared__ float As[4096];
    int t = threadIdx.x;
    int bid = blockIdx.x;
    int nblk = bid & 63;
    int h = (bid>>6)&3, b = (bid>>8)&1, var = (bid>>9)&1;
    int vbh = (var<<3) | (b<<2) | h;
    for (int l = t; l < 4096; l += 256) As[l] = g_attn[(size_t)vbh*4096 + l];
    __syncthreads();
    int n = nblk*256 + t;
    float acc[64];
#pragma unroll
    for (int d2 = 0; d2 < 64; d2++) acc[d2] = 0.f;
    if (!var) {
#pragma unroll 4
        for (int e0 = 0; e0 < 64; e0 += 4) {
            int ce = h*16 + (e0 >> 2);
            size_t cb = ((size_t)(b*64 + ce))*HWv;
            float v0 = g_vs[cb + n];
            float v1 = g_vs[cb + HWP_ + n];
            float v2 = g_vs[cb + 2*HWP_ + n];
            float v3 = g_vs[cb + 3*HWP_ + n];
#pragma unroll
            for (int d2 = 0; d2 < 64; d2++) {
                float4 a = *(const float4*)&As[d2*64 + e0];
                acc[d2] += a.x*v0 + a.y*v1 + a.z*v2 + a.w*v3;
            }
        }
#pragma unroll 1
        for (int d2 = 0; d2 < 64; d2++) {
            int cd = h*16 + (d2>>2), fd = d2 & 3;
            g_out1[((size_t)(b*64 + cd))*HWv + (size_t)fd*HWP_ + n] = acc[d2];
        }
    } else {
#pragma unroll 4
        for (int e0 = 0; e0 < 64; e0 += 4) {
            int ce = h*16 + (e0 >> 2);
            size_t cb = ((size_t)(b*64 + ce))*HWv;
            float4 vv = *(const float4*)&g_vs[cb + 4*(size_t)n];
#pragma unroll
            for (int d2 = 0; d2 < 64; d2++) {
                float4 a = *(const float4*)&As[d2*64 + e0];
                acc[d2] += a.x*vv.x + a.y*vv.y + a.z*vv.z + a.w*vv.w;
            }
        }
#pragma unroll 1
        for (int cg = 0; cg < 16; cg++) {
            int cd = h*16 + cg;
            size_t rb = ((size_t)(b*64 + cd))*HWv;
            size_t pos = rb + 4*(size_t)n;
            float4 o1 = *(const float4*)&g_out1[pos];
            int4   j4 = *(const int4*)&g_idx[pos];
            g_prod[rb + j4.x] = acc[cg*4 + 0] * o1.x;
            g_prod[rb + j4.y] = acc[cg*4 + 1] * o1.y;
            g_prod[rb + j4.z] = acc[cg*4 + 2] * o1.z;
            g_prod[rb + j4.w] = acc[cg*4 + 3] * o1.w;
        }
    }
}

// ---------------- fused unsort (both axes) ----------------
__global__ void unsort_kernel(float* __restrict__ out) {
    size_t gid = (size_t)blockIdx.x*256 + threadIdx.x;
    int b = (int)(gid / ((size_t)C_*HWv));
    size_t r0 = gid % ((size_t)C_*HWv);
    int c = (int)(r0 / HWv);
    int p = (int)(r0 % HWv);
    if (c < CH_) {
        int j = p & 255;
        size_t bc = (size_t)(b*CH_ + c);
        int r = g_invh[bc*HWv + p];
        int jw = g_invw[bc*HWv + (size_t)r*W_ + j];
        out[gid] = g_proj[((size_t)(b*C_ + c))*HWv + (size_t)r*W_ + jw];
    } else {
        out[gid] = g_proj[gid];
    }
}

// ---------------- launch ----------------
extern "C" void kernel_launch(void* const* d_in, const int* in_sizes, int n_in,
                              void* d_out, int out_size) {
    const float* x     = (const float*)d_in[0];
    const float* qkvw  = (const float*)d_in[1];
    const float* dww   = (const float*)d_in[2];
    const float* projw = (const float*)d_in[3];
    const float* temp  = (const float*)d_in[4];
    float* out = (float*)d_out;

    cudaFuncSetAttribute((const void*)conv1x1_kernel,
                         cudaFuncAttributeMaxDynamicSharedMemorySize, CV_SMEM);

    float *p_xcat, *p_qkvpre, *p_prod, *p_proj;
    unsigned long long *p_sA, *p_sB;
    cudaGetSymbolAddress((void**)&p_xcat,   g_xcat);
    cudaGetSymbolAddress((void**)&p_qkvpre, g_qkv_pre);
    cudaGetSymbolAddress((void**)&p_prod,   g_prod);
    cudaGetSymbolAddress((void**)&p_proj,   g_proj);
    cudaGetSymbolAddress((void**)&p_sA,     g_sortA);
    cudaGetSymbolAddress((void**)&p_sB,     g_sortB);

    const int NBC  = (B_*C_*HWv) / 256;     // 32768

    // stage A: small sorts (+ inverse perms fused)
    sort_h_kernel<<<B_*CH_*W_, 256>>>(x);
    sort_w_kernel<<<B_*CH_*H_, 256>>>();
    copy_rest_kernel<<<(B_*CH_*HWv/4)/256, 256>>>(x);

    // stage B: convs (dwconv also emits sort keys for v channels)
    conv1x1_kernel<<<dim3(HWv/CV_PX, QKVC/64, B_), 256, CV_SMEM>>>(p_xcat, qkvw, p_qkvpre, QKVC);
    dwconv_kernel<<<B_*QKVC*32, 256>>>(p_qkvpre, dww);

    // stage C: big stable argsort (final pass emits idx+vs directly)
    {
        const int NB = R_ROWS * R_NSEG;   // 2048
        unsigned long long* bufs[2] = { p_sA, p_sB };
        int shifts[4] = { 32, 40, 48, 56 };
        for (int p2 = 0; p2 < 4; p2++) {
            unsigned long long* s = bufs[p2 & 1];
            unsigned long long* d = bufs[(p2 & 1) ^ 1];
            rhist_kernel   <<<NB, R_THREADS>>>(s, shifts[p2]);
            rscan_kernel   <<<R_ROWS, 256>>>();
            rscatter_kernel<<<NB, R_THREADS>>>(s, d, shifts[p2], p2 == 3);
        }
    }

    // stage D: attention (qk gathers directly; norm partials fused)
    qk_kernel<<<dim3(32, 16), 256>>>();
    reduce_norm_kernel<<<16, 128>>>();
    softmax_kernel<<<16*64, 64>>>(temp);
    av_kernel<<<1024, 256>>>();

    // stage E: epilogue
    conv1x1_kernel<<<dim3(HWv/CV_PX, 1, B_), 256, CV_SMEM>>>(p_prod, projw, p_proj, C_);
    unsort_kernel<<<NBC, 256>>>(out);
}

// round 10
// speedup vs baseline: 1.4319x; 1.0123x over previous
#include <cuda_runtime.h>
#include <math.h>

// ---------------- constants ----------------
#define B_   2
#define C_   64
#define CH_  32
#define H_   256
#define W_   256
#define HWv  65536
#define QKVC 320
#define NH_  4
#define HWP_ 16384

// radix sort config
#define R_ROWS 128
#define R_N    65536
#define R_SEG  4096
#define R_NSEG 16
#define R_THREADS 512
#define R_EPT  8

// qk slicing
#define QK_SL 64

// conv1x1 tiling
#define CV_PX 256
#define CV_SMEM (64*CV_PX*4 + 64*64*4)   // 81920 bytes

// ---------------- scratch (static device memory; no allocs) ----------------
__device__ float g_xcat[B_*C_*HWv];
__device__ int   g_invh[B_*CH_*HWv];
__device__ int   g_invw[B_*CH_*HWv];
__device__ float g_qkv_pre[B_*QKVC*HWv];
__device__ float g_qkv[B_*QKVC*HWv];
__device__ unsigned g_keyA[R_ROWS*R_N];
__device__ unsigned g_keyB[R_ROWS*R_N];
__device__ unsigned short g_pidA[R_ROWS*R_N];
__device__ unsigned short g_pidB[R_ROWS*R_N];
__device__ unsigned g_rhist[R_ROWS*256*R_NSEG];
__device__ int   g_idx[B_*C_*HWv];
__device__ float g_vs [B_*C_*HWv];
__device__ float g_norm[2048];
__device__ float g_npart[2048*QK_SL];
__device__ float g_Spart[16*QK_SL*4096];
__device__ float g_attn[16*4096];
__device__ float g_out1[B_*C_*HWv];
__device__ float g_prod[B_*C_*HWv];
__device__ float g_proj[B_*C_*HWv];

// ---------------- small stable bitonic sort (256 elems) ----------------
__device__ __forceinline__ bool pair_gt(float va, int ia, float vb, int ib) {
    return (va > vb) || (va == vb && ia > ib);
}

__device__ __forceinline__ void bitonic256(float* sv, int* si) {
    int t = threadIdx.x;
    for (int k = 2; k <= 256; k <<= 1) {
        for (int j = k >> 1; j > 0; j >>= 1) {
            int ixj = t ^ j;
            if (ixj > t) {
                bool up = ((t & k) == 0);
                float va = sv[t], vb = sv[ixj];
                int   ia = si[t], ib = si[ixj];
                bool sw = up ? pair_gt(va, ia, vb, ib) : pair_gt(vb, ib, va, ia);
                if (sw) { sv[t] = vb; si[t] = ib; sv[ixj] = va; si[ixj] = ia; }
            }
            __syncthreads();
        }
    }
}

__global__ void sort_h_kernel(const float* __restrict__ x) {
    __shared__ float sv[256];
    __shared__ int   si[256];
    int blk = blockIdx.x;
    int b = blk / (CH_*W_);
    int c = (blk / W_) % CH_;
    int w = blk % W_;
    int t = threadIdx.x;
    const float* xp = x + ((size_t)(b*C_ + c))*HWv + w;
    sv[t] = xp[(size_t)t * W_];
    si[t] = t;
    __syncthreads();
    bitonic256(sv, si);
    g_xcat[((size_t)(b*C_ + c))*HWv + (size_t)t*W_ + w] = sv[t];
    g_invh[((size_t)(b*CH_ + c))*HWv + (size_t)si[t]*W_ + w] = t;
}

__global__ void sort_w_kernel() {
    __shared__ float sv[256];
    __shared__ int   si[256];
    int blk = blockIdx.x;
    int b = blk / (CH_*H_);
    int c = (blk / H_) % CH_;
    int h = blk % H_;
    int t = threadIdx.x;
    float* base = g_xcat + ((size_t)(b*C_ + c))*HWv + (size_t)h*W_;
    sv[t] = base[t];
    si[t] = t;
    __syncthreads();
    bitonic256(sv, si);
    base[t] = sv[t];
    g_invw[((size_t)(b*CH_ + c))*HWv + (size_t)h*W_ + si[t]] = t;
}

__global__ void copy_rest_kernel(const float* __restrict__ x) {
    size_t gid = (size_t)blockIdx.x*256 + threadIdx.x;
    int b = (int)(gid / ((size_t)CH_*HWv/4));
    size_t r = gid % ((size_t)CH_*HWv/4);
    int c = CH_ + (int)(r / (HWv/4));
    int p = (int)(r % (HWv/4)) * 4;
    size_t off = ((size_t)(b*C_ + c))*HWv + p;
    *(float4*)&g_xcat[off] = *(const float4*)&x[off];
}

// ---------------- conv1x1 (IC=64; tile 256px x 64oc; 8x8 microtile) ----------------
__global__ void __launch_bounds__(256)
conv1x1_kernel(const float* __restrict__ in, const float* __restrict__ w,
               float* __restrict__ out, int OC) {
    extern __shared__ float sm[];
    float* Xs = sm;                 // [64][256]
    float* Ws = sm + 64*CV_PX;      // [64][64]
    int p0  = blockIdx.x * CV_PX;
    int oc0 = blockIdx.y * 64;
    int b   = blockIdx.z;
    int t   = threadIdx.x;
#pragma unroll
    for (int r = 0; r < 16; r++) {
        int l = r*256 + t; int ic = l >> 6; int grp = l & 63;
        *(float4*)&Xs[ic*CV_PX + grp*4] =
            *(const float4*)&in[((size_t)(b*64 + ic))*HWv + p0 + grp*4];
    }
#pragma unroll
    for (int r = 0; r < 16; r++) {
        int l = r*256 + t; int oc = l >> 6; int ic = l & 63;
        Ws[ic*64 + oc] = w[(size_t)(oc0 + oc)*64 + ic];
    }
    __syncthreads();
    int tx = t & 31, ty = t >> 5;
    float acc[8][8];
#pragma unroll
    for (int i = 0; i < 8; i++)
#pragma unroll
        for (int j = 0; j < 8; j++) acc[i][j] = 0.f;
#pragma unroll
    for (int ic = 0; ic < 64; ic++) {
        float4 xa = *(const float4*)&Xs[ic*CV_PX + tx*4];
        float4 xb = *(const float4*)&Xs[ic*CV_PX + 128 + tx*4];
        float4 wa = *(const float4*)&Ws[ic*64 + ty*8];
        float4 wb = *(const float4*)&Ws[ic*64 + ty*8 + 4];
        float xv[8] = {xa.x,xa.y,xa.z,xa.w,xb.x,xb.y,xb.z,xb.w};
        float wv[8] = {wa.x,wa.y,wa.z,wa.w,wb.x,wb.y,wb.z,wb.w};
#pragma unroll
        for (int i = 0; i < 8; i++)
#pragma unroll
            for (int j = 0; j < 8; j++) acc[i][j] += wv[i]*xv[j];
    }
#pragma unroll
    for (int i = 0; i < 8; i++) {
        size_t ob = ((size_t)(b*OC + oc0 + ty*8 + i))*HWv + p0;
        *(float4*)&out[ob + tx*4]       = make_float4(acc[i][0],acc[i][1],acc[i][2],acc[i][3]);
        *(float4*)&out[ob + 128 + tx*4] = make_float4(acc[i][4],acc[i][5],acc[i][6],acc[i][7]);
    }
}

// ---------------- depthwise 3x3 SAME, 2D smem tile (8 rows/block) ----------------
__global__ void __launch_bounds__(256)
dwconv_kernel(const float* __restrict__ in, const float* __restrict__ wd) {
    __shared__ float tile[10][W_];
    int bid = blockIdx.x;
    int hblk = bid & 31;
    int chbc = bid >> 5;
    int ch = chbc % QKVC;
    int b  = chbc / QKVC;
    int h0 = hblk * 8;
    int t = threadIdx.x;
    const float* ip = in + (size_t)chbc * HWv;
#pragma unroll
    for (int r = 0; r < 10; r++) {
        int hh = h0 - 1 + r;
        tile[r][t] = (hh >= 0 && hh < H_) ? ip[(size_t)hh*W_ + t] : 0.f;
    }
    float wreg[9];
#pragma unroll
    for (int i = 0; i < 9; i++) wreg[i] = __ldg(&wd[(size_t)ch*9 + i]);
    __syncthreads();

    float wl[10], wm[10], wr[10];
#pragma unroll
    for (int r = 0; r < 10; r++) {
        wm[r] = tile[r][t];
        wl[r] = (t > 0)   ? tile[r][t-1] : 0.f;
        wr[r] = (t < 255) ? tile[r][t+1] : 0.f;
    }

    if (ch < 256) {
        float* op = g_qkv + (size_t)chbc*HWv;
#pragma unroll
        for (int r = 0; r < 8; r++) {
            float s = wl[r  ]*wreg[0] + wm[r  ]*wreg[1] + wr[r  ]*wreg[2]
                    + wl[r+1]*wreg[3] + wm[r+1]*wreg[4] + wr[r+1]*wreg[5]
                    + wl[r+2]*wreg[6] + wm[r+2]*wreg[7] + wr[r+2]*wreg[8];
            op[(size_t)(h0 + r)*W_ + t] = s;
        }
    } else {
        int row = b*64 + (ch - 256);
        unsigned* kp = g_keyA + (size_t)row*HWv;
#pragma unroll
        for (int r = 0; r < 8; r++) {
            float s = wl[r  ]*wreg[0] + wm[r  ]*wreg[1] + wr[r  ]*wreg[2]
                    + wl[r+1]*wreg[3] + wm[r+1]*wreg[4] + wr[r+1]*wreg[5]
                    + wl[r+2]*wreg[6] + wm[r+2]*wreg[7] + wr[r+2]*wreg[8];
            unsigned u = __float_as_uint(s);
            u ^= (u & 0x80000000u) ? 0xFFFFFFFFu : 0x80000000u;
            kp[(h0 + r)*W_ + t] = u;
        }
    }
}

// ---------------- multi-block stable radix sort (u32 key + u16 payload) ----------------
__global__ void rhist_kernel(const unsigned* __restrict__ src, int shift) {
    __shared__ unsigned h[256];
    int row = blockIdx.x >> 4, seg = blockIdx.x & 15;
    int tid = threadIdx.x;
    if (tid < 256) h[tid] = 0;
    __syncthreads();
    const unsigned* s = src + (size_t)row*R_N + (size_t)seg*R_SEG;
#pragma unroll
    for (int r = 0; r < R_EPT; r++) {
        unsigned dg = (s[r*R_THREADS + tid] >> shift) & 255u;
        atomicAdd(&h[dg], 1u);
    }
    __syncthreads();
    if (tid < 256)
        g_rhist[((size_t)row*256 + tid)*R_NSEG + seg] = h[tid];
}

__global__ void rscan_kernel() {
    int row = blockIdx.x, dg = threadIdx.x;
    unsigned* hp = g_rhist + ((size_t)row*256 + dg)*R_NSEG;
    unsigned v[R_NSEG]; unsigned tot = 0;
#pragma unroll
    for (int s2 = 0; s2 < R_NSEG; s2++) { unsigned t = hp[s2]; v[s2] = tot; tot += t; }
    unsigned lane = dg & 31, w = dg >> 5;
    unsigned x = tot;
#pragma unroll
    for (int o = 1; o < 32; o <<= 1) { unsigned y = __shfl_up_sync(0xffffffffu, x, o); if (lane >= o) x += y; }
    __shared__ unsigned wsum[8];
    if (lane == 31) wsum[w] = x;
    __syncthreads();
    if (dg == 0) { unsigned run = 0; for (int i = 0; i < 8; i++) { unsigned t = wsum[i]; wsum[i] = run; run += t; } }
    __syncthreads();
    unsigned base0 = (x - tot) + wsum[w];
#pragma unroll
    for (int s2 = 0; s2 < R_NSEG; s2++) hp[s2] = base0 + v[s2];
}

// mode: 1 = first pass (generate payload), 0 = middle, 2 = final (emit idx+vs)
__global__ void __launch_bounds__(R_THREADS)
rscatter_kernel(const unsigned* __restrict__ skeys,
                const unsigned short* __restrict__ spids,
                unsigned* __restrict__ dkeys,
                unsigned short* __restrict__ dpids,
                int shift, int mode) {
    __shared__ unsigned base[256];
    __shared__ unsigned bb0[256];
    __shared__ unsigned delta[256];
    __shared__ unsigned scanbuf[8];
    __shared__ unsigned skey[R_SEG];          // 16KB; doubles as woff (u32 16x256)
    __shared__ unsigned short spid[R_SEG];    // 8KB;  doubles as wcnt (u16 16x256)
    unsigned short* wcnt = spid;
    unsigned*       woff = skey;
    unsigned*       wc32 = (unsigned*)wcnt;

    int row = blockIdx.x >> 4, seg = blockIdx.x & 15;
    int tid = threadIdx.x, w = tid >> 5, lane = tid & 31;
    const unsigned* sk = skeys + (size_t)row*R_N + (size_t)seg*R_SEG;

    unsigned key[R_EPT];
    unsigned pid[R_EPT];
    unsigned posG[R_EPT];
#pragma unroll
    for (int r = 0; r < R_EPT; r++) key[r] = sk[r*R_THREADS + tid];
    if (mode == 1) {
#pragma unroll
        for (int r = 0; r < R_EPT; r++) pid[r] = seg*R_SEG + r*R_THREADS + tid;
    } else {
        const unsigned short* sp = spids + (size_t)row*R_N + (size_t)seg*R_SEG;
#pragma unroll
        for (int r = 0; r < R_EPT; r++) pid[r] = sp[r*R_THREADS + tid];
    }

    if (tid < 256) {
        unsigned bv = g_rhist[((size_t)row*256 + tid)*R_NSEG + seg];
        base[tid] = bv; bb0[tid] = bv;
    }

#pragma unroll
    for (int r = 0; r < R_EPT; r++) {
        wc32[tid] = 0; wc32[tid + 512] = 0; wc32[tid + 1024] = 0; wc32[tid + 1536] = 0;
        unsigned dg = (key[r] >> shift) & 255u;
        unsigned mask = __match_any_sync(0xffffffffu, dg);
        unsigned lr = __popc(mask & ((1u << lane) - 1u));
        unsigned cnt = __popc(mask);
        __syncthreads();
        if (lr == 0) wcnt[w*256 + dg] = (unsigned short)cnt;
        __syncthreads();
        if (tid < 256) {
            unsigned run = base[tid];
#pragma unroll
            for (int ww = 0; ww < 16; ww++) {
                unsigned c2 = wcnt[ww*256 + tid];
                woff[ww*256 + tid] = run;
                run += c2;
            }
            base[tid] = run;
        }
        __syncthreads();
        posG[r] = woff[w*256 + dg] + lr;
    }
    __syncthreads();

    if (tid < 256) {
        unsigned c = base[tid] - bb0[tid];
        unsigned x = c;
#pragma unroll
        for (int o = 1; o < 32; o <<= 1) { unsigned y = __shfl_up_sync(0xffffffffu, x, o); if (lane >= o) x += y; }
        woff[tid] = x - c;
        if (lane == 31) scanbuf[w] = x;
    }
    __syncthreads();
    if (tid == 0) { unsigned run = 0; for (int i = 0; i < 8; i++) { unsigned t2 = scanbuf[i]; scanbuf[i] = run; run += t2; } }
    __syncthreads();
    if (tid < 256) delta[tid] = bb0[tid] - (woff[tid] + scanbuf[tid >> 5]);
    __syncthreads();

    // stage into locally-sorted order
#pragma unroll
    for (int r = 0; r < R_EPT; r++) {
        unsigned dg = (key[r] >> shift) & 255u;
        unsigned loc = posG[r] - delta[dg];
        skey[loc] = key[r];
        spid[loc] = (unsigned short)pid[r];
    }
    __syncthreads();

    if (mode != 2) {
        unsigned* dk = dkeys + (size_t)row*R_N;
        unsigned short* dp = dpids + (size_t)row*R_N;
#pragma unroll
        for (int r = 0; r < R_EPT; r++) {
            unsigned i = r*R_THREADS + tid;
            unsigned k2 = skey[i];
            unsigned dg = (k2 >> shift) & 255u;
            unsigned pos = delta[dg] + i;
            dk[pos] = k2;
            dp[pos] = spid[i];
        }
    } else {
        int*   di = g_idx + (size_t)row*R_N;
        float* dv = g_vs  + (size_t)row*R_N;
#pragma unroll
        for (int r = 0; r < R_EPT; r++) {
            unsigned i = r*R_THREADS + tid;
            unsigned k2 = skey[i];
            unsigned dg = (k2 >> shift) & 255u;
            unsigned pos = delta[dg] + i;
            unsigned u = (k2 & 0x80000000u) ? (k2 ^ 0x80000000u) : ~k2;
            di[pos] = (int)spid[i];
            dv[pos] = __uint_as_float(u);
        }
    }
}

// ---------------- attention: qk with direct gather + norm partials ----------------
__global__ void qk_kernel() {
    __shared__ float Qs[64][65];
    __shared__ float Ks[64][65];
    __shared__ float nred[2][4][64];
    int t = threadIdx.x;
    int vbh = blockIdx.y;
    int var = vbh >> 3, b = (vbh>>2)&1, h = vbh & 3;
    int ty = t >> 4, tx = t & 15;
    int dn = t & 63, qtr = t >> 6;
    float acc[4][4];
#pragma unroll
    for (int i = 0; i < 4; i++)
#pragma unroll
        for (int j = 0; j < 4; j++) acc[i][j] = 0.f;
    float sumq = 0.f, sumk = 0.f;
    int n0 = blockIdx.x * 256;
    int qplane = var ? 128 : 0;
    for (int tile = 0; tile < 4; tile++) {
        int nb = n0 + tile*64;
#pragma unroll
        for (int rr = 0; rr < 16; rr++) {
            int l = rr*256 + t; int d = l >> 6; int nn = l & 63;
            int c = h*16 + (d>>2), f = d & 3;
            int pos = var ? 4*(nb+nn) + f : f*HWP_ + nb + nn;
            int j = g_idx[((size_t)(b*64 + c))*HWv + pos];
            size_t qb = ((size_t)(b*QKVC + qplane + c))*HWv;
            Qs[d][nn] = g_qkv[qb + j];
            Ks[d][nn] = g_qkv[qb + (size_t)64*HWv + j];
        }
        __syncthreads();
#pragma unroll
        for (int i = 0; i < 16; i++) {
            float qv = Qs[dn][qtr*16 + i];
            float kv = Ks[dn][qtr*16 + i];
            sumq += qv*qv; sumk += kv*kv;
        }
#pragma unroll 8
        for (int nn = 0; nn < 64; nn++) {
            float qa[4], ka[4];
#pragma unroll
            for (int i = 0; i < 4; i++) { qa[i] = Qs[ty*4+i][nn]; ka[i] = Ks[tx*4+i][nn]; }
#pragma unroll
            for (int i = 0; i < 4; i++)
#pragma unroll
                for (int j = 0; j < 4; j++) acc[i][j] += qa[i]*ka[j];
        }
        __syncthreads();
    }
    nred[0][qtr][dn] = sumq;
    nred[1][qtr][dn] = sumk;
    float* sp = g_Spart + ((size_t)(vbh*QK_SL + blockIdx.x))*4096;
#pragma unroll
    for (int i = 0; i < 4; i++)
#pragma unroll
        for (int j = 0; j < 4; j++)
            sp[(ty*4+i)*64 + tx*4 + j] = acc[i][j];
    __syncthreads();
    if (t < 128) {
        int qk = t >> 6, d = t & 63;
        float s = nred[qk][0][d] + nred[qk][1][d] + nred[qk][2][d] + nred[qk][3][d];
        int bin = (var<<10) | (qk<<9) | (b<<8) | (h<<6) | d;
        g_npart[(size_t)bin*QK_SL + blockIdx.x] = s;
    }
}

__global__ void reduce_norm_kernel() {
    int bin = blockIdx.x * 128 + threadIdx.x;   // 2048
    const float* p = g_npart + (size_t)bin*QK_SL;
    float s = 0.f;
#pragma unroll
    for (int i = 0; i < QK_SL; i++) s += p[i];
    g_norm[bin] = 1.0f / fmaxf(sqrtf(s), 1e-12f);
}

__global__ void softmax_kernel(const float* __restrict__ temp) {
    int blk = blockIdx.x;
    int vbh = blk >> 6, d = blk & 63;
    int var = vbh >> 3, b = (vbh>>2)&1, h = vbh & 3;
    int e = threadIdx.x;
    float sk = g_norm[(var<<10) | (1<<9) | (b<<8) | (h<<6) | e];
    float invq = g_norm[(var<<10) | (b<<8) | (h<<6) | d];
    float T = temp[h];
    const float* sp = g_Spart + (size_t)vbh*QK_SL*4096 + d*64 + e;
    float s = 0.f;
#pragma unroll
    for (int sl = 0; sl < QK_SL; sl++) s += sp[(size_t)sl*4096];
    float ex = expf(s * invq * sk * T);
    __shared__ float red[64];
    red[e] = ex;
    __syncthreads();
    if (e < 32) {
        float p = red[e] + red[e + 32];
#pragma unroll
        for (int o = 16; o > 0; o >>= 1) p += __shfl_down_sync(0xffffffffu, p, o);
        if (e == 0) red[0] = p;
    }
    __syncthreads();
    float r = 1.0f / (red[0] + 1.0f);
    g_attn[(size_t)vbh*4096 + d*64 + e] = ex * r;
}

// merged av: var = bid bit 9
__global__ void av_kernel() {
    __shared__ float As[4096];
    int t = threadIdx.x;
    int bid = blockIdx.x;
    int nblk = bid & 63;
    int h = (bid>>6)&3, b = (bid>>8)&1, var = (bid>>9)&1;
    int vbh = (var<<3) | (b<<2) | h;
    for (int l = t; l < 4096; l += 256) As[l] = g_attn[(size_t)vbh*4096 + l];
    __syncthreads();
    int n = nblk*256 + t;
    float acc[64];
#pragma unroll
    for (int d2 = 0; d2 < 64; d2++) acc[d2] = 0.f;
    if (!var) {
#pragma unroll 4
        for (int e0 = 0; e0 < 64; e0 += 4) {
            int ce = h*16 + (e0 >> 2);
            size_t cb = ((size_t)(b*64 + ce))*HWv;
            float v0 = g_vs[cb + n];
            float v1 = g_vs[cb + HWP_ + n];
            float v2 = g_vs[cb + 2*HWP_ + n];
            float v3 = g_vs[cb + 3*HWP_ + n];
#pragma unroll
            for (int d2 = 0; d2 < 64; d2++) {
                float4 a = *(const float4*)&As[d2*64 + e0];
                acc[d2] += a.x*v0 + a.y*v1 + a.z*v2 + a.w*v3;
            }
        }
#pragma unroll 1
        for (int d2 = 0; d2 < 64; d2++) {
            int cd = h*16 + (d2>>2), fd = d2 & 3;
            g_out1[((size_t)(b*64 + cd))*HWv + (size_t)fd*HWP_ + n] = acc[d2];
        }
    } else {
#pragma unroll 4
        for (int e0 = 0; e0 < 64; e0 += 4) {
            int ce = h*16 + (e0 >> 2);
            size_t cb = ((size_t)(b*64 + ce))*HWv;
            float4 vv = *(const float4*)&g_vs[cb + 4*(size_t)n];
#pragma unroll
            for (int d2 = 0; d2 < 64; d2++) {
                float4 a = *(const float4*)&As[d2*64 + e0];
                acc[d2] += a.x*vv.x + a.y*vv.y + a.z*vv.z + a.w*vv.w;
            }
        }
#pragma unroll 1
        for (int cg = 0; cg < 16; cg++) {
            int cd = h*16 + cg;
            size_t rb = ((size_t)(b*64 + cd))*HWv;
            size_t pos = rb + 4*(size_t)n;
            float4 o1 = *(const float4*)&g_out1[pos];
            int4   j4 = *(const int4*)&g_idx[pos];
            g_prod[rb + j4.x] = acc[cg*4 + 0] * o1.x;
            g_prod[rb + j4.y] = acc[cg*4 + 1] * o1.y;
            g_prod[rb + j4.z] = acc[cg*4 + 2] * o1.z;
            g_prod[rb + j4.w] = acc[cg*4 + 3] * o1.w;
        }
    }
}

// ---------------- fused unsort (both axes) ----------------
__global__ void unsort_kernel(float* __restrict__ out) {
    size_t gid = (size_t)blockIdx.x*256 + threadIdx.x;
    int b = (int)(gid / ((size_t)C_*HWv));
    size_t r0 = gid % ((size_t)C_*HWv);
    int c = (int)(r0 / HWv);
    int p = (int)(r0 % HWv);
    if (c < CH_) {
        int j = p & 255;
        size_t bc = (size_t)(b*CH_ + c);
        int r = g_invh[bc*HWv + p];
        int jw = g_invw[bc*HWv + (size_t)r*W_ + j];
        out[gid] = g_proj[((size_t)(b*C_ + c))*HWv + (size_t)r*W_ + jw];
    } else {
        out[gid] = g_proj[gid];
    }
}

// ---------------- launch ----------------
extern "C" void kernel_launch(void* const* d_in, const int* in_sizes, int n_in,
                              void* d_out, int out_size) {
    const float* x     = (const float*)d_in[0];
    const float* qkvw  = (const float*)d_in[1];
    const float* dww   = (const float*)d_in[2];
    const float* projw = (const float*)d_in[3];
    const float* temp  = (const float*)d_in[4];
    float* out = (float*)d_out;

    cudaFuncSetAttribute((const void*)conv1x1_kernel,
                         cudaFuncAttributeMaxDynamicSharedMemorySize, CV_SMEM);

    float *p_xcat, *p_qkvpre, *p_prod, *p_proj;
    unsigned *p_kA, *p_kB;
    unsigned short *p_pA, *p_pB;
    cudaGetSymbolAddress((void**)&p_xcat,   g_xcat);
    cudaGetSymbolAddress((void**)&p_qkvpre, g_qkv_pre);
    cudaGetSymbolAddress((void**)&p_prod,   g_prod);
    cudaGetSymbolAddress((void**)&p_proj,   g_proj);
    cudaGetSymbolAddress((void**)&p_kA,     g_keyA);
    cudaGetSymbolAddress((void**)&p_kB,     g_keyB);
    cudaGetSymbolAddress((void**)&p_pA,     g_pidA);
    cudaGetSymbolAddress((void**)&p_pB,     g_pidB);

    const int NBC  = (B_*C_*HWv) / 256;     // 32768

    // stage A: small sorts (+ inverse perms fused)
    sort_h_kernel<<<B_*CH_*W_, 256>>>(x);
    sort_w_kernel<<<B_*CH_*H_, 256>>>();
    copy_rest_kernel<<<(B_*CH_*HWv/4)/256, 256>>>(x);

    // stage B: convs (dwconv also emits u32 sort keys for v channels)
    conv1x1_kernel<<<dim3(HWv/CV_PX, QKVC/64, B_), 256, CV_SMEM>>>(p_xcat, qkvw, p_qkvpre, QKVC);
    dwconv_kernel<<<B_*QKVC*32, 256>>>(p_qkvpre, dww);

    // stage C: big stable argsort (u32 keys + u16 payloads, 4 passes)
    {
        const int NB = R_ROWS * R_NSEG;   // 2048
        rhist_kernel   <<<NB, R_THREADS>>>(p_kA, 0);
        rscan_kernel   <<<R_ROWS, 256>>>();
        rscatter_kernel<<<NB, R_THREADS>>>(p_kA, (const unsigned short*)0, p_kB, p_pB, 0, 1);

        rhist_kernel   <<<NB, R_THREADS>>>(p_kB, 8);
        rscan_kernel   <<<R_ROWS, 256>>>();
        rscatter_kernel<<<NB, R_THREADS>>>(p_kB, p_pB, p_kA, p_pA, 8, 0);

        rhist_kernel   <<<NB, R_THREADS>>>(p_kA, 16);
        rscan_kernel   <<<R_ROWS, 256>>>();
        rscatter_kernel<<<NB, R_THREADS>>>(p_kA, p_pA, p_kB, p_pB, 16, 0);

        rhist_kernel   <<<NB, R_THREADS>>>(p_kB, 24);
        rscan_kernel   <<<R_ROWS, 256>>>();
        rscatter_kernel<<<NB, R_THREADS>>>(p_kB, p_pB, (unsigned*)0, (unsigned short*)0, 24, 2);
    }

    // stage D: attention (qk gathers directly; norm partials fused)
    qk_kernel<<<dim3(QK_SL, 16), 256>>>();
    reduce_norm_kernel<<<16, 128>>>();
    softmax_kernel<<<16*64, 64>>>(temp);
    av_kernel<<<1024, 256>>>();

    // stage E: epilogue
    conv1x1_kernel<<<dim3(HWv/CV_PX, 1, B_), 256, CV_SMEM>>>(p_prod, projw, p_proj, C_);
    unsort_kernel<<<NBC, 256>>>(out);
}

// round 11
// speedup vs baseline: 1.4357x; 1.0027x over previous
#include <cuda_runtime.h>
#include <math.h>

// ---------------- constants ----------------
#define B_   2
#define C_   64
#define CH_  32
#define H_   256
#define W_   256
#define HWv  65536
#define QKVC 320
#define NH_  4
#define HWP_ 16384

// radix sort config
#define R_ROWS 128
#define R_N    65536
#define R_SEG  4096
#define R_NSEG 16
#define R_THREADS 512
#define R_EPT  8

// qk slicing
#define QK_SL 64

// conv1x1 tiling
#define CV_PX 256
#define CV_SMEM (64*CV_PX*4 + 64*64*4)   // 81920 bytes

// ---------------- scratch (static device memory; no allocs) ----------------
__device__ float g_xcat[B_*C_*HWv];
__device__ int   g_invh[B_*CH_*HWv];
__device__ int   g_invw[B_*CH_*HWv];
__device__ float g_qkv_pre[B_*QKVC*HWv];
__device__ float4 g_qkvi[B_*C_*HWv];           // interleaved {q1,k1,q2,k2}
__device__ unsigned g_keyA[R_ROWS*R_N];
__device__ unsigned g_keyB[R_ROWS*R_N];
__device__ unsigned short g_pidA[R_ROWS*R_N];
__device__ unsigned short g_pidB[R_ROWS*R_N];
__device__ unsigned g_rhist[R_ROWS*256*R_NSEG];
__device__ int   g_idx[B_*C_*HWv];
__device__ float g_vs [B_*C_*HWv];
__device__ float g_norm[2048];
__device__ float g_npart[2048*QK_SL];
__device__ float g_Spart[16*QK_SL*4096];
__device__ float g_attn[16*4096];
__device__ float g_out1[B_*C_*HWv];
__device__ float g_prod[B_*C_*HWv];
__device__ float g_proj[B_*C_*HWv];

// ---------------- small stable bitonic sort (256 elems) ----------------
__device__ __forceinline__ bool pair_gt(float va, int ia, float vb, int ib) {
    return (va > vb) || (va == vb && ia > ib);
}

__device__ __forceinline__ void bitonic256(float* sv, int* si) {
    int t = threadIdx.x;
    for (int k = 2; k <= 256; k <<= 1) {
        for (int j = k >> 1; j > 0; j >>= 1) {
            int ixj = t ^ j;
            if (ixj > t) {
                bool up = ((t & k) == 0);
                float va = sv[t], vb = sv[ixj];
                int   ia = si[t], ib = si[ixj];
                bool sw = up ? pair_gt(va, ia, vb, ib) : pair_gt(vb, ib, va, ia);
                if (sw) { sv[t] = vb; si[t] = ib; sv[ixj] = va; si[ixj] = ia; }
            }
            __syncthreads();
        }
    }
}

__global__ void sort_h_kernel(const float* __restrict__ x) {
    __shared__ float sv[256];
    __shared__ int   si[256];
    int blk = blockIdx.x;
    int b = blk / (CH_*W_);
    int c = (blk / W_) % CH_;
    int w = blk % W_;
    int t = threadIdx.x;
    const float* xp = x + ((size_t)(b*C_ + c))*HWv + w;
    sv[t] = xp[(size_t)t * W_];
    si[t] = t;
    __syncthreads();
    bitonic256(sv, si);
    g_xcat[((size_t)(b*C_ + c))*HWv + (size_t)t*W_ + w] = sv[t];
    g_invh[((size_t)(b*CH_ + c))*HWv + (size_t)si[t]*W_ + w] = t;
}

__global__ void sort_w_kernel() {
    __shared__ float sv[256];
    __shared__ int   si[256];
    int blk = blockIdx.x;
    int b = blk / (CH_*H_);
    int c = (blk / H_) % CH_;
    int h = blk % H_;
    int t = threadIdx.x;
    float* base = g_xcat + ((size_t)(b*C_ + c))*HWv + (size_t)h*W_;
    sv[t] = base[t];
    si[t] = t;
    __syncthreads();
    bitonic256(sv, si);
    base[t] = sv[t];
    g_invw[((size_t)(b*CH_ + c))*HWv + (size_t)h*W_ + si[t]] = t;
}

__global__ void copy_rest_kernel(const float* __restrict__ x) {
    size_t gid = (size_t)blockIdx.x*256 + threadIdx.x;
    int b = (int)(gid / ((size_t)CH_*HWv/4));
    size_t r = gid % ((size_t)CH_*HWv/4);
    int c = CH_ + (int)(r / (HWv/4));
    int p = (int)(r % (HWv/4)) * 4;
    size_t off = ((size_t)(b*C_ + c))*HWv + p;
    *(float4*)&g_xcat[off] = *(const float4*)&x[off];
}

// ---------------- conv1x1 (IC=64; tile 256px x 64oc; 8x8 microtile; pipelined) ----------------
__global__ void __launch_bounds__(256)
conv1x1_kernel(const float* __restrict__ in, const float* __restrict__ w,
               float* __restrict__ out, int OC) {
    extern __shared__ float sm[];
    float* Xs = sm;                 // [64][256]
    float* Ws = sm + 64*CV_PX;      // [64][64]
    int p0  = blockIdx.x * CV_PX;
    int oc0 = blockIdx.y * 64;
    int b   = blockIdx.z;
    int t   = threadIdx.x;
#pragma unroll
    for (int r = 0; r < 16; r++) {
        int l = r*256 + t; int ic = l >> 6; int grp = l & 63;
        *(float4*)&Xs[ic*CV_PX + grp*4] =
            *(const float4*)&in[((size_t)(b*64 + ic))*HWv + p0 + grp*4];
    }
#pragma unroll
    for (int r = 0; r < 16; r++) {
        int l = r*256 + t; int oc = l >> 6; int ic = l & 63;
        Ws[ic*64 + oc] = w[(size_t)(oc0 + oc)*64 + ic];
    }
    __syncthreads();
    int tx = t & 31, ty = t >> 5;
    float acc[8][8];
#pragma unroll
    for (int i = 0; i < 8; i++)
#pragma unroll
        for (int j = 0; j < 8; j++) acc[i][j] = 0.f;

    float4 xa = *(const float4*)&Xs[tx*4];
    float4 xb = *(const float4*)&Xs[128 + tx*4];
    float4 wa = *(const float4*)&Ws[ty*8];
    float4 wb = *(const float4*)&Ws[ty*8 + 4];
#pragma unroll
    for (int ic = 0; ic < 64; ic++) {
        float4 nxa, nxb, nwa, nwb;
        if (ic < 63) {
            nxa = *(const float4*)&Xs[(ic+1)*CV_PX + tx*4];
            nxb = *(const float4*)&Xs[(ic+1)*CV_PX + 128 + tx*4];
            nwa = *(const float4*)&Ws[(ic+1)*64 + ty*8];
            nwb = *(const float4*)&Ws[(ic+1)*64 + ty*8 + 4];
        }
        float xv[8] = {xa.x,xa.y,xa.z,xa.w,xb.x,xb.y,xb.z,xb.w};
        float wv[8] = {wa.x,wa.y,wa.z,wa.w,wb.x,wb.y,wb.z,wb.w};
#pragma unroll
        for (int i = 0; i < 8; i++)
#pragma unroll
            for (int j = 0; j < 8; j++) acc[i][j] += wv[i]*xv[j];
        xa = nxa; xb = nxb; wa = nwa; wb = nwb;
    }
#pragma unroll
    for (int i = 0; i < 8; i++) {
        size_t ob = ((size_t)(b*OC + oc0 + ty*8 + i))*HWv + p0;
        *(float4*)&out[ob + tx*4]       = make_float4(acc[i][0],acc[i][1],acc[i][2],acc[i][3]);
        *(float4*)&out[ob + 128 + tx*4] = make_float4(acc[i][4],acc[i][5],acc[i][6],acc[i][7]);
    }
}

// ---------------- depthwise 3x3: qk planes (4 channels/block, float4 out) ----------------
__global__ void __launch_bounds__(256)
dwconv_qk_kernel(const float* __restrict__ in, const float* __restrict__ wd) {
    __shared__ float tile[4][10][W_];   // 40KB
    int bid = blockIdx.x;               // (b*64+c)*32 + hblk
    int hblk = bid & 31;
    int cb = bid >> 5;
    int c = cb % 64;
    int b = cb / 64;
    int h0 = hblk * 8;
    int t = threadIdx.x;
#pragma unroll
    for (int p = 0; p < 4; p++) {
        const float* ip = in + ((size_t)(b*QKVC + p*64 + c))*HWv;
#pragma unroll
        for (int r = 0; r < 10; r++) {
            int hh = h0 - 1 + r;
            tile[p][r][t] = (hh >= 0 && hh < H_) ? ip[(size_t)hh*W_ + t] : 0.f;
        }
    }
    __syncthreads();

    float o[4][8];
#pragma unroll
    for (int p = 0; p < 4; p++) {
        float wreg[9];
#pragma unroll
        for (int i = 0; i < 9; i++) wreg[i] = __ldg(&wd[(size_t)(p*64 + c)*9 + i]);
        float wl[10], wm[10], wr[10];
#pragma unroll
        for (int r = 0; r < 10; r++) {
            wm[r] = tile[p][r][t];
            wl[r] = (t > 0)   ? tile[p][r][t-1] : 0.f;
            wr[r] = (t < 255) ? tile[p][r][t+1] : 0.f;
        }
#pragma unroll
        for (int r = 0; r < 8; r++) {
            o[p][r] = wl[r  ]*wreg[0] + wm[r  ]*wreg[1] + wr[r  ]*wreg[2]
                    + wl[r+1]*wreg[3] + wm[r+1]*wreg[4] + wr[r+1]*wreg[5]
                    + wl[r+2]*wreg[6] + wm[r+2]*wreg[7] + wr[r+2]*wreg[8];
        }
    }
    float4* op = g_qkvi + ((size_t)(b*64 + c))*HWv;
#pragma unroll
    for (int r = 0; r < 8; r++) {
        op[(h0 + r)*W_ + t] = make_float4(o[0][r], o[1][r], o[2][r], o[3][r]);
    }
}

// ---------------- depthwise 3x3: v channels -> u32 sort keys ----------------
__global__ void __launch_bounds__(256)
dwconv_v_kernel(const float* __restrict__ in, const float* __restrict__ wd) {
    __shared__ float tile[10][W_];
    int bid = blockIdx.x;               // (b*64+c)*32 + hblk
    int hblk = bid & 31;
    int cb = bid >> 5;
    int c = cb % 64;
    int b = cb / 64;
    int ch = 256 + c;
    int h0 = hblk * 8;
    int t = threadIdx.x;
    const float* ip = in + ((size_t)(b*QKVC + ch))*HWv;
#pragma unroll
    for (int r = 0; r < 10; r++) {
        int hh = h0 - 1 + r;
        tile[r][t] = (hh >= 0 && hh < H_) ? ip[(size_t)hh*W_ + t] : 0.f;
    }
    float wreg[9];
#pragma unroll
    for (int i = 0; i < 9; i++) wreg[i] = __ldg(&wd[(size_t)ch*9 + i]);
    __syncthreads();

    float wl[10], wm[10], wr[10];
#pragma unroll
    for (int r = 0; r < 10; r++) {
        wm[r] = tile[r][t];
        wl[r] = (t > 0)   ? tile[r][t-1] : 0.f;
        wr[r] = (t < 255) ? tile[r][t+1] : 0.f;
    }
    int row = b*64 + c;
    unsigned* kp = g_keyA + (size_t)row*HWv;
#pragma unroll
    for (int r = 0; r < 8; r++) {
        float s = wl[r  ]*wreg[0] + wm[r  ]*wreg[1] + wr[r  ]*wreg[2]
                + wl[r+1]*wreg[3] + wm[r+1]*wreg[4] + wr[r+1]*wreg[5]
                + wl[r+2]*wreg[6] + wm[r+2]*wreg[7] + wr[r+2]*wreg[8];
        unsigned u = __float_as_uint(s);
        u ^= (u & 0x80000000u) ? 0xFFFFFFFFu : 0x80000000u;
        kp[(h0 + r)*W_ + t] = u;
    }
}

// ---------------- multi-block stable radix sort (u32 key + u16 payload) ----------------
__global__ void rhist_kernel(const unsigned* __restrict__ src, int shift) {
    __shared__ unsigned h[256];
    int row = blockIdx.x >> 4, seg = blockIdx.x & 15;
    int tid = threadIdx.x;
    if (tid < 256) h[tid] = 0;
    __syncthreads();
    const unsigned* s = src + (size_t)row*R_N + (size_t)seg*R_SEG;
#pragma unroll
    for (int r = 0; r < R_EPT; r++) {
        unsigned dg = (s[r*R_THREADS + tid] >> shift) & 255u;
        atomicAdd(&h[dg], 1u);
    }
    __syncthreads();
    if (tid < 256)
        g_rhist[((size_t)row*256 + tid)*R_NSEG + seg] = h[tid];
}

__global__ void rscan_kernel() {
    int row = blockIdx.x, dg = threadIdx.x;
    unsigned* hp = g_rhist + ((size_t)row*256 + dg)*R_NSEG;
    unsigned v[R_NSEG]; unsigned tot = 0;
#pragma unroll
    for (int s2 = 0; s2 < R_NSEG; s2++) { unsigned t = hp[s2]; v[s2] = tot; tot += t; }
    unsigned lane = dg & 31, w = dg >> 5;
    unsigned x = tot;
#pragma unroll
    for (int o = 1; o < 32; o <<= 1) { unsigned y = __shfl_up_sync(0xffffffffu, x, o); if (lane >= o) x += y; }
    __shared__ unsigned wsum[8];
    if (lane == 31) wsum[w] = x;
    __syncthreads();
    if (dg == 0) { unsigned run = 0; for (int i = 0; i < 8; i++) { unsigned t = wsum[i]; wsum[i] = run; run += t; } }
    __syncthreads();
    unsigned base0 = (x - tot) + wsum[w];
#pragma unroll
    for (int s2 = 0; s2 < R_NSEG; s2++) hp[s2] = base0 + v[s2];
}

// mode: 1 = first pass (generate payload), 0 = middle, 2 = final (emit idx+vs)
__global__ void __launch_bounds__(R_THREADS)
rscatter_kernel(const unsigned* __restrict__ skeys,
                const unsigned short* __restrict__ spids,
                unsigned* __restrict__ dkeys,
                unsigned short* __restrict__ dpids,
                int shift, int mode) {
    __shared__ unsigned base[256];
    __shared__ unsigned bb0[256];
    __shared__ unsigned delta[256];
    __shared__ unsigned scanbuf[8];
    __shared__ unsigned skey[R_SEG];          // 16KB; doubles as woff
    __shared__ unsigned short spid[R_SEG];    // 8KB;  doubles as wcnt
    unsigned short* wcnt = spid;
    unsigned*       woff = skey;
    unsigned*       wc32 = (unsigned*)wcnt;

    int row = blockIdx.x >> 4, seg = blockIdx.x & 15;
    int tid = threadIdx.x, w = tid >> 5, lane = tid & 31;
    const unsigned* sk = skeys + (size_t)row*R_N + (size_t)seg*R_SEG;

    unsigned key[R_EPT];
    unsigned pid[R_EPT];
    unsigned posG[R_EPT];
#pragma unroll
    for (int r = 0; r < R_EPT; r++) key[r] = sk[r*R_THREADS + tid];
    if (mode == 1) {
#pragma unroll
        for (int r = 0; r < R_EPT; r++) pid[r] = seg*R_SEG + r*R_THREADS + tid;
    } else {
        const unsigned short* sp = spids + (size_t)row*R_N + (size_t)seg*R_SEG;
#pragma unroll
        for (int r = 0; r < R_EPT; r++) pid[r] = sp[r*R_THREADS + tid];
    }

    if (tid < 256) {
        unsigned bv = g_rhist[((size_t)row*256 + tid)*R_NSEG + seg];
        base[tid] = bv; bb0[tid] = bv;
    }

#pragma unroll
    for (int r = 0; r < R_EPT; r++) {
        wc32[tid] = 0; wc32[tid + 512] = 0; wc32[tid + 1024] = 0; wc32[tid + 1536] = 0;
        unsigned dg = (key[r] >> shift) & 255u;
        unsigned mask = __match_any_sync(0xffffffffu, dg);
        unsigned lr = __popc(mask & ((1u << lane) - 1u));
        unsigned cnt = __popc(mask);
        __syncthreads();
        if (lr == 0) wcnt[w*256 + dg] = (unsigned short)cnt;
        __syncthreads();
        if (tid < 256) {
            unsigned run = base[tid];
#pragma unroll
            for (int ww = 0; ww < 16; ww++) {
                unsigned c2 = wcnt[ww*256 + tid];
                woff[ww*256 + tid] = run;
                run += c2;
            }
            base[tid] = run;
        }
        __syncthreads();
        posG[r] = woff[w*256 + dg] + lr;
    }
    __syncthreads();

    if (tid < 256) {
        unsigned c = base[tid] - bb0[tid];
        unsigned x = c;
#pragma unroll
        for (int o = 1; o < 32; o <<= 1) { unsigned y = __shfl_up_sync(0xffffffffu, x, o); if (lane >= o) x += y; }
        woff[tid] = x - c;
        if (lane == 31) scanbuf[w] = x;
    }
    __syncthreads();
    if (tid == 0) { unsigned run = 0; for (int i = 0; i < 8; i++) { unsigned t2 = scanbuf[i]; scanbuf[i] = run; run += t2; } }
    __syncthreads();
    if (tid < 256) delta[tid] = bb0[tid] - (woff[tid] + scanbuf[tid >> 5]);
    __syncthreads();

#pragma unroll
    for (int r = 0; r < R_EPT; r++) {
        unsigned dg = (key[r] >> shift) & 255u;
        unsigned loc = posG[r] - delta[dg];
        skey[loc] = key[r];
        spid[loc] = (unsigned short)pid[r];
    }
    __syncthreads();

    if (mode != 2) {
        unsigned* dk = dkeys + (size_t)row*R_N;
        unsigned short* dp = dpids + (size_t)row*R_N;
#pragma unroll
        for (int r = 0; r < R_EPT; r++) {
            unsigned i = r*R_THREADS + tid;
            unsigned k2 = skey[i];
            unsigned dg = (k2 >> shift) & 255u;
            unsigned pos = delta[dg] + i;
            dk[pos] = k2;
            dp[pos] = spid[i];
        }
    } else {
        int*   di = g_idx + (size_t)row*R_N;
        float* dv = g_vs  + (size_t)row*R_N;
#pragma unroll
        for (int r = 0; r < R_EPT; r++) {
            unsigned i = r*R_THREADS + tid;
            unsigned k2 = skey[i];
            unsigned dg = (k2 >> shift) & 255u;
            unsigned pos = delta[dg] + i;
            unsigned u = (k2 & 0x80000000u) ? (k2 ^ 0x80000000u) : ~k2;
            di[pos] = (int)spid[i];
            dv[pos] = __uint_as_float(u);
        }
    }
}

// ---------------- attention: qk with float4-interleaved gather + norm partials ----------------
__global__ void qk_kernel() {
    __shared__ float Qs[64][65];
    __shared__ float Ks[64][65];
    __shared__ float nred[2][4][64];
    int t = threadIdx.x;
    int vbh = blockIdx.y;
    int var = vbh >> 3, b = (vbh>>2)&1, h = vbh & 3;
    int ty = t >> 4, tx = t & 15;
    int dn = t & 63, qtr = t >> 6;
    float acc[4][4];
#pragma unroll
    for (int i = 0; i < 4; i++)
#pragma unroll
        for (int j = 0; j < 4; j++) acc[i][j] = 0.f;
    float sumq = 0.f, sumk = 0.f;
    int n0 = blockIdx.x * 256;
    for (int tile = 0; tile < 4; tile++) {
        int nb = n0 + tile*64;
#pragma unroll
        for (int rr = 0; rr < 16; rr++) {
            int l = rr*256 + t; int d = l >> 6; int nn = l & 63;
            int c = h*16 + (d>>2), f = d & 3;
            int pos = var ? 4*(nb+nn) + f : f*HWP_ + nb + nn;
            size_t rowb = ((size_t)(b*64 + c))*HWv;
            int j = g_idx[rowb + pos];
            float4 v4 = g_qkvi[rowb + j];
            Qs[d][nn] = var ? v4.z : v4.x;
            Ks[d][nn] = var ? v4.w : v4.y;
        }
        __syncthreads();
#pragma unroll
        for (int i = 0; i < 16; i++) {
            float qv = Qs[dn][qtr*16 + i];
            float kv = Ks[dn][qtr*16 + i];
            sumq += qv*qv; sumk += kv*kv;
        }
#pragma unroll 8
        for (int nn = 0; nn < 64; nn++) {
            float qa[4], ka[4];
#pragma unroll
            for (int i = 0; i < 4; i++) { qa[i] = Qs[ty*4+i][nn]; ka[i] = Ks[tx*4+i][nn]; }
#pragma unroll
            for (int i = 0; i < 4; i++)
#pragma unroll
                for (int j = 0; j < 4; j++) acc[i][j] += qa[i]*ka[j];
        }
        __syncthreads();
    }
    nred[0][qtr][dn] = sumq;
    nred[1][qtr][dn] = sumk;
    float* sp = g_Spart + ((size_t)(vbh*QK_SL + blockIdx.x))*4096;
#pragma unroll
    for (int i = 0; i < 4; i++)
#pragma unroll
        for (int j = 0; j < 4; j++)
            sp[(ty*4+i)*64 + tx*4 + j] = acc[i][j];
    __syncthreads();
    if (t < 128) {
        int qk = t >> 6, d = t & 63;
        float s = nred[qk][0][d] + nred[qk][1][d] + nred[qk][2][d] + nred[qk][3][d];
        int bin = (var<<10) | (qk<<9) | (b<<8) | (h<<6) | d;
        g_npart[(size_t)bin*QK_SL + blockIdx.x] = s;
    }
}

__global__ void reduce_norm_kernel() {
    int bin = blockIdx.x * 128 + threadIdx.x;   // 2048
    const float* p = g_npart + (size_t)bin*QK_SL;
    float s = 0.f;
#pragma unroll
    for (int i = 0; i < QK_SL; i++) s += p[i];
    g_norm[bin] = 1.0f / fmaxf(sqrtf(s), 1e-12f);
}

__global__ void softmax_kernel(const float* __restrict__ temp) {
    int blk = blockIdx.x;
    int vbh = blk >> 6, d = blk & 63;
    int var = vbh >> 3, b = (vbh>>2)&1, h = vbh & 3;
    int e = threadIdx.x;
    float sk = g_norm[(var<<10) | (1<<9) | (b<<8) | (h<<6) | e];
    float invq = g_norm[(var<<10) | (b<<8) | (h<<6) | d];
    float T = temp[h];
    const float* sp = g_Spart + (size_t)vbh*QK_SL*4096 + d*64 + e;
    float s = 0.f;
#pragma unroll
    for (int sl = 0; sl < QK_SL; sl++) s += sp[(size_t)sl*4096];
    float ex = expf(s * invq * sk * T);
    __shared__ float red[64];
    red[e] = ex;
    __syncthreads();
    if (e < 32) {
        float p = red[e] + red[e + 32];
#pragma unroll
        for (int o = 16; o > 0; o >>= 1) p += __shfl_down_sync(0xffffffffu, p, o);
        if (e == 0) red[0] = p;
    }
    __syncthreads();
    float r = 1.0f / (red[0] + 1.0f);
    g_attn[(size_t)vbh*4096 + d*64 + e] = ex * r;
}

// merged av: var = bid bit 9
__global__ void av_kernel() {
    __shared__ float As[4096];
    int t = threadIdx.x;
    int bid = blockIdx.x;
    int nblk = bid & 63;
    int h = (bid>>6)&3, b = (bid>>8)&1, var = (bid>>9)&1;
    int vbh = (var<<3) | (b<<2) | h;
    for (int l = t; l < 4096; l += 256) As[l] = g_attn[(size_t)vbh*4096 + l];
    __syncthreads();
    int n = nblk*256 + t;
    float acc[64];
#pragma unroll
    for (int d2 = 0; d2 < 64; d2++) acc[d2] = 0.f;
    if (!var) {
#pragma unroll 4
        for (int e0 = 0; e0 < 64; e0 += 4) {
            int ce = h*16 + (e0 >> 2);
            size_t cb = ((size_t)(b*64 + ce))*HWv;
            float v0 = g_vs[cb + n];
            float v1 = g_vs[cb + HWP_ + n];
            float v2 = g_vs[cb + 2*HWP_ + n];
            float v3 = g_vs[cb + 3*HWP_ + n];
#pragma unroll
            for (int d2 = 0; d2 < 64; d2++) {
                float4 a = *(const float4*)&As[d2*64 + e0];
                acc[d2] += a.x*v0 + a.y*v1 + a.z*v2 + a.w*v3;
            }
        }
#pragma unroll 1
        for (int d2 = 0; d2 < 64; d2++) {
            int cd = h*16 + (d2>>2), fd = d2 & 3;
            g_out1[((size_t)(b*64 + cd))*HWv + (size_t)fd*HWP_ + n] = acc[d2];
        }
    } else {
#pragma unroll 4
        for (int e0 = 0; e0 < 64; e0 += 4) {
            int ce = h*16 + (e0 >> 2);
            size_t cb = ((size_t)(b*64 + ce))*HWv;
            float4 vv = *(const float4*)&g_vs[cb + 4*(size_t)n];
#pragma unroll
            for (int d2 = 0; d2 < 64; d2++) {
                float4 a = *(const float4*)&As[d2*64 + e0];
                acc[d2] += a.x*vv.x + a.y*vv.y + a.z*vv.z + a.w*vv.w;
            }
        }
#pragma unroll 1
        for (int cg = 0; cg < 16; cg++) {
            int cd = h*16 + cg;
            size_t rb = ((size_t)(b*64 + cd))*HWv;
            size_t pos = rb + 4*(size_t)n;
            float4 o1 = *(const float4*)&g_out1[pos];
            int4   j4 = *(const int4*)&g_idx[pos];
            g_prod[rb + j4.x] = acc[cg*4 + 0] * o1.x;
            g_prod[rb + j4.y] = acc[cg*4 + 1] * o1.y;
            g_prod[rb + j4.z] = acc[cg*4 + 2] * o1.z;
            g_prod[rb + j4.w] = acc[cg*4 + 3] * o1.w;
        }
    }
}

// ---------------- fused unsort (both axes) ----------------
__global__ void unsort_kernel(float* __restrict__ out) {
    size_t gid = (size_t)blockIdx.x*256 + threadIdx.x;
    int b = (int)(gid / ((size_t)C_*HWv));
    size_t r0 = gid % ((size_t)C_*HWv);
    int c = (int)(r0 / HWv);
    int p = (int)(r0 % HWv);
    if (c < CH_) {
        int j = p & 255;
        size_t bc = (size_t)(b*CH_ + c);
        int r = g_invh[bc*HWv + p];
        int jw = g_invw[bc*HWv + (size_t)r*W_ + j];
        out[gid] = g_proj[((size_t)(b*C_ + c))*HWv + (size_t)r*W_ + jw];
    } else {
        out[gid] = g_proj[gid];
    }
}

// ---------------- launch ----------------
extern "C" void kernel_launch(void* const* d_in, const int* in_sizes, int n_in,
                              void* d_out, int out_size) {
    const float* x     = (const float*)d_in[0];
    const float* qkvw  = (const float*)d_in[1];
    const float* dww   = (const float*)d_in[2];
    const float* projw = (const float*)d_in[3];
    const float* temp  = (const float*)d_in[4];
    float* out = (float*)d_out;

    cudaFuncSetAttribute((const void*)conv1x1_kernel,
                         cudaFuncAttributeMaxDynamicSharedMemorySize, CV_SMEM);

    float *p_xcat, *p_qkvpre, *p_prod, *p_proj;
    unsigned *p_kA, *p_kB;
    unsigned short *p_pA, *p_pB;
    cudaGetSymbolAddress((void**)&p_xcat,   g_xcat);
    cudaGetSymbolAddress((void**)&p_qkvpre, g_qkv_pre);
    cudaGetSymbolAddress((void**)&p_prod,   g_prod);
    cudaGetSymbolAddress((void**)&p_proj,   g_proj);
    cudaGetSymbolAddress((void**)&p_kA,     g_keyA);
    cudaGetSymbolAddress((void**)&p_kB,     g_keyB);
    cudaGetSymbolAddress((void**)&p_pA,     g_pidA);
    cudaGetSymbolAddress((void**)&p_pB,     g_pidB);

    const int NBC  = (B_*C_*HWv) / 256;     // 32768

    // stage A: small sorts (+ inverse perms fused)
    sort_h_kernel<<<B_*CH_*W_, 256>>>(x);
    sort_w_kernel<<<B_*CH_*H_, 256>>>();
    copy_rest_kernel<<<(B_*CH_*HWv/4)/256, 256>>>(x);

    // stage B: convs
    conv1x1_kernel<<<dim3(HWv/CV_PX, QKVC/64, B_), 256, CV_SMEM>>>(p_xcat, qkvw, p_qkvpre, QKVC);
    dwconv_v_kernel <<<B_*64*32, 256>>>(p_qkvpre, dww);
    dwconv_qk_kernel<<<B_*64*32, 256>>>(p_qkvpre, dww);

    // stage C: big stable argsort (u32 keys + u16 payloads, 4 passes)
    {
        const int NB = R_ROWS * R_NSEG;   // 2048
        rhist_kernel   <<<NB, R_THREADS>>>(p_kA, 0);
        rscan_kernel   <<<R_ROWS, 256>>>();
        rscatter_kernel<<<NB, R_THREADS>>>(p_kA, (const unsigned short*)0, p_kB, p_pB, 0, 1);

        rhist_kernel   <<<NB, R_THREADS>>>(p_kB, 8);
        rscan_kernel   <<<R_ROWS, 256>>>();
        rscatter_kernel<<<NB, R_THREADS>>>(p_kB, p_pB, p_kA, p_pA, 8, 0);

        rhist_kernel   <<<NB, R_THREADS>>>(p_kA, 16);
        rscan_kernel   <<<R_ROWS, 256>>>();
        rscatter_kernel<<<NB, R_THREADS>>>(p_kA, p_pA, p_kB, p_pB, 16, 0);

        rhist_kernel   <<<NB, R_THREADS>>>(p_kB, 24);
        rscan_kernel   <<<R_ROWS, 256>>>();
        rscatter_kernel<<<NB, R_THREADS>>>(p_kB, p_pB, (unsigned*)0, (unsigned short*)0, 24, 2);
    }

    // stage D: attention
    qk_kernel<<<dim3(QK_SL, 16), 256>>>();
    reduce_norm_kernel<<<16, 128>>>();
    softmax_kernel<<<16*64, 64>>>(temp);
    av_kernel<<<1024, 256>>>();

    // stage E: epilogue
    conv1x1_kernel<<<dim3(HWv/CV_PX, 1, B_), 256, CV_SMEM>>>(p_prod, projw, p_proj, C_);
    unsort_kernel<<<NBC, 256>>>(out);
}

// round 12
// speedup vs baseline: 1.5710x; 1.0943x over previous
#include <cuda_runtime.h>
#include <math.h>

// ---------------- constants ----------------
#define B_   2
#define C_   64
#define CH_  32
#define H_   256
#define W_   256
#define HWv  65536
#define QKVC 320
#define NH_  4
#define HWP_ 16384

// radix sort config
#define R_ROWS 128
#define R_N    65536
#define R_SEG  4096
#define R_NSEG 16
#define R_THREADS 512
#define R_EPT  8

// qk slicing
#define QK_SL 64

// conv1x1 tiling
#define CV_PX 256
#define CV_SMEM (64*CV_PX*4 + 64*64*4)   // 81920 bytes

// sort_h tiled smem: sv[256][33] f32 + si[256][33] u8 + inv[256][33] u8
#define SH_SMEM (256*33*4 + 2*256*33)    // 50688 bytes

// ---------------- scratch (static device memory; no allocs) ----------------
__device__ float g_xcat[B_*C_*HWv];            // only ch<32 used (sorted)
__device__ int   g_invh[B_*CH_*HWv];
__device__ int   g_invw[B_*CH_*HWv];
__device__ float g_qkv_pre[B_*QKVC*HWv];
__device__ float4 g_qkvi[B_*C_*HWv];           // interleaved {q1,k1,q2,k2}
__device__ unsigned g_keyA[R_ROWS*R_N];
__device__ unsigned g_keyB[R_ROWS*R_N];
__device__ unsigned short g_pidA[R_ROWS*R_N];
__device__ unsigned short g_pidB[R_ROWS*R_N];
__device__ unsigned g_rhist[R_ROWS*256*R_NSEG];
__device__ int   g_idx[B_*C_*HWv];
__device__ float g_vs [B_*C_*HWv];
__device__ float g_norm[2048];
__device__ float g_npart[2048*QK_SL];
__device__ float g_Spart[16*QK_SL*4096];
__device__ float g_attn[16*4096];
__device__ float g_out1[B_*C_*HWv];
__device__ float g_prod[B_*C_*HWv];
__device__ float g_proj[B_*C_*HWv];            // only ch<32 used

// ---------------- helpers ----------------
__device__ __forceinline__ bool pair_gt(float va, int ia, float vb, int ib) {
    return (va > vb) || (va == vb && ia > ib);
}

// ---------------- sort_h: tiled, coalesced (32 columns per block) ----------------
__global__ void __launch_bounds__(256)
sort_h_kernel(const float* __restrict__ x) {
    extern __shared__ char shm[];
    float* sv = (float*)shm;                          // [256][33]
    unsigned char* si  = (unsigned char*)(sv + 256*33);   // [256][33]
    unsigned char* inv = si + 256*33;                     // [256][33]
    int blk = blockIdx.x;                 // b*CH*(W/32)
    int b = blk / (CH_*(W_/32));
    int c = (blk / (W_/32)) % CH_;
    int w0 = (blk % (W_/32)) * 32;
    int t = threadIdx.x;
    int lane = t & 31, wrow = t >> 5;
    const float* xp = x + ((size_t)(b*C_ + c))*HWv + w0;
#pragma unroll 4
    for (int r = 0; r < 32; r++) {
        int row = r*8 + wrow;
        sv[row*33 + lane] = xp[(size_t)row*W_ + lane];
        si[row*33 + lane] = (unsigned char)row;
    }
    __syncthreads();
    int col = t & 31;
    int grp = t >> 5;
    for (int k = 2; k <= 256; k <<= 1) {
        for (int j = k >> 1; j > 0; j >>= 1) {
#pragma unroll 4
            for (int pp = 0; pp < 16; pp++) {
                int idx = grp*16 + pp;                       // 0..127
                int i = ((idx & ~(j-1)) << 1) | (idx & (j-1));
                int partner = i | j;
                bool up = ((i & k) == 0);
                float va = sv[i*33 + col], vb = sv[partner*33 + col];
                int   ia = si[i*33 + col], ib = si[partner*33 + col];
                bool sw = up ? pair_gt(va, ia, vb, ib) : pair_gt(vb, ib, va, ia);
                if (sw) {
                    sv[i*33 + col] = vb;       si[i*33 + col] = (unsigned char)ib;
                    sv[partner*33 + col] = va; si[partner*33 + col] = (unsigned char)ia;
                }
            }
            __syncthreads();
        }
    }
    float* xo = g_xcat + ((size_t)(b*C_ + c))*HWv + w0;
#pragma unroll 4
    for (int r = 0; r < 32; r++) {
        int row = r*8 + wrow;
        xo[(size_t)row*W_ + lane] = sv[row*33 + lane];
        inv[(int)si[row*33 + lane]*33 + lane] = (unsigned char)row;
    }
    __syncthreads();
    int* io = g_invh + ((size_t)(b*CH_ + c))*HWv + w0;
#pragma unroll 4
    for (int r = 0; r < 32; r++) {
        int row = r*8 + wrow;
        io[(size_t)row*W_ + lane] = inv[row*33 + lane];
    }
}

// ---------------- sort_w (row-wise; already coalesced) ----------------
__device__ __forceinline__ void bitonic256(float* sv, int* si) {
    int t = threadIdx.x;
    for (int k = 2; k <= 256; k <<= 1) {
        for (int j = k >> 1; j > 0; j >>= 1) {
            int ixj = t ^ j;
            if (ixj > t) {
                bool up = ((t & k) == 0);
                float va = sv[t], vb = sv[ixj];
                int   ia = si[t], ib = si[ixj];
                bool sw = up ? pair_gt(va, ia, vb, ib) : pair_gt(vb, ib, va, ia);
                if (sw) { sv[t] = vb; si[t] = ib; sv[ixj] = va; si[ixj] = ia; }
            }
            __syncthreads();
        }
    }
}

__global__ void sort_w_kernel() {
    __shared__ float sv[256];
    __shared__ int   si[256];
    int blk = blockIdx.x;
    int b = blk / (CH_*H_);
    int c = (blk / H_) % CH_;
    int h = blk % H_;
    int t = threadIdx.x;
    float* base = g_xcat + ((size_t)(b*C_ + c))*HWv + (size_t)h*W_;
    sv[t] = base[t];
    si[t] = t;
    __syncthreads();
    bitonic256(sv, si);
    base[t] = sv[t];
    g_invw[((size_t)(b*CH_ + c))*HWv + (size_t)h*W_ + si[t]] = t;
}

// ---------------- conv1x1 (split input ic<32 / ic>=32, split output oc) ----------------
__global__ void __launch_bounds__(256)
conv1x1_kernel(const float* __restrict__ inA, const float* __restrict__ inB,
               const float* __restrict__ w,
               float* __restrict__ outA, float* __restrict__ outB,
               int OC, int oc_split) {
    extern __shared__ float sm[];
    float* Xs = sm;                 // [64][256]
    float* Ws = sm + 64*CV_PX;      // [64][64]
    int p0  = blockIdx.x * CV_PX;
    int oc0 = blockIdx.y * 64;
    int b   = blockIdx.z;
    int t   = threadIdx.x;
#pragma unroll
    for (int r = 0; r < 16; r++) {
        int l = r*256 + t; int ic = l >> 6; int grp = l & 63;
        const float* src = (ic < 32) ? inA : inB;
        *(float4*)&Xs[ic*CV_PX + grp*4] =
            *(const float4*)&src[((size_t)(b*64 + ic))*HWv + p0 + grp*4];
    }
#pragma unroll
    for (int r = 0; r < 16; r++) {
        int l = r*256 + t; int oc = l >> 6; int ic = l & 63;
        Ws[ic*64 + oc] = w[(size_t)(oc0 + oc)*64 + ic];
    }
    __syncthreads();
    int tx = t & 31, ty = t >> 5;
    float acc[8][8];
#pragma unroll
    for (int i = 0; i < 8; i++)
#pragma unroll
        for (int j = 0; j < 8; j++) acc[i][j] = 0.f;
#pragma unroll
    for (int ic = 0; ic < 64; ic++) {
        float4 xa = *(const float4*)&Xs[ic*CV_PX + tx*4];
        float4 xb = *(const float4*)&Xs[ic*CV_PX + 128 + tx*4];
        float4 wa = *(const float4*)&Ws[ic*64 + ty*8];
        float4 wb = *(const float4*)&Ws[ic*64 + ty*8 + 4];
        float xv[8] = {xa.x,xa.y,xa.z,xa.w,xb.x,xb.y,xb.z,xb.w};
        float wv[8] = {wa.x,wa.y,wa.z,wa.w,wb.x,wb.y,wb.z,wb.w};
#pragma unroll
        for (int i = 0; i < 8; i++)
#pragma unroll
            for (int j = 0; j < 8; j++) acc[i][j] += wv[i]*xv[j];
    }
#pragma unroll
    for (int i = 0; i < 8; i++) {
        int oc = oc0 + ty*8 + i;
        float* dst = (oc < oc_split) ? outA : outB;
        size_t ob = ((size_t)(b*OC + oc))*HWv + p0;
        *(float4*)&dst[ob + tx*4]       = make_float4(acc[i][0],acc[i][1],acc[i][2],acc[i][3]);
        *(float4*)&dst[ob + 128 + tx*4] = make_float4(acc[i][4],acc[i][5],acc[i][6],acc[i][7]);
    }
}

// ---------------- depthwise 3x3: qk planes (4 channels/block, float4 out) ----------------
__global__ void __launch_bounds__(256)
dwconv_qk_kernel(const float* __restrict__ in, const float* __restrict__ wd) {
    __shared__ float tile[4][10][W_];   // 40KB
    int bid = blockIdx.x;               // (b*64+c)*32 + hblk
    int hblk = bid & 31;
    int cb = bid >> 5;
    int c = cb % 64;
    int b = cb / 64;
    int h0 = hblk * 8;
    int t = threadIdx.x;
#pragma unroll
    for (int p = 0; p < 4; p++) {
        const float* ip = in + ((size_t)(b*QKVC + p*64 + c))*HWv;
#pragma unroll
        for (int r = 0; r < 10; r++) {
            int hh = h0 - 1 + r;
            tile[p][r][t] = (hh >= 0 && hh < H_) ? ip[(size_t)hh*W_ + t] : 0.f;
        }
    }
    __syncthreads();

    float o[4][8];
#pragma unroll
    for (int p = 0; p < 4; p++) {
        float wreg[9];
#pragma unroll
        for (int i = 0; i < 9; i++) wreg[i] = __ldg(&wd[(size_t)(p*64 + c)*9 + i]);
        float wl[10], wm[10], wr[10];
#pragma unroll
        for (int r = 0; r < 10; r++) {
            wm[r] = tile[p][r][t];
            wl[r] = (t > 0)   ? tile[p][r][t-1] : 0.f;
            wr[r] = (t < 255) ? tile[p][r][t+1] : 0.f;
        }
#pragma unroll
        for (int r = 0; r < 8; r++) {
            o[p][r] = wl[r  ]*wreg[0] + wm[r  ]*wreg[1] + wr[r  ]*wreg[2]
                    + wl[r+1]*wreg[3] + wm[r+1]*wreg[4] + wr[r+1]*wreg[5]
                    + wl[r+2]*wreg[6] + wm[r+2]*wreg[7] + wr[r+2]*wreg[8];
        }
    }
    float4* op = g_qkvi + ((size_t)(b*64 + c))*HWv;
#pragma unroll
    for (int r = 0; r < 8; r++) {
        op[(h0 + r)*W_ + t] = make_float4(o[0][r], o[1][r], o[2][r], o[3][r]);
    }
}

// ---------------- depthwise 3x3: v channels -> u32 sort keys ----------------
__global__ void __launch_bounds__(256)
dwconv_v_kernel(const float* __restrict__ in, const float* __restrict__ wd) {
    __shared__ float tile[10][W_];
    int bid = blockIdx.x;
    int hblk = bid & 31;
    int cb = bid >> 5;
    int c = cb % 64;
    int b = cb / 64;
    int ch = 256 + c;
    int h0 = hblk * 8;
    int t = threadIdx.x;
    const float* ip = in + ((size_t)(b*QKVC + ch))*HWv;
#pragma unroll
    for (int r = 0; r < 10; r++) {
        int hh = h0 - 1 + r;
        tile[r][t] = (hh >= 0 && hh < H_) ? ip[(size_t)hh*W_ + t] : 0.f;
    }
    float wreg[9];
#pragma unroll
    for (int i = 0; i < 9; i++) wreg[i] = __ldg(&wd[(size_t)ch*9 + i]);
    __syncthreads();

    float wl[10], wm[10], wr[10];
#pragma unroll
    for (int r = 0; r < 10; r++) {
        wm[r] = tile[r][t];
        wl[r] = (t > 0)   ? tile[r][t-1] : 0.f;
        wr[r] = (t < 255) ? tile[r][t+1] : 0.f;
    }
    int row = b*64 + c;
    unsigned* kp = g_keyA + (size_t)row*HWv;
#pragma unroll
    for (int r = 0; r < 8; r++) {
        float s = wl[r  ]*wreg[0] + wm[r  ]*wreg[1] + wr[r  ]*wreg[2]
                + wl[r+1]*wreg[3] + wm[r+1]*wreg[4] + wr[r+1]*wreg[5]
                + wl[r+2]*wreg[6] + wm[r+2]*wreg[7] + wr[r+2]*wreg[8];
        unsigned u = __float_as_uint(s);
        u ^= (u & 0x80000000u) ? 0xFFFFFFFFu : 0x80000000u;
        kp[(h0 + r)*W_ + t] = u;
    }
}

// ---------------- multi-block stable radix sort (u32 key + u16 payload) ----------------
__global__ void rhist_kernel(const unsigned* __restrict__ src, int shift) {
    __shared__ unsigned h[256];
    int row = blockIdx.x >> 4, seg = blockIdx.x & 15;
    int tid = threadIdx.x;
    if (tid < 256) h[tid] = 0;
    __syncthreads();
    const unsigned* s = src + (size_t)row*R_N + (size_t)seg*R_SEG;
#pragma unroll
    for (int r = 0; r < R_EPT; r++) {
        unsigned dg = (s[r*R_THREADS + tid] >> shift) & 255u;
        atomicAdd(&h[dg], 1u);
    }
    __syncthreads();
    if (tid < 256)
        g_rhist[((size_t)row*256 + tid)*R_NSEG + seg] = h[tid];
}

__global__ void rscan_kernel() {
    int row = blockIdx.x, dg = threadIdx.x;
    unsigned* hp = g_rhist + ((size_t)row*256 + dg)*R_NSEG;
    unsigned v[R_NSEG]; unsigned tot = 0;
#pragma unroll
    for (int s2 = 0; s2 < R_NSEG; s2++) { unsigned t = hp[s2]; v[s2] = tot; tot += t; }
    unsigned lane = dg & 31, w = dg >> 5;
    unsigned x = tot;
#pragma unroll
    for (int o = 1; o < 32; o <<= 1) { unsigned y = __shfl_up_sync(0xffffffffu, x, o); if (lane >= o) x += y; }
    __shared__ unsigned wsum[8];
    if (lane == 31) wsum[w] = x;
    __syncthreads();
    if (dg == 0) { unsigned run = 0; for (int i = 0; i < 8; i++) { unsigned t = wsum[i]; wsum[i] = run; run += t; } }
    __syncthreads();
    unsigned base0 = (x - tot) + wsum[w];
#pragma unroll
    for (int s2 = 0; s2 < R_NSEG; s2++) hp[s2] = base0 + v[s2];
}

// mode: 1 = first pass (generate payload), 0 = middle, 2 = final (emit idx+vs)
__global__ void __launch_bounds__(R_THREADS)
rscatter_kernel(const unsigned* __restrict__ skeys,
                const unsigned short* __restrict__ spids,
                unsigned* __restrict__ dkeys,
                unsigned short* __restrict__ dpids,
                int shift, int mode) {
    __shared__ unsigned base[256];
    __shared__ unsigned bb0[256];
    __shared__ unsigned delta[256];
    __shared__ unsigned scanbuf[8];
    __shared__ unsigned skey[R_SEG];          // 16KB; doubles as woff
    __shared__ unsigned short spid[R_SEG];    // 8KB;  doubles as wcnt
    unsigned short* wcnt = spid;
    unsigned*       woff = skey;
    unsigned*       wc32 = (unsigned*)wcnt;

    int row = blockIdx.x >> 4, seg = blockIdx.x & 15;
    int tid = threadIdx.x, w = tid >> 5, lane = tid & 31;
    const unsigned* sk = skeys + (size_t)row*R_N + (size_t)seg*R_SEG;

    unsigned key[R_EPT];
    unsigned pid[R_EPT];
    unsigned posG[R_EPT];
#pragma unroll
    for (int r = 0; r < R_EPT; r++) key[r] = sk[r*R_THREADS + tid];
    if (mode == 1) {
#pragma unroll
        for (int r = 0; r < R_EPT; r++) pid[r] = seg*R_SEG + r*R_THREADS + tid;
    } else {
        const unsigned short* sp = spids + (size_t)row*R_N + (size_t)seg*R_SEG;
#pragma unroll
        for (int r = 0; r < R_EPT; r++) pid[r] = sp[r*R_THREADS + tid];
    }

    if (tid < 256) {
        unsigned bv = g_rhist[((size_t)row*256 + tid)*R_NSEG + seg];
        base[tid] = bv; bb0[tid] = bv;
    }

#pragma unroll
    for (int r = 0; r < R_EPT; r++) {
        wc32[tid] = 0; wc32[tid + 512] = 0; wc32[tid + 1024] = 0; wc32[tid + 1536] = 0;
        unsigned dg = (key[r] >> shift) & 255u;
        unsigned mask = __match_any_sync(0xffffffffu, dg);
        unsigned lr = __popc(mask & ((1u << lane) - 1u));
        unsigned cnt = __popc(mask);
        __syncthreads();
        if (lr == 0) wcnt[w*256 + dg] = (unsigned short)cnt;
        __syncthreads();
        if (tid < 256) {
            unsigned run = base[tid];
#pragma unroll
            for (int ww = 0; ww < 16; ww++) {
                unsigned c2 = wcnt[ww*256 + tid];
                woff[ww*256 + tid] = run;
                run += c2;
            }
            base[tid] = run;
        }
        __syncthreads();
        posG[r] = woff[w*256 + dg] + lr;
    }
    __syncthreads();

    if (tid < 256) {
        unsigned c = base[tid] - bb0[tid];
        unsigned x = c;
#pragma unroll
        for (int o = 1; o < 32; o <<= 1) { unsigned y = __shfl_up_sync(0xffffffffu, x, o); if (lane >= o) x += y; }
        woff[tid] = x - c;
        if (lane == 31) scanbuf[w] = x;
    }
    __syncthreads();
    if (tid == 0) { unsigned run = 0; for (int i = 0; i < 8; i++) { unsigned t2 = scanbuf[i]; scanbuf[i] = run; run += t2; } }
    __syncthreads();
    if (tid < 256) delta[tid] = bb0[tid] - (woff[tid] + scanbuf[tid >> 5]);
    __syncthreads();

#pragma unroll
    for (int r = 0; r < R_EPT; r++) {
        unsigned dg = (key[r] >> shift) & 255u;
        unsigned loc = posG[r] - delta[dg];
        skey[loc] = key[r];
        spid[loc] = (unsigned short)pid[r];
    }
    __syncthreads();

    if (mode != 2) {
        unsigned* dk = dkeys + (size_t)row*R_N;
        unsigned short* dp = dpids + (size_t)row*R_N;
#pragma unroll
        for (int r = 0; r < R_EPT; r++) {
            unsigned i = r*R_THREADS + tid;
            unsigned k2 = skey[i];
            unsigned dg = (k2 >> shift) & 255u;
            unsigned pos = delta[dg] + i;
            dk[pos] = k2;
            dp[pos] = spid[i];
        }
    } else {
        int*   di = g_idx + (size_t)row*R_N;
        float* dv = g_vs  + (size_t)row*R_N;
#pragma unroll
        for (int r = 0; r < R_EPT; r++) {
            unsigned i = r*R_THREADS + tid;
            unsigned k2 = skey[i];
            unsigned dg = (k2 >> shift) & 255u;
            unsigned pos = delta[dg] + i;
            unsigned u = (k2 & 0x80000000u) ? (k2 ^ 0x80000000u) : ~k2;
            di[pos] = (int)spid[i];
            dv[pos] = __uint_as_float(u);
        }
    }
}

// ---------------- attention: qk with float4-interleaved gather + norm partials ----------------
__global__ void qk_kernel() {
    __shared__ float Qs[64][65];
    __shared__ float Ks[64][65];
    __shared__ float nred[2][4][64];
    int t = threadIdx.x;
    int vbh = blockIdx.y;
    int var = vbh >> 3, b = (vbh>>2)&1, h = vbh & 3;
    int ty = t >> 4, tx = t & 15;
    int dn = t & 63, qtr = t >> 6;
    float acc[4][4];
#pragma unroll
    for (int i = 0; i < 4; i++)
#pragma unroll
        for (int j = 0; j < 4; j++) acc[i][j] = 0.f;
    float sumq = 0.f, sumk = 0.f;
    int n0 = blockIdx.x * 256;
    for (int tile = 0; tile < 4; tile++) {
        int nb = n0 + tile*64;
#pragma unroll
        for (int rr = 0; rr < 16; rr++) {
            int l = rr*256 + t; int d = l >> 6; int nn = l & 63;
            int c = h*16 + (d>>2), f = d & 3;
            int pos = var ? 4*(nb+nn) + f : f*HWP_ + nb + nn;
            size_t rowb = ((size_t)(b*64 + c))*HWv;
            int j = g_idx[rowb + pos];
            float4 v4 = g_qkvi[rowb + j];
            Qs[d][nn] = var ? v4.z : v4.x;
            Ks[d][nn] = var ? v4.w : v4.y;
        }
        __syncthreads();
#pragma unroll
        for (int i = 0; i < 16; i++) {
            float qv = Qs[dn][qtr*16 + i];
            float kv = Ks[dn][qtr*16 + i];
            sumq += qv*qv; sumk += kv*kv;
        }
#pragma unroll 8
        for (int nn = 0; nn < 64; nn++) {
            float qa[4], ka[4];
#pragma unroll
            for (int i = 0; i < 4; i++) { qa[i] = Qs[ty*4+i][nn]; ka[i] = Ks[tx*4+i][nn]; }
#pragma unroll
            for (int i = 0; i < 4; i++)
#pragma unroll
                for (int j = 0; j < 4; j++) acc[i][j] += qa[i]*ka[j];
        }
        __syncthreads();
    }
    nred[0][qtr][dn] = sumq;
    nred[1][qtr][dn] = sumk;
    float* sp = g_Spart + ((size_t)(vbh*QK_SL + blockIdx.x))*4096;
#pragma unroll
    for (int i = 0; i < 4; i++)
#pragma unroll
        for (int j = 0; j < 4; j++)
            sp[(ty*4+i)*64 + tx*4 + j] = acc[i][j];
    __syncthreads();
    if (t < 128) {
        int qk = t >> 6, d = t & 63;
        float s = nred[qk][0][d] + nred[qk][1][d] + nred[qk][2][d] + nred[qk][3][d];
        int bin = (var<<10) | (qk<<9) | (b<<8) | (h<<6) | d;
        g_npart[(size_t)bin*QK_SL + blockIdx.x] = s;
    }
}

__global__ void reduce_norm_kernel() {
    int bin = blockIdx.x * 128 + threadIdx.x;   // 2048
    const float* p = g_npart + (size_t)bin*QK_SL;
    float s = 0.f;
#pragma unroll
    for (int i = 0; i < QK_SL; i++) s += p[i];
    g_norm[bin] = 1.0f / fmaxf(sqrtf(s), 1e-12f);
}

__global__ void softmax_kernel(const float* __restrict__ temp) {
    int blk = blockIdx.x;
    int vbh = blk >> 6, d = blk & 63;
    int var = vbh >> 3, b = (vbh>>2)&1, h = vbh & 3;
    int e = threadIdx.x;
    float sk = g_norm[(var<<10) | (1<<9) | (b<<8) | (h<<6) | e];
    float invq = g_norm[(var<<10) | (b<<8) | (h<<6) | d];
    float T = temp[h];
    const float* sp = g_Spart + (size_t)vbh*QK_SL*4096 + d*64 + e;
    float s = 0.f;
#pragma unroll
    for (int sl = 0; sl < QK_SL; sl++) s += sp[(size_t)sl*4096];
    float ex = expf(s * invq * sk * T);
    __shared__ float red[64];
    red[e] = ex;
    __syncthreads();
    if (e < 32) {
        float p = red[e] + red[e + 32];
#pragma unroll
        for (int o = 16; o > 0; o >>= 1) p += __shfl_down_sync(0xffffffffu, p, o);
        if (e == 0) red[0] = p;
    }
    __syncthreads();
    float r = 1.0f / (red[0] + 1.0f);
    g_attn[(size_t)vbh*4096 + d*64 + e] = ex * r;
}

// merged av: var = bid bit 9
__global__ void av_kernel() {
    __shared__ float As[4096];
    int t = threadIdx.x;
    int bid = blockIdx.x;
    int nblk = bid & 63;
    int h = (bid>>6)&3, b = (bid>>8)&1, var = (bid>>9)&1;
    int vbh = (var<<3) | (b<<2) | h;
    for (int l = t; l < 4096; l += 256) As[l] = g_attn[(size_t)vbh*4096 + l];
    __syncthreads();
    int n = nblk*256 + t;
    float acc[64];
#pragma unroll
    for (int d2 = 0; d2 < 64; d2++) acc[d2] = 0.f;
    if (!var) {
#pragma unroll 4
        for (int e0 = 0; e0 < 64; e0 += 4) {
            int ce = h*16 + (e0 >> 2);
            size_t cb = ((size_t)(b*64 + ce))*HWv;
            float v0 = g_vs[cb + n];
            float v1 = g_vs[cb + HWP_ + n];
            float v2 = g_vs[cb + 2*HWP_ + n];
            float v3 = g_vs[cb + 3*HWP_ + n];
#pragma unroll
            for (int d2 = 0; d2 < 64; d2++) {
                float4 a = *(const float4*)&As[d2*64 + e0];
                acc[d2] += a.x*v0 + a.y*v1 + a.z*v2 + a.w*v3;
            }
        }
#pragma unroll 1
        for (int d2 = 0; d2 < 64; d2++) {
            int cd = h*16 + (d2>>2), fd = d2 & 3;
            g_out1[((size_t)(b*64 + cd))*HWv + (size_t)fd*HWP_ + n] = acc[d2];
        }
    } else {
#pragma unroll 4
        for (int e0 = 0; e0 < 64; e0 += 4) {
            int ce = h*16 + (e0 >> 2);
            size_t cb = ((size_t)(b*64 + ce))*HWv;
            float4 vv = *(const float4*)&g_vs[cb + 4*(size_t)n];
#pragma unroll
            for (int d2 = 0; d2 < 64; d2++) {
                float4 a = *(const float4*)&As[d2*64 + e0];
                acc[d2] += a.x*vv.x + a.y*vv.y + a.z*vv.z + a.w*vv.w;
            }
        }
#pragma unroll 1
        for (int cg = 0; cg < 16; cg++) {
            int cd = h*16 + cg;
            size_t rb = ((size_t)(b*64 + cd))*HWv;
            size_t pos = rb + 4*(size_t)n;
            float4 o1 = *(const float4*)&g_out1[pos];
            int4   j4 = *(const int4*)&g_idx[pos];
            g_prod[rb + j4.x] = acc[cg*4 + 0] * o1.x;
            g_prod[rb + j4.y] = acc[cg*4 + 1] * o1.y;
            g_prod[rb + j4.z] = acc[cg*4 + 2] * o1.z;
            g_prod[rb + j4.w] = acc[cg*4 + 3] * o1.w;
        }
    }
}

// ---------------- fused unsort (ch<32 only; upper half written by conv) ----------------
__global__ void unsort_kernel(float* __restrict__ out) {
    size_t gid = (size_t)blockIdx.x*256 + threadIdx.x;   // B*CH*HW
    size_t bc = gid / HWv;
    int b = (int)(bc / CH_), c = (int)(bc % CH_);
    int p = (int)(gid % HWv);
    int j = p & 255;
    int r = g_invh[bc*HWv + p];
    int jw = g_invw[bc*HWv + (size_t)r*W_ + j];
    out[((size_t)(b*C_ + c))*HWv + p] = g_proj[((size_t)(b*C_ + c))*HWv + (size_t)r*W_ + jw];
}

// ---------------- launch ----------------
extern "C" void kernel_launch(void* const* d_in, const int* in_sizes, int n_in,
                              void* d_out, int out_size) {
    const float* x     = (const float*)d_in[0];
    const float* qkvw  = (const float*)d_in[1];
    const float* dww   = (const float*)d_in[2];
    const float* projw = (const float*)d_in[3];
    const float* temp  = (const float*)d_in[4];
    float* out = (float*)d_out;

    cudaFuncSetAttribute((const void*)conv1x1_kernel,
                         cudaFuncAttributeMaxDynamicSharedMemorySize, CV_SMEM);
    cudaFuncSetAttribute((const void*)sort_h_kernel,
                         cudaFuncAttributeMaxDynamicSharedMemorySize, SH_SMEM);

    float *p_xcat, *p_qkvpre, *p_prod, *p_proj;
    unsigned *p_kA, *p_kB;
    unsigned short *p_pA, *p_pB;
    cudaGetSymbolAddress((void**)&p_xcat,   g_xcat);
    cudaGetSymbolAddress((void**)&p_qkvpre, g_qkv_pre);
    cudaGetSymbolAddress((void**)&p_prod,   g_prod);
    cudaGetSymbolAddress((void**)&p_proj,   g_proj);
    cudaGetSymbolAddress((void**)&p_kA,     g_keyA);
    cudaGetSymbolAddress((void**)&p_kB,     g_keyB);
    cudaGetSymbolAddress((void**)&p_pA,     g_pidA);
    cudaGetSymbolAddress((void**)&p_pB,     g_pidB);

    const int NBCH = (B_*CH_*HWv) / 256;    // 16384

    // stage A: small sorts (tiled sort_h; inverse perms fused)
    sort_h_kernel<<<B_*CH_*(W_/32), 256, SH_SMEM>>>(x);
    sort_w_kernel<<<B_*CH_*H_, 256>>>();

    // stage B: convs (conv reads ic<32 from g_xcat, ic>=32 straight from x)
    conv1x1_kernel<<<dim3(HWv/CV_PX, QKVC/64, B_), 256, CV_SMEM>>>(
        p_xcat, x, qkvw, p_qkvpre, p_qkvpre, QKVC, QKVC);
    dwconv_v_kernel <<<B_*64*32, 256>>>(p_qkvpre, dww);
    dwconv_qk_kernel<<<B_*64*32, 256>>>(p_qkvpre, dww);

    // stage C: big stable argsort (u32 keys + u16 payloads, 4 passes)
    {
        const int NB = R_ROWS * R_NSEG;   // 2048
        rhist_kernel   <<<NB, R_THREADS>>>(p_kA, 0);
        rscan_kernel   <<<R_ROWS, 256>>>();
        rscatter_kernel<<<NB, R_THREADS>>>(p_kA, (const unsigned short*)0, p_kB, p_pB, 0, 1);

        rhist_kernel   <<<NB, R_THREADS>>>(p_kB, 8);
        rscan_kernel   <<<R_ROWS, 256>>>();
        rscatter_kernel<<<NB, R_THREADS>>>(p_kB, p_pB, p_kA, p_pA, 8, 0);

        rhist_kernel   <<<NB, R_THREADS>>>(p_kA, 16);
        rscan_kernel   <<<R_ROWS, 256>>>();
        rscatter_kernel<<<NB, R_THREADS>>>(p_kA, p_pA, p_kB, p_pB, 16, 0);

        rhist_kernel   <<<NB, R_THREADS>>>(p_kB, 24);
        rscan_kernel   <<<R_ROWS, 256>>>();
        rscatter_kernel<<<NB, R_THREADS>>>(p_kB, p_pB, (unsigned*)0, (unsigned short*)0, 24, 2);
    }

    // stage D: attention
    qk_kernel<<<dim3(QK_SL, 16), 256>>>();
    reduce_norm_kernel<<<16, 128>>>();
    softmax_kernel<<<16*64, 64>>>(temp);
    av_kernel<<<1024, 256>>>();

    // stage E: epilogue (proj conv writes oc<32 -> g_proj, oc>=32 -> out directly)
    conv1x1_kernel<<<dim3(HWv/CV_PX, 1, B_), 256, CV_SMEM>>>(
        p_prod, p_prod, projw, p_proj, out, C_, CH_);
    unsort_kernel<<<NBCH, 256>>>(out);
}